// round 1
// baseline (speedup 1.0000x reference)
#include <cuda_runtime.h>
#include <math.h>

#define N_   128
#define T_   32
#define TCAP 33
#define D_   400
#define WE_  512
#define H_   1024
#define H4_  4096
#define V_   10000
#define L_   16

// ---------------- device scratch (no cudaMalloc allowed) ----------------
__device__ float g_A[N_ * H_ * L_];              // A_flat [n][h][l]   8 MB
__device__ float g_h[N_ * H_];
__device__ float g_c[N_ * H_];
__device__ float g_attn[N_ * H_];
__device__ float g_hn[N_ * T_ * H_];             // 16 MB, row = n*T + t
__device__ float g_xproj[(size_t)N_ * T_ * H4_]; // 64 MB, row = n*T + t
__device__ float g_z[N_ * H4_];                  // 2 MB
__device__ float g_scores[(size_t)N_ * T_ * V_]; // 164 MB

__device__ __forceinline__ float sigf(float x) { return 1.0f / (1.0f + expf(-x)); }

// ---------------- output init ----------------
__global__ void init_out(float* out) { out[0] = 0.0f; }

// ---------------- A_flat + h0/c0 ----------------
// block per n; A[n,h,l] = sum_d feat[n,d,l]*Wp[d,h] + bp[h]; h0 = mean_l
__global__ __launch_bounds__(256) void kA(const float* __restrict__ feat,
                                          const float* __restrict__ Wp,
                                          const float* __restrict__ bp) {
    int n = blockIdx.x;
    __shared__ float fsh[D_ * L_];   // 25.6 KB
    const float* f = feat + (size_t)n * D_ * L_;
    for (int i = threadIdx.x; i < D_ * L_; i += 256) fsh[i] = f[i];
    __syncthreads();
    for (int h = threadIdx.x; h < H_; h += 256) {
        float acc[L_];
        float bb = bp[h];
#pragma unroll
        for (int l = 0; l < L_; l++) acc[l] = bb;
        for (int d = 0; d < D_; d++) {
            float wv = Wp[d * H_ + h];
            const float* fr = &fsh[d * L_];
#pragma unroll
            for (int l = 0; l < L_; l++) acc[l] = fmaf(fr[l], wv, acc[l]);
        }
        float s = 0.0f;
        float* Ar = g_A + ((size_t)n * H_ + h) * L_;
#pragma unroll
        for (int l = 0; l < L_; l++) { Ar[l] = acc[l]; s += acc[l]; }
        float h0 = s * (1.0f / 16.0f);
        g_h[n * H_ + h] = h0;
        g_c[n * H_ + h] = h0;
    }
}

// ---------------- shared GEMM tile geometry ----------------
#define BM 64
#define BN 64
#define BK 16

// xproj[(n*T+t), :] = W_embed[cap[n,t]] @ Wx     (M=4096, K=512, N=4096)
__global__ __launch_bounds__(256) void gemm_embed(const int* __restrict__ captions,
                                                  const float* __restrict__ Wemb,
                                                  const float* __restrict__ Wx) {
    __shared__ float As[BK][BM + 4];
    __shared__ float Bs[BK][BN + 4];
    int row0 = blockIdx.y * BM, col0 = blockIdx.x * BN;
    int tid = threadIdx.x;
    int tx = tid & 15, ty = tid >> 4;
    float acc[4][4] = {};
    int am = tid >> 2, ak4 = (tid & 3) * 4;       // A loader: float4 per thread
    int bk = tid >> 4, bn4 = (tid & 15) * 4;      // B loader: float4 per thread
    int r = row0 + am;
    int tok = captions[(r >> 5) * TCAP + (r & 31)];
    const float* arow = Wemb + (size_t)tok * WE_;
    for (int k0 = 0; k0 < WE_; k0 += BK) {
        float4 av = *(const float4*)&arow[k0 + ak4];
        As[ak4 + 0][am] = av.x; As[ak4 + 1][am] = av.y;
        As[ak4 + 2][am] = av.z; As[ak4 + 3][am] = av.w;
        float4 bv = *(const float4*)&Wx[(size_t)(k0 + bk) * H4_ + col0 + bn4];
        *(float4*)&Bs[bk][bn4] = bv;
        __syncthreads();
#pragma unroll
        for (int k = 0; k < BK; k++) {
            float4 a = *(float4*)&As[k][ty * 4];
            float4 b = *(float4*)&Bs[k][tx * 4];
            acc[0][0] = fmaf(a.x, b.x, acc[0][0]); acc[0][1] = fmaf(a.x, b.y, acc[0][1]);
            acc[0][2] = fmaf(a.x, b.z, acc[0][2]); acc[0][3] = fmaf(a.x, b.w, acc[0][3]);
            acc[1][0] = fmaf(a.y, b.x, acc[1][0]); acc[1][1] = fmaf(a.y, b.y, acc[1][1]);
            acc[1][2] = fmaf(a.y, b.z, acc[1][2]); acc[1][3] = fmaf(a.y, b.w, acc[1][3]);
            acc[2][0] = fmaf(a.z, b.x, acc[2][0]); acc[2][1] = fmaf(a.z, b.y, acc[2][1]);
            acc[2][2] = fmaf(a.z, b.z, acc[2][2]); acc[2][3] = fmaf(a.z, b.w, acc[2][3]);
            acc[3][0] = fmaf(a.w, b.x, acc[3][0]); acc[3][1] = fmaf(a.w, b.y, acc[3][1]);
            acc[3][2] = fmaf(a.w, b.z, acc[3][2]); acc[3][3] = fmaf(a.w, b.w, acc[3][3]);
        }
        __syncthreads();
    }
#pragma unroll
    for (int i = 0; i < 4; i++)
#pragma unroll
        for (int j = 0; j < 4; j++)
            g_xproj[(size_t)(row0 + ty * 4 + i) * H4_ + col0 + tx * 4 + j] = acc[i][j];
}

// z = [h | attn] @ [Wh ; Wattn] + xproj_t + b    (M=128, K=2048, N=4096)
__global__ __launch_bounds__(256) void gemm_z(const float* __restrict__ Wh,
                                              const float* __restrict__ Wattn,
                                              const float* __restrict__ b,
                                              int t) {
    __shared__ float As[BK][BM + 4];
    __shared__ float Bs[BK][BN + 4];
    int row0 = blockIdx.y * BM, col0 = blockIdx.x * BN;
    int tid = threadIdx.x;
    int tx = tid & 15, ty = tid >> 4;
    float acc[4][4] = {};
    int am = tid >> 2, ak4 = (tid & 3) * 4;
    int bk = tid >> 4, bn4 = (tid & 15) * 4;
    for (int k0 = 0; k0 < 2 * H_; k0 += BK) {
        const float* Abase = (k0 < H_) ? (g_h + k0) : (g_attn + (k0 - H_));
        const float* Bbase = (k0 < H_) ? (Wh + (size_t)k0 * H4_)
                                       : (Wattn + (size_t)(k0 - H_) * H4_);
        float4 av = *(const float4*)&Abase[(size_t)(row0 + am) * H_ + ak4];
        As[ak4 + 0][am] = av.x; As[ak4 + 1][am] = av.y;
        As[ak4 + 2][am] = av.z; As[ak4 + 3][am] = av.w;
        float4 bv = *(const float4*)&Bbase[(size_t)bk * H4_ + col0 + bn4];
        *(float4*)&Bs[bk][bn4] = bv;
        __syncthreads();
#pragma unroll
        for (int k = 0; k < BK; k++) {
            float4 a = *(float4*)&As[k][ty * 4];
            float4 bb = *(float4*)&Bs[k][tx * 4];
            acc[0][0] = fmaf(a.x, bb.x, acc[0][0]); acc[0][1] = fmaf(a.x, bb.y, acc[0][1]);
            acc[0][2] = fmaf(a.x, bb.z, acc[0][2]); acc[0][3] = fmaf(a.x, bb.w, acc[0][3]);
            acc[1][0] = fmaf(a.y, bb.x, acc[1][0]); acc[1][1] = fmaf(a.y, bb.y, acc[1][1]);
            acc[1][2] = fmaf(a.y, bb.z, acc[1][2]); acc[1][3] = fmaf(a.y, bb.w, acc[1][3]);
            acc[2][0] = fmaf(a.z, bb.x, acc[2][0]); acc[2][1] = fmaf(a.z, bb.y, acc[2][1]);
            acc[2][2] = fmaf(a.z, bb.z, acc[2][2]); acc[2][3] = fmaf(a.z, bb.w, acc[2][3]);
            acc[3][0] = fmaf(a.w, bb.x, acc[3][0]); acc[3][1] = fmaf(a.w, bb.y, acc[3][1]);
            acc[3][2] = fmaf(a.w, bb.z, acc[3][2]); acc[3][3] = fmaf(a.w, bb.w, acc[3][3]);
        }
        __syncthreads();
    }
#pragma unroll
    for (int i = 0; i < 4; i++) {
        int row = row0 + ty * 4 + i;
        const float* xr = g_xproj + ((size_t)row * T_ + t) * H4_;
#pragma unroll
        for (int j = 0; j < 4; j++) {
            int col = col0 + tx * 4 + j;
            g_z[(size_t)row * H4_ + col] = acc[i][j] + xr[col] + b[col];
        }
    }
}

// scores = hn @ W_vocab + b_vocab    (M=4096, K=1024, N=10000, bounds on N)
__global__ __launch_bounds__(256) void gemm_vocab(const float* __restrict__ Wv,
                                                  const float* __restrict__ bv) {
    __shared__ float As[BK][BM + 4];
    __shared__ float Bs[BK][BN + 4];
    int row0 = blockIdx.y * BM, col0 = blockIdx.x * BN;
    int tid = threadIdx.x;
    int tx = tid & 15, ty = tid >> 4;
    float acc[4][4] = {};
    int am = tid >> 2, ak4 = (tid & 3) * 4;
    int bk = tid >> 4, bn4 = (tid & 15) * 4;
    for (int k0 = 0; k0 < H_; k0 += BK) {
        float4 av = *(const float4*)&g_hn[(size_t)(row0 + am) * H_ + k0 + ak4];
        As[ak4 + 0][am] = av.x; As[ak4 + 1][am] = av.y;
        As[ak4 + 2][am] = av.z; As[ak4 + 3][am] = av.w;
        int col = col0 + bn4;
        float4 bvv = make_float4(0.f, 0.f, 0.f, 0.f);
        if (col + 3 < V_) {
            bvv = *(const float4*)&Wv[(size_t)(k0 + bk) * V_ + col];
        } else {
            const float* brow = &Wv[(size_t)(k0 + bk) * V_];
            if (col + 0 < V_) bvv.x = brow[col + 0];
            if (col + 1 < V_) bvv.y = brow[col + 1];
            if (col + 2 < V_) bvv.z = brow[col + 2];
            if (col + 3 < V_) bvv.w = brow[col + 3];
        }
        *(float4*)&Bs[bk][bn4] = bvv;
        __syncthreads();
#pragma unroll
        for (int k = 0; k < BK; k++) {
            float4 a = *(float4*)&As[k][ty * 4];
            float4 bb = *(float4*)&Bs[k][tx * 4];
            acc[0][0] = fmaf(a.x, bb.x, acc[0][0]); acc[0][1] = fmaf(a.x, bb.y, acc[0][1]);
            acc[0][2] = fmaf(a.x, bb.z, acc[0][2]); acc[0][3] = fmaf(a.x, bb.w, acc[0][3]);
            acc[1][0] = fmaf(a.y, bb.x, acc[1][0]); acc[1][1] = fmaf(a.y, bb.y, acc[1][1]);
            acc[1][2] = fmaf(a.y, bb.z, acc[1][2]); acc[1][3] = fmaf(a.y, bb.w, acc[1][3]);
            acc[2][0] = fmaf(a.z, bb.x, acc[2][0]); acc[2][1] = fmaf(a.z, bb.y, acc[2][1]);
            acc[2][2] = fmaf(a.z, bb.z, acc[2][2]); acc[2][3] = fmaf(a.z, bb.w, acc[2][3]);
            acc[3][0] = fmaf(a.w, bb.x, acc[3][0]); acc[3][1] = fmaf(a.w, bb.y, acc[3][1]);
            acc[3][2] = fmaf(a.w, bb.z, acc[3][2]); acc[3][3] = fmaf(a.w, bb.w, acc[3][3]);
        }
        __syncthreads();
    }
#pragma unroll
    for (int i = 0; i < 4; i++) {
        int row = row0 + ty * 4 + i;
#pragma unroll
        for (int j = 0; j < 4; j++) {
            int col = col0 + tx * 4 + j;
            if (col < V_)
                g_scores[(size_t)row * V_ + col] = acc[i][j] + bv[col];
        }
    }
}

// ---------------- attention (shared by attn0 / gate_attn) ----------------
// block per n; hs = h[n,:] in smem (1024); writes g_attn[n,:]
__device__ __forceinline__ void attn_compute(int n, const float* hs, float* ws, float* wl) {
    float local[L_];
#pragma unroll
    for (int l = 0; l < L_; l++) local[l] = 0.0f;
    for (int h = threadIdx.x; h < H_; h += 256) {
        float hv = hs[h];
        const float* Ar = g_A + ((size_t)n * H_ + h) * L_;
#pragma unroll
        for (int l = 0; l < L_; l++) local[l] = fmaf(hv, Ar[l], local[l]);
    }
#pragma unroll
    for (int l = 0; l < L_; l++)
#pragma unroll
        for (int off = 16; off; off >>= 1)
            local[l] += __shfl_down_sync(0xffffffffu, local[l], off);
    int lane = threadIdx.x & 31, warp = threadIdx.x >> 5;
    if (lane == 0)
#pragma unroll
        for (int l = 0; l < L_; l++) ws[warp * L_ + l] = local[l];
    __syncthreads();
    if (threadIdx.x < L_) {
        float s = 0.0f;
        for (int w = 0; w < 8; w++) s += ws[w * L_ + threadIdx.x];
        wl[threadIdx.x] = s * 0.03125f;   // 1/sqrt(1024)
    }
    __syncthreads();
    if (threadIdx.x == 0) {
        float m = -1e30f;
        for (int l = 0; l < L_; l++) m = fmaxf(m, wl[l]);
        float se = 0.0f;
        for (int l = 0; l < L_; l++) { wl[l] = expf(wl[l] - m); se += wl[l]; }
        float inv = 1.0f / se;
        for (int l = 0; l < L_; l++) wl[l] *= inv;
    }
    __syncthreads();
    for (int h = threadIdx.x; h < H_; h += 256) {
        const float* Ar = g_A + ((size_t)n * H_ + h) * L_;
        float s = 0.0f;
#pragma unroll
        for (int l = 0; l < L_; l++) s = fmaf(Ar[l], wl[l], s);
        g_attn[n * H_ + h] = s;
    }
}

__global__ __launch_bounds__(256) void attn0() {
    int n = blockIdx.x;
    __shared__ float hs[H_];
    __shared__ float ws[8 * L_];
    __shared__ float wl[L_];
    for (int h = threadIdx.x; h < H_; h += 256) hs[h] = g_h[n * H_ + h];
    __syncthreads();
    attn_compute(n, hs, ws, wl);
}

// gates from g_z -> update h,c, store hn[t], then attn for next step
__global__ __launch_bounds__(256) void gate_attn(int t) {
    int n = blockIdx.x;
    __shared__ float hs[H_];
    __shared__ float ws[8 * L_];
    __shared__ float wl[L_];
    const float* zr = g_z + (size_t)n * H4_;
    for (int h = threadIdx.x; h < H_; h += 256) {
        float ai = zr[h], af = zr[H_ + h], ao = zr[2 * H_ + h], ag = zr[3 * H_ + h];
        float c = sigf(af) * g_c[n * H_ + h] + sigf(ai) * tanhf(ag);
        float hv = sigf(ao) * tanhf(c);
        g_c[n * H_ + h] = c;
        g_h[n * H_ + h] = hv;
        g_hn[((size_t)n * T_ + t) * H_ + h] = hv;
        hs[h] = hv;
    }
    __syncthreads();
    attn_compute(n, hs, ws, wl);
}

// ---------------- NLL reduce ----------------
__global__ __launch_bounds__(256) void loss_k(const int* __restrict__ captions,
                                              float* __restrict__ out) {
    int r = blockIdx.x;                 // row = n*T + t
    int tid = threadIdx.x;
    __shared__ float red[256];
    const float* sr = g_scores + (size_t)r * V_;
    float m = -1e30f;
    for (int i = tid; i < V_; i += 256) m = fmaxf(m, sr[i]);
    red[tid] = m; __syncthreads();
    for (int o = 128; o; o >>= 1) { if (tid < o) red[tid] = fmaxf(red[tid], red[tid + o]); __syncthreads(); }
    float mv = red[0]; __syncthreads();
    float s = 0.0f;
    for (int i = tid; i < V_; i += 256) s += expf(sr[i] - mv);
    red[tid] = s; __syncthreads();
    for (int o = 128; o; o >>= 1) { if (tid < o) red[tid] += red[tid + o]; __syncthreads(); }
    if (tid == 0) {
        int n = r >> 5, t = r & 31;
        int tgt = captions[n * TCAP + t + 1];
        if (tgt != 0) {
            float nll = logf(red[0]) + mv - sr[tgt];
            atomicAdd(out, nll * (1.0f / (float)N_));
        }
    }
}

// ---------------- launch ----------------
extern "C" void kernel_launch(void* const* d_in, const int* in_sizes, int n_in,
                              void* d_out, int out_size) {
    const float* features = (const float*)d_in[0];
    const int*   captions = (const int*)d_in[1];
    const float* W_embed  = (const float*)d_in[2];
    const float* W_proj   = (const float*)d_in[3];
    const float* b_proj   = (const float*)d_in[4];
    const float* Wx       = (const float*)d_in[5];
    const float* Wh       = (const float*)d_in[6];
    const float* Wattn    = (const float*)d_in[7];
    const float* b        = (const float*)d_in[8];
    const float* W_vocab  = (const float*)d_in[9];
    const float* b_vocab  = (const float*)d_in[10];
    float* out = (float*)d_out;

    init_out<<<1, 1>>>(out);
    kA<<<N_, 256>>>(features, W_proj, b_proj);
    gemm_embed<<<dim3(H4_ / BN, (N_ * T_) / BM), 256>>>(captions, W_embed, Wx);
    attn0<<<N_, 256>>>();
    for (int t = 0; t < T_; t++) {
        gemm_z<<<dim3(H4_ / BN, N_ / BM), 256>>>(Wh, Wattn, b, t);
        gate_attn<<<N_, 256>>>(t);
    }
    gemm_vocab<<<dim3((V_ + BN - 1) / BN, (N_ * T_) / BM), 256>>>(W_vocab, b_vocab);
    loss_k<<<N_ * T_, 256>>>(captions, out);
}

// round 2
// speedup vs baseline: 1.3024x; 1.3024x over previous
#include <cuda_runtime.h>
#include <math.h>

#define N_   128
#define T_   32
#define TCAP 33
#define D_   400
#define WE_  512
#define H_   1024
#define H4_  4096
#define V_   10000
#define L_   16

// ---------------- device scratch ----------------
__device__ float g_A[N_ * H_ * L_];                 // A_flat [n][h][l]
__device__ float g_At[N_ * L_ * H_];                // A^T    [(n*16+l)][h]
__device__ float g_P[(size_t)N_ * L_ * H4_];        // P[(n*16+l)][4H]  32 MB
__device__ float g_h[N_ * H_];
__device__ float g_c[N_ * H_];
__device__ float g_hn[N_ * T_ * H_];                // row = n*T + t
__device__ float g_xproj[(size_t)N_ * T_ * H4_];    // x@Wx + b, row = n*T+t
__device__ float g_z[N_ * H4_];
__device__ float g_zattn[N_ * H4_];                 // w·P per step
__device__ float g_scores[(size_t)N_ * T_ * V_];

__device__ __forceinline__ float sigf(float x) { return 1.0f / (1.0f + expf(-x)); }

__global__ void init_out(float* out) { out[0] = 0.0f; }

// ---------------- A_flat + A^T + h0/c0 ----------------
__global__ __launch_bounds__(256) void kA(const float* __restrict__ feat,
                                          const float* __restrict__ Wp,
                                          const float* __restrict__ bp) {
    int n = blockIdx.x;
    __shared__ float fsh[D_ * L_];
    const float* f = feat + (size_t)n * D_ * L_;
    for (int i = threadIdx.x; i < D_ * L_; i += 256) fsh[i] = f[i];
    __syncthreads();
    for (int h = threadIdx.x; h < H_; h += 256) {
        float acc[L_];
        float bb = bp[h];
#pragma unroll
        for (int l = 0; l < L_; l++) acc[l] = bb;
        for (int d = 0; d < D_; d++) {
            float wv = Wp[d * H_ + h];
            const float* fr = &fsh[d * L_];
#pragma unroll
            for (int l = 0; l < L_; l++) acc[l] = fmaf(fr[l], wv, acc[l]);
        }
        float s = 0.0f;
        float* Ar = g_A + ((size_t)n * H_ + h) * L_;
#pragma unroll
        for (int l = 0; l < L_; l++) {
            Ar[l] = acc[l];
            g_At[((size_t)n * L_ + l) * H_ + h] = acc[l];
            s += acc[l];
        }
        float h0 = s * (1.0f / 16.0f);
        g_h[n * H_ + h] = h0;
        g_c[n * H_ + h] = h0;
    }
}

// ================= 128x128x8 SGEMM core (double-buffered) =================
#define TBM 128
#define TBN 128
#define TBK 8

#define GEMM_FMA_BLOCK(buf_)                                                  \
    _Pragma("unroll")                                                         \
    for (int k = 0; k < TBK; k++) {                                           \
        float4 a0 = *(const float4*)&As[buf_][k][ty * 4];                     \
        float4 a1 = *(const float4*)&As[buf_][k][64 + ty * 4];                \
        float4 b0 = *(const float4*)&Bs[buf_][k][tx * 4];                     \
        float4 b1 = *(const float4*)&Bs[buf_][k][64 + tx * 4];                \
        float av[8] = {a0.x, a0.y, a0.z, a0.w, a1.x, a1.y, a1.z, a1.w};       \
        float bv[8] = {b0.x, b0.y, b0.z, b0.w, b1.x, b1.y, b1.z, b1.w};       \
        _Pragma("unroll")                                                     \
        for (int i = 0; i < 8; i++)                                           \
            _Pragma("unroll")                                                 \
            for (int j = 0; j < 8; j++)                                       \
                acc[i][j] = fmaf(av[i], bv[j], acc[i][j]);                    \
    }

#define GEMM_STORE_A(buf_)                                                    \
    As[buf_][aks + 0][arow] = areg.x; As[buf_][aks + 1][arow] = areg.y;       \
    As[buf_][aks + 2][arow] = areg.z; As[buf_][aks + 3][arow] = areg.w;

// xproj[(n*T+t), :] = W_embed[cap[n,t]] @ Wx + b   (M=4096, K=512, N=4096)
__global__ __launch_bounds__(256) void gemm_embed(const int* __restrict__ captions,
                                                  const float* __restrict__ Wemb,
                                                  const float* __restrict__ Wx,
                                                  const float* __restrict__ b) {
    __shared__ float As[2][TBK][TBM];
    __shared__ float Bs[2][TBK][TBN];
    int tid = threadIdx.x, tx = tid & 15, ty = tid >> 4;
    int row0 = blockIdx.y * TBM, col0 = blockIdx.x * TBN;
    int arow = tid >> 1, aks = (tid & 1) * 4;
    int bk = tid >> 5, bn4 = (tid & 31) * 4;
    int r = row0 + arow;
    int tok = captions[(r >> 5) * TCAP + (r & 31)];
    const float* Aptr = Wemb + (size_t)tok * WE_ + aks;
    const float* Bptr = Wx + (size_t)bk * H4_ + col0 + bn4;
    float acc[8][8] = {};
    float4 areg = *(const float4*)Aptr;
    float4 breg = *(const float4*)Bptr;
    GEMM_STORE_A(0)
    *(float4*)&Bs[0][bk][bn4] = breg;
    __syncthreads();
    const int nIter = WE_ / TBK;
    for (int it = 0; it < nIter; it++) {
        int buf = it & 1;
        if (it + 1 < nIter) {
            areg = *(const float4*)(Aptr + (it + 1) * TBK);
            breg = *(const float4*)(Bptr + (size_t)(it + 1) * TBK * H4_);
        }
        GEMM_FMA_BLOCK(buf)
        if (it + 1 < nIter) {
            int nb = buf ^ 1;
            GEMM_STORE_A(nb)
            *(float4*)&Bs[nb][bk][bn4] = breg;
        }
        __syncthreads();
    }
#pragma unroll
    for (int i = 0; i < 8; i++) {
        int row = row0 + ((i < 4) ? (ty * 4 + i) : (64 + ty * 4 + i - 4));
#pragma unroll
        for (int j = 0; j < 8; j++) {
            int col = col0 + ((j < 4) ? (tx * 4 + j) : (64 + tx * 4 + j - 4));
            g_xproj[(size_t)row * H4_ + col] = acc[i][j] + b[col];
        }
    }
}

// P = A^T @ Wattn   (M=2048, K=1024, N=4096)
__global__ __launch_bounds__(256) void gemm_P(const float* __restrict__ Wattn) {
    __shared__ float As[2][TBK][TBM];
    __shared__ float Bs[2][TBK][TBN];
    int tid = threadIdx.x, tx = tid & 15, ty = tid >> 4;
    int row0 = blockIdx.y * TBM, col0 = blockIdx.x * TBN;
    int arow = tid >> 1, aks = (tid & 1) * 4;
    int bk = tid >> 5, bn4 = (tid & 31) * 4;
    const float* Aptr = g_At + (size_t)(row0 + arow) * H_ + aks;
    const float* Bptr = Wattn + (size_t)bk * H4_ + col0 + bn4;
    float acc[8][8] = {};
    float4 areg = *(const float4*)Aptr;
    float4 breg = *(const float4*)Bptr;
    GEMM_STORE_A(0)
    *(float4*)&Bs[0][bk][bn4] = breg;
    __syncthreads();
    const int nIter = H_ / TBK;
    for (int it = 0; it < nIter; it++) {
        int buf = it & 1;
        if (it + 1 < nIter) {
            areg = *(const float4*)(Aptr + (it + 1) * TBK);
            breg = *(const float4*)(Bptr + (size_t)(it + 1) * TBK * H4_);
        }
        GEMM_FMA_BLOCK(buf)
        if (it + 1 < nIter) {
            int nb = buf ^ 1;
            GEMM_STORE_A(nb)
            *(float4*)&Bs[nb][bk][bn4] = breg;
        }
        __syncthreads();
    }
#pragma unroll
    for (int i = 0; i < 8; i++) {
        int row = row0 + ((i < 4) ? (ty * 4 + i) : (64 + ty * 4 + i - 4));
#pragma unroll
        for (int j = 0; j < 8; j++) {
            int col = col0 + ((j < 4) ? (tx * 4 + j) : (64 + tx * 4 + j - 4));
            g_P[(size_t)row * H4_ + col] = acc[i][j];
        }
    }
}

// scores = hn @ W_vocab + b_vocab   (M=4096, K=1024, N=10000)
__global__ __launch_bounds__(256) void gemm_vocab(const float* __restrict__ Wv,
                                                  const float* __restrict__ bv) {
    __shared__ float As[2][TBK][TBM];
    __shared__ float Bs[2][TBK][TBN];
    int tid = threadIdx.x, tx = tid & 15, ty = tid >> 4;
    int row0 = blockIdx.y * TBM, col0 = blockIdx.x * TBN;
    int arow = tid >> 1, aks = (tid & 1) * 4;
    int bk = tid >> 5, bn4 = (tid & 31) * 4;
    const float* Aptr = g_hn + (size_t)(row0 + arow) * H_ + aks;
    int bcol = col0 + bn4;
    bool bok = (bcol < V_);
    const float* Bptr = Wv + (size_t)bk * V_ + bcol;
    float acc[8][8] = {};
    float4 zero4 = make_float4(0.f, 0.f, 0.f, 0.f);
    float4 areg = *(const float4*)Aptr;
    float4 breg = bok ? *(const float4*)Bptr : zero4;
    GEMM_STORE_A(0)
    *(float4*)&Bs[0][bk][bn4] = breg;
    __syncthreads();
    const int nIter = H_ / TBK;
    for (int it = 0; it < nIter; it++) {
        int buf = it & 1;
        if (it + 1 < nIter) {
            areg = *(const float4*)(Aptr + (it + 1) * TBK);
            breg = bok ? *(const float4*)(Bptr + (size_t)(it + 1) * TBK * V_) : zero4;
        }
        GEMM_FMA_BLOCK(buf)
        if (it + 1 < nIter) {
            int nb = buf ^ 1;
            GEMM_STORE_A(nb)
            *(float4*)&Bs[nb][bk][bn4] = breg;
        }
        __syncthreads();
    }
#pragma unroll
    for (int i = 0; i < 8; i++) {
        int row = row0 + ((i < 4) ? (ty * 4 + i) : (64 + ty * 4 + i - 4));
#pragma unroll
        for (int j = 0; j < 8; j++) {
            int col = col0 + ((j < 4) ? (tx * 4 + j) : (64 + tx * 4 + j - 4));
            if (col < V_)
                g_scores[(size_t)row * V_ + col] = acc[i][j] + bv[col];
        }
    }
}

// ---------------- per-step GEMM: z = h @ Wh + xproj_t + zattn ----------------
// M=128 (all rows), BN=32, K=1024
#define ZBN 32
__global__ __launch_bounds__(256) void gemm_zh(const float* __restrict__ Wh, int t) {
    __shared__ float As[2][TBK][TBM];
    __shared__ float Bs[2][TBK][ZBN];
    int tid = threadIdx.x, tx = tid & 15, ty = tid >> 4;
    int col0 = blockIdx.x * ZBN;
    int arow = tid >> 1, aks = (tid & 1) * 4;
    int bk = tid >> 5, bn = tid & 31;
    const float* Aptr = g_h + (size_t)arow * H_ + aks;
    const float* Bptr = Wh + (size_t)bk * H4_ + col0 + bn;
    float acc[8][2] = {};
    float4 areg = *(const float4*)Aptr;
    float breg = *Bptr;
    GEMM_STORE_A(0)
    Bs[0][bk][bn] = breg;
    __syncthreads();
    const int nIter = H_ / TBK;
    for (int it = 0; it < nIter; it++) {
        int buf = it & 1;
        if (it + 1 < nIter) {
            areg = *(const float4*)(Aptr + (it + 1) * TBK);
            breg = *(Bptr + (size_t)(it + 1) * TBK * H4_);
        }
#pragma unroll
        for (int k = 0; k < TBK; k++) {
            float4 a0 = *(const float4*)&As[buf][k][ty * 4];
            float4 a1 = *(const float4*)&As[buf][k][64 + ty * 4];
            float2 bb = *(const float2*)&Bs[buf][k][tx * 2];
            float av[8] = {a0.x, a0.y, a0.z, a0.w, a1.x, a1.y, a1.z, a1.w};
#pragma unroll
            for (int i = 0; i < 8; i++) {
                acc[i][0] = fmaf(av[i], bb.x, acc[i][0]);
                acc[i][1] = fmaf(av[i], bb.y, acc[i][1]);
            }
        }
        if (it + 1 < nIter) {
            int nb = buf ^ 1;
            GEMM_STORE_A(nb)
            Bs[nb][bk][bn] = breg;
        }
        __syncthreads();
    }
#pragma unroll
    for (int i = 0; i < 8; i++) {
        int row = (i < 4) ? (ty * 4 + i) : (64 + ty * 4 + i - 4);
        const float* xr = g_xproj + ((size_t)row * T_ + t) * H4_;
        const float* za = g_zattn + (size_t)row * H4_;
#pragma unroll
        for (int j = 0; j < 2; j++) {
            int col = col0 + tx * 2 + j;
            g_z[(size_t)row * H4_ + col] = acc[i][j] + xr[col] + za[col];
        }
    }
}

// ---------------- attention weights + zattn (shared helper) ----------------
__device__ __forceinline__ void attn_w(int n, const float* hs, float* ws, float* wl) {
    float local[L_];
#pragma unroll
    for (int l = 0; l < L_; l++) local[l] = 0.0f;
    for (int h = threadIdx.x; h < H_; h += 256) {
        float hv = hs[h];
        const float* Ar = g_A + ((size_t)n * H_ + h) * L_;
#pragma unroll
        for (int l = 0; l < L_; l++) local[l] = fmaf(hv, Ar[l], local[l]);
    }
#pragma unroll
    for (int l = 0; l < L_; l++)
#pragma unroll
        for (int off = 16; off; off >>= 1)
            local[l] += __shfl_down_sync(0xffffffffu, local[l], off);
    int lane = threadIdx.x & 31, warp = threadIdx.x >> 5;
    if (lane == 0)
#pragma unroll
        for (int l = 0; l < L_; l++) ws[warp * L_ + l] = local[l];
    __syncthreads();
    if (threadIdx.x < L_) {
        float s = 0.0f;
        for (int w = 0; w < 8; w++) s += ws[w * L_ + threadIdx.x];
        wl[threadIdx.x] = s * 0.03125f;
    }
    __syncthreads();
    if (threadIdx.x == 0) {
        float m = -1e30f;
        for (int l = 0; l < L_; l++) m = fmaxf(m, wl[l]);
        float se = 0.0f;
        for (int l = 0; l < L_; l++) { wl[l] = expf(wl[l] - m); se += wl[l]; }
        float inv = 1.0f / se;
        for (int l = 0; l < L_; l++) wl[l] *= inv;
    }
    __syncthreads();
    // zattn[n, :] = sum_l w_l * P[n,l,:]
    for (int col = threadIdx.x; col < H4_; col += 256) {
        float s = 0.0f;
        const float* Pr = g_P + (size_t)n * L_ * H4_ + col;
#pragma unroll
        for (int l = 0; l < L_; l++) s = fmaf(wl[l], Pr[(size_t)l * H4_], s);
        g_zattn[(size_t)n * H4_ + col] = s;
    }
}

__global__ __launch_bounds__(256) void init_w() {
    int n = blockIdx.x;
    __shared__ float hs[H_];
    __shared__ float ws[8 * L_];
    __shared__ float wl[L_];
    for (int h = threadIdx.x; h < H_; h += 256) hs[h] = g_h[n * H_ + h];
    __syncthreads();
    attn_w(n, hs, ws, wl);
}

// gates -> h,c,hn; then attention weights + zattn for next step
__global__ __launch_bounds__(256) void gate_attn(int t) {
    int n = blockIdx.x;
    __shared__ float hs[H_];
    __shared__ float ws[8 * L_];
    __shared__ float wl[L_];
    const float* zr = g_z + (size_t)n * H4_;
    for (int h = threadIdx.x; h < H_; h += 256) {
        float ai = zr[h], af = zr[H_ + h], ao = zr[2 * H_ + h], ag = zr[3 * H_ + h];
        float c = sigf(af) * g_c[n * H_ + h] + sigf(ai) * tanhf(ag);
        float hv = sigf(ao) * tanhf(c);
        g_c[n * H_ + h] = c;
        g_h[n * H_ + h] = hv;
        g_hn[((size_t)n * T_ + t) * H_ + h] = hv;
        hs[h] = hv;
    }
    __syncthreads();
    attn_w(n, hs, ws, wl);
}

// ---------------- NLL reduce ----------------
__global__ __launch_bounds__(256) void loss_k(const int* __restrict__ captions,
                                              float* __restrict__ out) {
    int r = blockIdx.x;
    int tid = threadIdx.x;
    __shared__ float red[256];
    const float* sr = g_scores + (size_t)r * V_;
    float m = -1e30f;
    for (int i = tid; i < V_; i += 256) m = fmaxf(m, sr[i]);
    red[tid] = m; __syncthreads();
    for (int o = 128; o; o >>= 1) { if (tid < o) red[tid] = fmaxf(red[tid], red[tid + o]); __syncthreads(); }
    float mv = red[0]; __syncthreads();
    float s = 0.0f;
    for (int i = tid; i < V_; i += 256) s += expf(sr[i] - mv);
    red[tid] = s; __syncthreads();
    for (int o = 128; o; o >>= 1) { if (tid < o) red[tid] += red[tid + o]; __syncthreads(); }
    if (tid == 0) {
        int n = r >> 5, t = r & 31;
        int tgt = captions[n * TCAP + t + 1];
        if (tgt != 0) {
            float nll = logf(red[0]) + mv - sr[tgt];
            atomicAdd(out, nll * (1.0f / (float)N_));
        }
    }
}

// ---------------- launch ----------------
extern "C" void kernel_launch(void* const* d_in, const int* in_sizes, int n_in,
                              void* d_out, int out_size) {
    const float* features = (const float*)d_in[0];
    const int*   captions = (const int*)d_in[1];
    const float* W_embed  = (const float*)d_in[2];
    const float* W_proj   = (const float*)d_in[3];
    const float* b_proj   = (const float*)d_in[4];
    const float* Wx       = (const float*)d_in[5];
    const float* Wh       = (const float*)d_in[6];
    const float* Wattn    = (const float*)d_in[7];
    const float* b        = (const float*)d_in[8];
    const float* W_vocab  = (const float*)d_in[9];
    const float* b_vocab  = (const float*)d_in[10];
    float* out = (float*)d_out;

    init_out<<<1, 1>>>(out);
    kA<<<N_, 256>>>(features, W_proj, b_proj);
    gemm_embed<<<dim3(H4_ / TBN, (N_ * T_) / TBM), 256>>>(captions, W_embed, Wx, b);
    gemm_P<<<dim3(H4_ / TBN, (N_ * L_) / TBM), 256>>>(Wattn);
    init_w<<<N_, 256>>>();
    for (int t = 0; t < T_; t++) {
        gemm_zh<<<H4_ / ZBN, 256>>>(Wh, t);
        gate_attn<<<N_, 256>>>(t);
    }
    gemm_vocab<<<dim3((V_ + TBN - 1) / TBN, (N_ * T_) / TBM), 256>>>(W_vocab, b_vocab);
    loss_k<<<N_ * T_, 256>>>(captions, out);
}

// round 3
// speedup vs baseline: 2.6317x; 2.0206x over previous
#include <cuda_runtime.h>
#include <math.h>

#define N_   128
#define T_   32
#define TCAP 33
#define D_   400
#define WE_  512
#define H_   1024
#define H4_  4096
#define V_   10000
#define L_   16

// ---------------- device scratch ----------------
__device__ float g_A[N_ * H_ * L_];
__device__ float g_At[N_ * L_ * H_];
__device__ float g_P[(size_t)N_ * L_ * H4_];
__device__ float g_h[N_ * H_];
__device__ float g_c[N_ * H_];
__device__ float g_hn[N_ * T_ * H_];
__device__ float g_xproj[(size_t)N_ * T_ * H4_];
__device__ float g_zpart[(size_t)4 * N_ * H4_];
__device__ float g_zattn[N_ * H4_];
__device__ float g_scores[(size_t)N_ * T_ * V_];

__device__ __forceinline__ float sigf(float x) { return 1.0f / (1.0f + expf(-x)); }
__device__ __forceinline__ float tf32r(float x) {
    unsigned u; asm("cvt.rna.tf32.f32 %0, %1;" : "=r"(u) : "f"(x));
    return __uint_as_float(u);
}

__global__ void init_out(float* out) { out[0] = 0.0f; }

// ---------------- A_flat + A^T + h0/c0 (fp32) ----------------
__global__ __launch_bounds__(256) void kA(const float* __restrict__ feat,
                                          const float* __restrict__ Wp,
                                          const float* __restrict__ bp) {
    int n = blockIdx.x;
    __shared__ float fsh[D_ * L_];
    const float* f = feat + (size_t)n * D_ * L_;
    for (int i = threadIdx.x; i < D_ * L_; i += 256) fsh[i] = f[i];
    __syncthreads();
    for (int h = threadIdx.x; h < H_; h += 256) {
        float acc[L_];
        float bb = bp[h];
#pragma unroll
        for (int l = 0; l < L_; l++) acc[l] = bb;
        for (int d = 0; d < D_; d++) {
            float wv = Wp[d * H_ + h];
            const float* fr = &fsh[d * L_];
#pragma unroll
            for (int l = 0; l < L_; l++) acc[l] = fmaf(fr[l], wv, acc[l]);
        }
        float s = 0.0f;
        float* Ar = g_A + ((size_t)n * H_ + h) * L_;
#pragma unroll
        for (int l = 0; l < L_; l++) {
            Ar[l] = acc[l];
            g_At[((size_t)n * L_ + l) * H_ + h] = acc[l];
            s += acc[l];
        }
        float h0 = s * (1.0f / 16.0f);
        g_h[n * H_ + h] = h0;
        g_c[n * H_ + h] = h0;
    }
}

// ================= TF32 mma GEMM core (128x128 tile, 8 warps) =================
// smem fragment layouts (padded for bank behavior, 16B-aligned strides):
//   A: [buf][kt (stride 1028)][mtile (stride 128)][f*4 + reg]
//   B: [buf][kt (stride 1056)][ntile (stride 66)][lane*2 + reg]
#define ASP(bf, kt, mt, w) As_p[bf][(kt) * 1028 + (mt) * 128 + (w)]
#define BSP(bf, kt, nt, w) Bs_p[bf][(kt) * 1056 + (nt) * 66 + (w)]

#define TFG_DECL                                                               \
    __shared__ float As_p[2][2056];                                            \
    __shared__ float Bs_p[2][2112];                                            \
    int tid = threadIdx.x, lane = tid & 31, wid = tid >> 5;                    \
    int wm = wid >> 1, wn = wid & 1;                                           \
    int arow = tid >> 1, ak0 = (tid & 1) * 8;                                  \
    int bkrow = tid >> 4, bn0 = (tid & 15) * 8;                                \
    int amtile = arow >> 4, amloc = arow & 15;                                 \
    int akt = ak0 >> 3;                                                        \
    int bkt = bkrow >> 3, bntile = bn0 >> 3;                                   \
    int bbase = (bkrow & 3) * 2 + ((bkrow >> 2) & 1);                          \
    int aoff = ((((lane >> 2) + 2 * (lane & 3)) & 7) + 8 * (lane & 3)) * 4;    \
    float acc[2][8][4];                                                        \
    _Pragma("unroll") for (int i_ = 0; i_ < 2; i_++)                           \
    _Pragma("unroll") for (int j_ = 0; j_ < 8; j_++)                           \
    _Pragma("unroll") for (int q_ = 0; q_ < 4; q_++) acc[i_][j_][q_] = 0.f;    \
    float4 areg0, areg1, breg0, breg1;

#define TFG_STAGE(nb) {                                                        \
    float av_[8] = {areg0.x, areg0.y, areg0.z, areg0.w,                        \
                    areg1.x, areg1.y, areg1.z, areg1.w};                       \
    _Pragma("unroll") for (int j = 0; j < 8; j++) {                            \
        int c_ = j & 3;                                                        \
        int fx_ = (((amloc & 7) + 2 * c_) & 7) + 8 * c_;                       \
        int rg_ = (amloc >> 3) + 2 * ((j >> 2) & 1);                           \
        ASP(nb, akt, amtile, fx_ * 4 + rg_) = tf32r(av_[j]);                   \
    }                                                                          \
    float bv_[8] = {breg0.x, breg0.y, breg0.z, breg0.w,                        \
                    breg1.x, breg1.y, breg1.z, breg1.w};                       \
    _Pragma("unroll") for (int j = 0; j < 8; j++)                              \
        BSP(nb, bkt, bntile, j * 8 + bbase) = tf32r(bv_[j]);                   \
    }

#define TFG_MMA(c, a, b0v, b1v)                                                \
    asm volatile("mma.sync.aligned.m16n8k8.row.col.f32.tf32.tf32.f32 "         \
                 "{%0,%1,%2,%3},{%4,%5,%6,%7},{%8,%9},{%0,%1,%2,%3};"          \
                 : "+f"((c)[0]), "+f"((c)[1]), "+f"((c)[2]), "+f"((c)[3])      \
                 : "r"((a)[0]), "r"((a)[1]), "r"((a)[2]), "r"((a)[3]),         \
                   "r"(b0v), "r"(b1v))

#define TFG_COMPUTE(bf)                                                        \
    _Pragma("unroll") for (int kt = 0; kt < 2; kt++) {                         \
        unsigned af_[2][4];                                                    \
        _Pragma("unroll") for (int mt = 0; mt < 2; mt++) {                     \
            float4 ta_ = *(const float4*)&ASP(bf, kt, wm * 2 + mt, aoff);      \
            af_[mt][0] = __float_as_uint(ta_.x);                               \
            af_[mt][1] = __float_as_uint(ta_.y);                               \
            af_[mt][2] = __float_as_uint(ta_.z);                               \
            af_[mt][3] = __float_as_uint(ta_.w);                               \
        }                                                                      \
        _Pragma("unroll") for (int nt = 0; nt < 8; nt++) {                     \
            float2 tb_ = *(const float2*)&BSP(bf, kt, wn * 8 + nt, lane * 2);  \
            unsigned ub0_ = __float_as_uint(tb_.x);                            \
            unsigned ub1_ = __float_as_uint(tb_.y);                            \
            TFG_MMA(acc[0][nt], af_[0], ub0_, ub1_);                           \
            TFG_MMA(acc[1][nt], af_[1], ub0_, ub1_);                           \
        }                                                                      \
    }

#define TFG_LOOP(NIT, AF, BF)                                                  \
    AF(0) BF(0) TFG_STAGE(0) __syncthreads();                                  \
    for (int it = 0; it < (NIT); it++) {                                       \
        int buf_ = it & 1;                                                     \
        if (it + 1 < (NIT)) { AF(it + 1) BF(it + 1) }                          \
        TFG_COMPUTE(buf_)                                                      \
        if (it + 1 < (NIT)) { TFG_STAGE(buf_ ^ 1) }                            \
        __syncthreads();                                                       \
    }

// ---- xproj = W_embed[cap] @ Wx + b   (M=4096, K=512, N=4096) ----
__global__ __launch_bounds__(256) void gemm_embed(const int* __restrict__ captions,
                                                  const float* __restrict__ Wemb,
                                                  const float* __restrict__ Wx,
                                                  const float* __restrict__ bias) {
    int row0 = blockIdx.y * 128, col0 = blockIdx.x * 128;
    TFG_DECL;
    int r = row0 + arow;
    const float* Arow = Wemb + (size_t)captions[(r >> 5) * TCAP + (r & 31)] * WE_ + ak0;
    const float* Bcol = Wx + col0 + bn0 + (size_t)bkrow * H4_;
#define AF_E(it) { const float* p_ = Arow + (it) * 16; \
    areg0 = *(const float4*)p_; areg1 = *(const float4*)(p_ + 4); }
#define BF_E(it) { const float* p_ = Bcol + (size_t)(it) * 16 * H4_; \
    breg0 = *(const float4*)p_; breg1 = *(const float4*)(p_ + 4); }
    TFG_LOOP(WE_ / 16, AF_E, BF_E)
#undef AF_E
#undef BF_E
    int eg = lane >> 2, ec = (lane & 3) * 2;
#pragma unroll
    for (int mt = 0; mt < 2; mt++)
#pragma unroll
        for (int nt = 0; nt < 8; nt++) {
            int row = row0 + wm * 32 + mt * 16 + eg;
            int col = col0 + wn * 64 + nt * 8 + ec;
            float b0 = bias[col], b1 = bias[col + 1];
            *(float2*)&g_xproj[(size_t)row * H4_ + col] =
                make_float2(acc[mt][nt][0] + b0, acc[mt][nt][1] + b1);
            *(float2*)&g_xproj[(size_t)(row + 8) * H4_ + col] =
                make_float2(acc[mt][nt][2] + b0, acc[mt][nt][3] + b1);
        }
}

// ---- P = A^T @ Wattn   (M=2048, K=1024, N=4096) ----
__global__ __launch_bounds__(256) void gemm_P(const float* __restrict__ Wattn) {
    int row0 = blockIdx.y * 128, col0 = blockIdx.x * 128;
    TFG_DECL;
    const float* Arow = g_At + (size_t)(row0 + arow) * H_ + ak0;
    const float* Bcol = Wattn + col0 + bn0 + (size_t)bkrow * H4_;
#define AF_P(it) { const float* p_ = Arow + (it) * 16; \
    areg0 = *(const float4*)p_; areg1 = *(const float4*)(p_ + 4); }
#define BF_P(it) { const float* p_ = Bcol + (size_t)(it) * 16 * H4_; \
    breg0 = *(const float4*)p_; breg1 = *(const float4*)(p_ + 4); }
    TFG_LOOP(H_ / 16, AF_P, BF_P)
#undef AF_P
#undef BF_P
    int eg = lane >> 2, ec = (lane & 3) * 2;
#pragma unroll
    for (int mt = 0; mt < 2; mt++)
#pragma unroll
        for (int nt = 0; nt < 8; nt++) {
            int row = row0 + wm * 32 + mt * 16 + eg;
            int col = col0 + wn * 64 + nt * 8 + ec;
            *(float2*)&g_P[(size_t)row * H4_ + col] =
                make_float2(acc[mt][nt][0], acc[mt][nt][1]);
            *(float2*)&g_P[(size_t)(row + 8) * H4_ + col] =
                make_float2(acc[mt][nt][2], acc[mt][nt][3]);
        }
}

// ---- scores = hn @ W_vocab + b_vocab   (M=4096, K=1024, N=10000) ----
__global__ __launch_bounds__(256) void gemm_vocab(const float* __restrict__ Wv,
                                                  const float* __restrict__ bv) {
    int row0 = blockIdx.y * 128, col0 = blockIdx.x * 128;
    TFG_DECL;
    const float* Arow = g_hn + (size_t)(row0 + arow) * H_ + ak0;
    int bc = col0 + bn0;
    bool bfull = (bc + 7) < V_;
    const float* Bcol = Wv + bc + (size_t)bkrow * V_;
#define AF_V(it) { const float* p_ = Arow + (it) * 16; \
    areg0 = *(const float4*)p_; areg1 = *(const float4*)(p_ + 4); }
#define BF_V(it) { const float* p_ = Bcol + (size_t)(it) * 16 * V_; \
    if (bfull) { breg0 = *(const float4*)p_; breg1 = *(const float4*)(p_ + 4); } \
    else { float t_[8]; \
        _Pragma("unroll") for (int q = 0; q < 8; q++) t_[q] = (bc + q < V_) ? p_[q] : 0.f; \
        breg0 = make_float4(t_[0], t_[1], t_[2], t_[3]); \
        breg1 = make_float4(t_[4], t_[5], t_[6], t_[7]); } }
    TFG_LOOP(H_ / 16, AF_V, BF_V)
#undef AF_V
#undef BF_V
    int eg = lane >> 2, ec = (lane & 3) * 2;
#pragma unroll
    for (int mt = 0; mt < 2; mt++)
#pragma unroll
        for (int nt = 0; nt < 8; nt++) {
            int row = row0 + wm * 32 + mt * 16 + eg;
            int col = col0 + wn * 64 + nt * 8 + ec;
            if (col < V_) {
                float b0 = bv[col], b1 = bv[col + 1];
                *(float2*)&g_scores[(size_t)row * V_ + col] =
                    make_float2(acc[mt][nt][0] + b0, acc[mt][nt][1] + b1);
                *(float2*)&g_scores[(size_t)(row + 8) * V_ + col] =
                    make_float2(acc[mt][nt][2] + b0, acc[mt][nt][3] + b1);
            }
        }
}

// ---- per-step: zpart[ks] = h @ Wh[k-slice]   (M=128, K=256/slice, N=4096) ----
__global__ __launch_bounds__(256) void gemm_zh(const float* __restrict__ Wh) {
    int col0 = blockIdx.x * 128;
    int ks = blockIdx.y;
    TFG_DECL;
    const float* Arow = g_h + (size_t)arow * H_ + ks * 256 + ak0;
    const float* Bcol = Wh + col0 + bn0 + (size_t)(ks * 256 + bkrow) * H4_;
#define AF_Z(it) { const float* p_ = Arow + (it) * 16; \
    areg0 = *(const float4*)p_; areg1 = *(const float4*)(p_ + 4); }
#define BF_Z(it) { const float* p_ = Bcol + (size_t)(it) * 16 * H4_; \
    breg0 = *(const float4*)p_; breg1 = *(const float4*)(p_ + 4); }
    TFG_LOOP(16, AF_Z, BF_Z)
#undef AF_Z
#undef BF_Z
    int eg = lane >> 2, ec = (lane & 3) * 2;
#pragma unroll
    for (int mt = 0; mt < 2; mt++)
#pragma unroll
        for (int nt = 0; nt < 8; nt++) {
            int row = wm * 32 + mt * 16 + eg;
            int col = col0 + wn * 64 + nt * 8 + ec;
            *(float2*)&g_zpart[((size_t)ks * N_ + row) * H4_ + col] =
                make_float2(acc[mt][nt][0], acc[mt][nt][1]);
            *(float2*)&g_zpart[((size_t)ks * N_ + row + 8) * H4_ + col] =
                make_float2(acc[mt][nt][2], acc[mt][nt][3]);
        }
}

// ---------------- attention weights + zattn ----------------
__device__ __forceinline__ void attn_w(int n, const float* hs, float* ws, float* wl) {
    float local[L_];
#pragma unroll
    for (int l = 0; l < L_; l++) local[l] = 0.0f;
    for (int h = threadIdx.x; h < H_; h += 256) {
        float hv = hs[h];
        const float* Ar = g_A + ((size_t)n * H_ + h) * L_;
#pragma unroll
        for (int l = 0; l < L_; l++) local[l] = fmaf(hv, Ar[l], local[l]);
    }
#pragma unroll
    for (int l = 0; l < L_; l++)
#pragma unroll
        for (int off = 16; off; off >>= 1)
            local[l] += __shfl_down_sync(0xffffffffu, local[l], off);
    int lane = threadIdx.x & 31, warp = threadIdx.x >> 5;
    if (lane == 0)
#pragma unroll
        for (int l = 0; l < L_; l++) ws[warp * L_ + l] = local[l];
    __syncthreads();
    if (threadIdx.x < L_) {
        float s = 0.0f;
        for (int w = 0; w < 8; w++) s += ws[w * L_ + threadIdx.x];
        wl[threadIdx.x] = s * 0.03125f;
    }
    __syncthreads();
    if (threadIdx.x == 0) {
        float m = -1e30f;
        for (int l = 0; l < L_; l++) m = fmaxf(m, wl[l]);
        float se = 0.0f;
        for (int l = 0; l < L_; l++) { wl[l] = expf(wl[l] - m); se += wl[l]; }
        float inv = 1.0f / se;
        for (int l = 0; l < L_; l++) wl[l] *= inv;
    }
    __syncthreads();
    for (int col = threadIdx.x; col < H4_; col += 256) {
        float s = 0.0f;
        const float* Pr = g_P + (size_t)n * L_ * H4_ + col;
#pragma unroll
        for (int l = 0; l < L_; l++) s = fmaf(wl[l], Pr[(size_t)l * H4_], s);
        g_zattn[(size_t)n * H4_ + col] = s;
    }
}

__global__ __launch_bounds__(256) void init_w() {
    int n = blockIdx.x;
    __shared__ float hs[H_];
    __shared__ float ws[8 * L_];
    __shared__ float wl[L_];
    for (int h = threadIdx.x; h < H_; h += 256) hs[h] = g_h[n * H_ + h];
    __syncthreads();
    attn_w(n, hs, ws, wl);
}

__global__ __launch_bounds__(256) void gate_attn(int t) {
    int n = blockIdx.x;
    __shared__ float hs[H_];
    __shared__ float ws[8 * L_];
    __shared__ float wl[L_];
    const float* xr = g_xproj + ((size_t)n * T_ + t) * H4_;
    const float* za = g_zattn + (size_t)n * H4_;
    for (int h = threadIdx.x; h < H_; h += 256) {
        float zi = 0.f, zf = 0.f, zo = 0.f, zg = 0.f;
#pragma unroll
        for (int ks = 0; ks < 4; ks++) {
            const float* zp = g_zpart + ((size_t)ks * N_ + n) * H4_;
            zi += zp[h]; zf += zp[H_ + h]; zo += zp[2 * H_ + h]; zg += zp[3 * H_ + h];
        }
        float ai = zi + xr[h] + za[h];
        float af = zf + xr[H_ + h] + za[H_ + h];
        float ao = zo + xr[2 * H_ + h] + za[2 * H_ + h];
        float ag = zg + xr[3 * H_ + h] + za[3 * H_ + h];
        float c = sigf(af) * g_c[n * H_ + h] + sigf(ai) * tanhf(ag);
        float hv = sigf(ao) * tanhf(c);
        g_c[n * H_ + h] = c;
        g_h[n * H_ + h] = hv;
        g_hn[((size_t)n * T_ + t) * H_ + h] = hv;
        hs[h] = hv;
    }
    __syncthreads();
    attn_w(n, hs, ws, wl);
}

// ---------------- NLL reduce ----------------
__global__ __launch_bounds__(256) void loss_k(const int* __restrict__ captions,
                                              float* __restrict__ out) {
    int r = blockIdx.x;
    int tid = threadIdx.x;
    __shared__ float red[256];
    const float* sr = g_scores + (size_t)r * V_;
    float m = -1e30f;
    for (int i = tid; i < V_; i += 256) m = fmaxf(m, sr[i]);
    red[tid] = m; __syncthreads();
    for (int o = 128; o; o >>= 1) { if (tid < o) red[tid] = fmaxf(red[tid], red[tid + o]); __syncthreads(); }
    float mv = red[0]; __syncthreads();
    float s = 0.0f;
    for (int i = tid; i < V_; i += 256) s += expf(sr[i] - mv);
    red[tid] = s; __syncthreads();
    for (int o = 128; o; o >>= 1) { if (tid < o) red[tid] += red[tid + o]; __syncthreads(); }
    if (tid == 0) {
        int n = r >> 5, t = r & 31;
        int tgt = captions[n * TCAP + t + 1];
        if (tgt != 0) {
            float nll = logf(red[0]) + mv - sr[tgt];
            atomicAdd(out, nll * (1.0f / (float)N_));
        }
    }
}

// ---------------- launch ----------------
extern "C" void kernel_launch(void* const* d_in, const int* in_sizes, int n_in,
                              void* d_out, int out_size) {
    const float* features = (const float*)d_in[0];
    const int*   captions = (const int*)d_in[1];
    const float* W_embed  = (const float*)d_in[2];
    const float* W_proj   = (const float*)d_in[3];
    const float* b_proj   = (const float*)d_in[4];
    const float* Wx       = (const float*)d_in[5];
    const float* Wh       = (const float*)d_in[6];
    const float* Wattn    = (const float*)d_in[7];
    const float* b        = (const float*)d_in[8];
    const float* W_vocab  = (const float*)d_in[9];
    const float* b_vocab  = (const float*)d_in[10];
    float* out = (float*)d_out;

    init_out<<<1, 1>>>(out);
    kA<<<N_, 256>>>(features, W_proj, b_proj);
    gemm_embed<<<dim3(H4_ / 128, (N_ * T_) / 128), 256>>>(captions, W_embed, Wx, b);
    gemm_P<<<dim3(H4_ / 128, (N_ * L_) / 128), 256>>>(Wattn);
    init_w<<<N_, 256>>>();
    for (int t = 0; t < T_; t++) {
        gemm_zh<<<dim3(H4_ / 128, 4), 256>>>(Wh);
        gate_attn<<<N_, 256>>>(t);
    }
    gemm_vocab<<<dim3((V_ + 127) / 128, (N_ * T_) / 128), 256>>>(W_vocab, b_vocab);
    loss_k<<<N_ * T_, 256>>>(captions, out);
}

// round 6
// speedup vs baseline: 3.9229x; 1.4907x over previous
#include <cuda_runtime.h>
#include <cuda_bf16.h>
#include <cstdint>
#include <math.h>

#define N_   128
#define T_   32
#define TCAP 33
#define D_   400
#define WE_  512
#define H_   1024
#define H4_  4096
#define V_   10000
#define L_   16

// ---------------- device scratch ----------------
__device__ float g_A[N_ * H_ * L_];
__device__ float g_P[(size_t)N_ * L_ * H4_];
__device__ float g_h[N_ * H_];
__device__ float g_c[N_ * H_];
__device__ float g_xproj[(size_t)N_ * T_ * H4_];
__device__ float g_zpart[(size_t)4 * N_ * H4_];
__device__ float g_zattn[N_ * H4_];
__device__ float g_scores[(size_t)N_ * T_ * V_];

// bf16 operands
__device__ __nv_bfloat16 gb_Wemb[(size_t)V_ * WE_];
__device__ __nv_bfloat16 gb_Wx[(size_t)WE_ * H4_];
__device__ __nv_bfloat16 gb_Wh[(size_t)H_ * H4_];
__device__ __nv_bfloat16 gb_Wattn[(size_t)H_ * H4_];
__device__ __nv_bfloat16 gb_Wv[(size_t)H_ * V_];
__device__ __nv_bfloat16 gb_At[N_ * L_ * H_];
__device__ __nv_bfloat16 gb_h[N_ * H_];
__device__ __nv_bfloat16 gb_hn[N_ * T_ * H_];

__device__ __forceinline__ float sigf(float x) { return 1.0f / (1.0f + expf(-x)); }

__global__ void init_out(float* out) { out[0] = 0.0f; }

// ---------------- fp32 -> bf16 conversion ----------------
__global__ __launch_bounds__(256) void f2b(const float* __restrict__ s,
                                           __nv_bfloat16* __restrict__ d, int n) {
    int i = (blockIdx.x * 256 + threadIdx.x) * 8;
    if (i >= n) return;
    float4 v0 = *(const float4*)(s + i);
    float4 v1 = *(const float4*)(s + i + 4);
    union { __nv_bfloat162 h2[4]; uint4 u; } o;
    o.h2[0] = __floats2bfloat162_rn(v0.x, v0.y);
    o.h2[1] = __floats2bfloat162_rn(v0.z, v0.w);
    o.h2[2] = __floats2bfloat162_rn(v1.x, v1.y);
    o.h2[3] = __floats2bfloat162_rn(v1.z, v1.w);
    *(uint4*)(d + i) = o.u;
}

// ---------------- A_flat + A^T + h0/c0 ----------------
__global__ __launch_bounds__(256) void kA(const float* __restrict__ feat,
                                          const float* __restrict__ Wp,
                                          const float* __restrict__ bp) {
    int n = blockIdx.x;
    __shared__ float fsh[D_ * L_];
    const float* f = feat + (size_t)n * D_ * L_;
    for (int i = threadIdx.x; i < D_ * L_; i += 256) fsh[i] = f[i];
    __syncthreads();
    for (int h = threadIdx.x; h < H_; h += 256) {
        float acc[L_];
        float bb = bp[h];
#pragma unroll
        for (int l = 0; l < L_; l++) acc[l] = bb;
        for (int d = 0; d < D_; d++) {
            float wv = Wp[d * H_ + h];
            const float* fr = &fsh[d * L_];
#pragma unroll
            for (int l = 0; l < L_; l++) acc[l] = fmaf(fr[l], wv, acc[l]);
        }
        float s = 0.0f;
        float* Ar = g_A + ((size_t)n * H_ + h) * L_;
#pragma unroll
        for (int l = 0; l < L_; l++) {
            Ar[l] = acc[l];
            gb_At[((size_t)n * L_ + l) * H_ + h] = __float2bfloat16_rn(acc[l]);
            s += acc[l];
        }
        float h0 = s * (1.0f / 16.0f);
        g_h[n * H_ + h] = h0;
        g_c[n * H_ + h] = h0;
        gb_h[n * H_ + h] = __float2bfloat16_rn(h0);
    }
}

// ================= BF16 mma GEMM core =================
// CTA 128(M) x 128(N), BK=32 bf16, 8 warps, warp tile 32x64.
// A smem: 128 rows x 128B; data chunk g (0..3) at  m*128 + ((g^(m&7))&7)*16
// B smem: 32 k-rows x 256B; chunk g (0..15)  at  k*256 + ((g^(k&7))*16)

__device__ __forceinline__ void ldsm4(uint32_t a, unsigned& r0, unsigned& r1,
                                      unsigned& r2, unsigned& r3) {
    asm volatile("ldmatrix.sync.aligned.m8n8.x4.shared.b16 {%0,%1,%2,%3}, [%4];"
                 : "=r"(r0), "=r"(r1), "=r"(r2), "=r"(r3) : "r"(a));
}
__device__ __forceinline__ void ldsm4t(uint32_t a, unsigned& r0, unsigned& r1,
                                       unsigned& r2, unsigned& r3) {
    asm volatile("ldmatrix.sync.aligned.m8n8.x4.trans.shared.b16 {%0,%1,%2,%3}, [%4];"
                 : "=r"(r0), "=r"(r1), "=r"(r2), "=r"(r3) : "r"(a));
}
__device__ __forceinline__ void bmma(float* c, const unsigned* a,
                                     unsigned b0, unsigned b1) {
    asm volatile("mma.sync.aligned.m16n8k16.row.col.f32.bf16.bf16.f32 "
                 "{%0,%1,%2,%3},{%4,%5,%6,%7},{%8,%9},{%0,%1,%2,%3};"
                 : "+f"(c[0]), "+f"(c[1]), "+f"(c[2]), "+f"(c[3])
                 : "r"(a[0]), "r"(a[1]), "r"(a[2]), "r"(a[3]), "r"(b0), "r"(b1));
}
__device__ __forceinline__ void cpa16(uint32_t dst, const void* src) {
    asm volatile("cp.async.cg.shared.global [%0], [%1], 16;" ::"r"(dst), "l"(src));
}
__device__ __forceinline__ void cpa16z(uint32_t dst, const void* src, unsigned sz) {
    asm volatile("cp.async.cg.shared.global [%0], [%1], 16, %2;"
                 ::"r"(dst), "l"(src), "r"(sz));
}
__device__ __forceinline__ void cp_commit() { asm volatile("cp.async.commit_group;"); }
__device__ __forceinline__ void cp_wait1() { asm volatile("cp.async.wait_group 1;"); }
__device__ __forceinline__ void cp_wait0() { asm volatile("cp.async.wait_group 0;"); }

struct BfgLoader {
    const __nv_bfloat16 *a0, *a1, *b0, *b1;
    uint32_t aoff0, aoff1, boff0, boff1;
    size_t bstep;     // elements to advance B per 32-k step
    unsigned bsz;     // 16 normally; 0 for OOB vocab columns
    __device__ __forceinline__ void issue(int it, uint32_t dA, uint32_t dB) const {
        cpa16(dA + aoff0, a0 + it * 32);
        cpa16(dA + aoff1, a1 + it * 32);
        cpa16z(dB + boff0, b0 + (size_t)it * bstep, bsz);
        cpa16z(dB + boff1, b1 + (size_t)it * bstep, bsz);
    }
};

__device__ __forceinline__ void bfg_compute(uint32_t bA, uint32_t bB,
                                            int lane, int wm, int wn,
                                            float acc[2][8][4]) {
    const int l15 = lane & 15, l7 = lane & 7, lhi = lane >> 4;
    const int mA0 = wm * 32 + l15, mA1 = mA0 + 16;
    const uint32_t aR0 = (uint32_t)mA0 * 128, aR1 = (uint32_t)mA1 * 128;
    const int a70 = mA0 & 7, a71 = mA1 & 7;
    const uint32_t bRk = (uint32_t)l15 * 256;
#pragma unroll
    for (int ks = 0; ks < 2; ks++) {
        int c = ks * 2 + lhi;
        unsigned af0[4], af1[4];
        ldsm4(bA + aR0 + (uint32_t)(((c ^ a70) & 7) << 4),
              af0[0], af0[1], af0[2], af0[3]);
        ldsm4(bA + aR1 + (uint32_t)(((c ^ a71) & 7) << 4),
              af1[0], af1[1], af1[2], af1[3]);
#pragma unroll
        for (int p = 0; p < 4; p++) {
            unsigned bf0, bf1, bf2, bf3;
            int g = wn * 8 + p * 2 + lhi;
            ldsm4t(bB + (uint32_t)(ks * 16) * 256 + bRk + (uint32_t)((g ^ l7) << 4),
                   bf0, bf1, bf2, bf3);
            bmma(acc[0][2 * p],     af0, bf0, bf1);
            bmma(acc[0][2 * p + 1], af0, bf2, bf3);
            bmma(acc[1][2 * p],     af1, bf0, bf1);
            bmma(acc[1][2 * p + 1], af1, bf2, bf3);
        }
    }
}

__device__ __forceinline__ void bfg_run(const BfgLoader& ld, int nIter,
                                        uint32_t sA0, uint32_t sB0,
                                        int lane, int wm, int wn,
                                        float acc[2][8][4]) {
    ld.issue(0, sA0, sB0);
    cp_commit();
    for (int it = 0; it < nIter; it++) {
        uint32_t bA = sA0 + (uint32_t)(it & 1) * 16384;
        uint32_t bB = sB0 + (uint32_t)(it & 1) * 8192;
        if (it + 1 < nIter) {
            ld.issue(it + 1, sA0 + (uint32_t)((it + 1) & 1) * 16384,
                     sB0 + (uint32_t)((it + 1) & 1) * 8192);
            cp_commit();
            cp_wait1();
        } else {
            cp_wait0();
        }
        __syncthreads();
        bfg_compute(bA, bB, lane, wm, wn, acc);
        __syncthreads();
    }
}

// common per-thread setup
struct BfgIdx {
    int tid, lane, wid, wm, wn, am, ag, bks, bg;
    uint32_t aoff0, aoff1, boff0, boff1;
    __device__ __forceinline__ BfgIdx() {
        tid = threadIdx.x; lane = tid & 31; wid = tid >> 5;
        wm = wid >> 1; wn = wid & 1;
        am = tid >> 2; ag = tid & 3;
        bks = tid >> 4; bg = tid & 15;
        aoff0 = (uint32_t)am * 128 + (uint32_t)(((ag ^ (am & 7)) & 7) << 4);
        aoff1 = aoff0 + 64 * 128;
        boff0 = (uint32_t)bks * 256 + (uint32_t)((bg ^ (bks & 7)) << 4);
        boff1 = boff0 + 16 * 256;
    }
};

#define BFG_SMEM                                                               \
    __shared__ __align__(16) char sAm[2][16384];                               \
    __shared__ __align__(16) char sBm[2][8192];                                \
    uint32_t sA0 = (uint32_t)__cvta_generic_to_shared(sAm);                    \
    uint32_t sB0 = (uint32_t)__cvta_generic_to_shared(sBm);

// ---- xproj = W_embed[cap] @ Wx + b   (M=4096, K=512, N=4096) ----
__global__ __launch_bounds__(256) void gemm_embed(const int* __restrict__ captions,
                                                  const float* __restrict__ bias) {
    int row0 = blockIdx.y * 128, col0 = blockIdx.x * 128;
    BFG_SMEM;
    BfgIdx ix;
    float acc[2][8][4] = {};
    int r0i = row0 + ix.am, r1i = r0i + 64;
    BfgLoader ld;
    ld.a0 = gb_Wemb + (size_t)captions[(r0i >> 5) * TCAP + (r0i & 31)] * WE_ + ix.ag * 8;
    ld.a1 = gb_Wemb + (size_t)captions[(r1i >> 5) * TCAP + (r1i & 31)] * WE_ + ix.ag * 8;
    ld.b0 = gb_Wx + (size_t)ix.bks * H4_ + col0 + ix.bg * 8;
    ld.b1 = ld.b0 + (size_t)16 * H4_;
    ld.aoff0 = ix.aoff0; ld.aoff1 = ix.aoff1; ld.boff0 = ix.boff0; ld.boff1 = ix.boff1;
    ld.bstep = (size_t)32 * H4_; ld.bsz = 16;
    bfg_run(ld, WE_ / 32, sA0, sB0, ix.lane, ix.wm, ix.wn, acc);
    int eg = ix.lane >> 2, ec = (ix.lane & 3) * 2;
#pragma unroll
    for (int mt = 0; mt < 2; mt++)
#pragma unroll
        for (int nt = 0; nt < 8; nt++) {
            int row = row0 + ix.wm * 32 + mt * 16 + eg;
            int col = col0 + ix.wn * 64 + nt * 8 + ec;
            float b0v = bias[col], b1v = bias[col + 1];
            *(float2*)&g_xproj[(size_t)row * H4_ + col] =
                make_float2(acc[mt][nt][0] + b0v, acc[mt][nt][1] + b1v);
            *(float2*)&g_xproj[(size_t)(row + 8) * H4_ + col] =
                make_float2(acc[mt][nt][2] + b0v, acc[mt][nt][3] + b1v);
        }
}

// ---- P = A^T @ Wattn   (M=2048, K=1024, N=4096) ----
__global__ __launch_bounds__(256) void gemm_P() {
    int row0 = blockIdx.y * 128, col0 = blockIdx.x * 128;
    BFG_SMEM;
    BfgIdx ix;
    float acc[2][8][4] = {};
    BfgLoader ld;
    ld.a0 = gb_At + (size_t)(row0 + ix.am) * H_ + ix.ag * 8;
    ld.a1 = ld.a0 + (size_t)64 * H_;
    ld.b0 = gb_Wattn + (size_t)ix.bks * H4_ + col0 + ix.bg * 8;
    ld.b1 = ld.b0 + (size_t)16 * H4_;
    ld.aoff0 = ix.aoff0; ld.aoff1 = ix.aoff1; ld.boff0 = ix.boff0; ld.boff1 = ix.boff1;
    ld.bstep = (size_t)32 * H4_; ld.bsz = 16;
    bfg_run(ld, H_ / 32, sA0, sB0, ix.lane, ix.wm, ix.wn, acc);
    int eg = ix.lane >> 2, ec = (ix.lane & 3) * 2;
#pragma unroll
    for (int mt = 0; mt < 2; mt++)
#pragma unroll
        for (int nt = 0; nt < 8; nt++) {
            int row = row0 + ix.wm * 32 + mt * 16 + eg;
            int col = col0 + ix.wn * 64 + nt * 8 + ec;
            *(float2*)&g_P[(size_t)row * H4_ + col] =
                make_float2(acc[mt][nt][0], acc[mt][nt][1]);
            *(float2*)&g_P[(size_t)(row + 8) * H4_ + col] =
                make_float2(acc[mt][nt][2], acc[mt][nt][3]);
        }
}

// ---- scores = hn @ W_vocab + b_vocab   (M=4096, K=1024, N=10000) ----
__global__ __launch_bounds__(256) void gemm_vocab(const float* __restrict__ bv) {
    int row0 = blockIdx.y * 128, col0 = blockIdx.x * 128;
    BFG_SMEM;
    BfgIdx ix;
    float acc[2][8][4] = {};
    BfgLoader ld;
    ld.a0 = gb_hn + (size_t)(row0 + ix.am) * H_ + ix.ag * 8;
    ld.a1 = ld.a0 + (size_t)64 * H_;
    int bcol = col0 + ix.bg * 8;
    ld.bsz = (bcol + 8 <= V_) ? 16u : 0u;
    ld.b0 = gb_Wv + (size_t)ix.bks * V_ + ((bcol + 8 <= V_) ? bcol : 0);
    ld.b1 = ld.b0 + (size_t)16 * V_;
    ld.aoff0 = ix.aoff0; ld.aoff1 = ix.aoff1; ld.boff0 = ix.boff0; ld.boff1 = ix.boff1;
    ld.bstep = (size_t)32 * V_;
    bfg_run(ld, H_ / 32, sA0, sB0, ix.lane, ix.wm, ix.wn, acc);
    int eg = ix.lane >> 2, ec = (ix.lane & 3) * 2;
#pragma unroll
    for (int mt = 0; mt < 2; mt++)
#pragma unroll
        for (int nt = 0; nt < 8; nt++) {
            int row = row0 + ix.wm * 32 + mt * 16 + eg;
            int col = col0 + ix.wn * 64 + nt * 8 + ec;
            if (col < V_) {
                float b0v = bv[col], b1v = bv[col + 1];
                *(float2*)&g_scores[(size_t)row * V_ + col] =
                    make_float2(acc[mt][nt][0] + b0v, acc[mt][nt][1] + b1v);
                *(float2*)&g_scores[(size_t)(row + 8) * V_ + col] =
                    make_float2(acc[mt][nt][2] + b0v, acc[mt][nt][3] + b1v);
            }
        }
}

// ---- per-step: zpart[ks] = h @ Wh[k-slice]  (M=128, K=256/slice, N=4096) ----
__global__ __launch_bounds__(256) void gemm_zh() {
    int col0 = blockIdx.x * 128;
    int kslice = blockIdx.y;
    BFG_SMEM;
    BfgIdx ix;
    float acc[2][8][4] = {};
    BfgLoader ld;
    ld.a0 = gb_h + (size_t)ix.am * H_ + kslice * 256 + ix.ag * 8;
    ld.a1 = ld.a0 + (size_t)64 * H_;
    ld.b0 = gb_Wh + (size_t)(kslice * 256 + ix.bks) * H4_ + col0 + ix.bg * 8;
    ld.b1 = ld.b0 + (size_t)16 * H4_;
    ld.aoff0 = ix.aoff0; ld.aoff1 = ix.aoff1; ld.boff0 = ix.boff0; ld.boff1 = ix.boff1;
    ld.bstep = (size_t)32 * H4_; ld.bsz = 16;
    bfg_run(ld, 8, sA0, sB0, ix.lane, ix.wm, ix.wn, acc);
    int eg = ix.lane >> 2, ec = (ix.lane & 3) * 2;
    float* zp = g_zpart + (size_t)kslice * N_ * H4_;
#pragma unroll
    for (int mt = 0; mt < 2; mt++)
#pragma unroll
        for (int nt = 0; nt < 8; nt++) {
            int row = ix.wm * 32 + mt * 16 + eg;
            int col = col0 + ix.wn * 64 + nt * 8 + ec;
            *(float2*)&zp[(size_t)row * H4_ + col] =
                make_float2(acc[mt][nt][0], acc[mt][nt][1]);
            *(float2*)&zp[(size_t)(row + 8) * H4_ + col] =
                make_float2(acc[mt][nt][2], acc[mt][nt][3]);
        }
}

// ---------------- attention weights + zattn ----------------
__device__ __forceinline__ void attn_w(int n, const float* hs, float* ws, float* wl) {
    float local[L_];
#pragma unroll
    for (int l = 0; l < L_; l++) local[l] = 0.0f;
    for (int h = threadIdx.x; h < H_; h += 256) {
        float hv = hs[h];
        const float* Ar = g_A + ((size_t)n * H_ + h) * L_;
#pragma unroll
        for (int l = 0; l < L_; l++) local[l] = fmaf(hv, Ar[l], local[l]);
    }
#pragma unroll
    for (int l = 0; l < L_; l++)
#pragma unroll
        for (int off = 16; off; off >>= 1)
            local[l] += __shfl_down_sync(0xffffffffu, local[l], off);
    int lane = threadIdx.x & 31, warp = threadIdx.x >> 5;
    if (lane == 0)
#pragma unroll
        for (int l = 0; l < L_; l++) ws[warp * L_ + l] = local[l];
    __syncthreads();
    if (threadIdx.x < L_) {
        float s = 0.0f;
        for (int w = 0; w < 8; w++) s += ws[w * L_ + threadIdx.x];
        wl[threadIdx.x] = s * 0.03125f;
    }
    __syncthreads();
    if (threadIdx.x == 0) {
        float m = -1e30f;
        for (int l = 0; l < L_; l++) m = fmaxf(m, wl[l]);
        float se = 0.0f;
        for (int l = 0; l < L_; l++) { wl[l] = expf(wl[l] - m); se += wl[l]; }
        float inv = 1.0f / se;
        for (int l = 0; l < L_; l++) wl[l] *= inv;
    }
    __syncthreads();
    for (int col = threadIdx.x; col < H4_; col += 256) {
        float s = 0.0f;
        const float* Pr = g_P + (size_t)n * L_ * H4_ + col;
#pragma unroll
        for (int l = 0; l < L_; l++) s = fmaf(wl[l], Pr[(size_t)l * H4_], s);
        g_zattn[(size_t)n * H4_ + col] = s;
    }
}

__global__ __launch_bounds__(256) void init_w() {
    int n = blockIdx.x;
    __shared__ float hs[H_];
    __shared__ float ws[8 * L_];
    __shared__ float wl[L_];
    for (int h = threadIdx.x; h < H_; h += 256) hs[h] = g_h[n * H_ + h];
    __syncthreads();
    attn_w(n, hs, ws, wl);
}

__global__ __launch_bounds__(256) void gate_attn(int t) {
    int n = blockIdx.x;
    __shared__ float hs[H_];
    __shared__ float ws[8 * L_];
    __shared__ float wl[L_];
    const float* xr = g_xproj + ((size_t)n * T_ + t) * H4_;
    const float* za = g_zattn + (size_t)n * H4_;
    for (int h = threadIdx.x; h < H_; h += 256) {
        float zi = 0.f, zf = 0.f, zo = 0.f, zg = 0.f;
#pragma unroll
        for (int ks = 0; ks < 4; ks++) {
            const float* zp = g_zpart + ((size_t)ks * N_ + n) * H4_;
            zi += zp[h]; zf += zp[H_ + h]; zo += zp[2 * H_ + h]; zg += zp[3 * H_ + h];
        }
        float ai = zi + xr[h] + za[h];
        float af = zf + xr[H_ + h] + za[H_ + h];
        float ao = zo + xr[2 * H_ + h] + za[2 * H_ + h];
        float ag = zg + xr[3 * H_ + h] + za[3 * H_ + h];
        float c = sigf(af) * g_c[n * H_ + h] + sigf(ai) * tanhf(ag);
        float hv = sigf(ao) * tanhf(c);
        g_c[n * H_ + h] = c;
        gb_h[n * H_ + h] = __float2bfloat16_rn(hv);
        gb_hn[((size_t)n * T_ + t) * H_ + h] = __float2bfloat16_rn(hv);
        hs[h] = hv;
    }
    __syncthreads();
    attn_w(n, hs, ws, wl);
}

// ---------------- NLL reduce ----------------
__global__ __launch_bounds__(256) void loss_k(const int* __restrict__ captions,
                                              float* __restrict__ out) {
    int r = blockIdx.x;
    int tid = threadIdx.x;
    __shared__ float red[256];
    const float* sr = g_scores + (size_t)r * V_;
    float m = -1e30f;
    for (int i = tid; i < V_; i += 256) m = fmaxf(m, sr[i]);
    red[tid] = m; __syncthreads();
    for (int o = 128; o; o >>= 1) { if (tid < o) red[tid] = fmaxf(red[tid], red[tid + o]); __syncthreads(); }
    float mv = red[0]; __syncthreads();
    float s = 0.0f;
    for (int i = tid; i < V_; i += 256) s += expf(sr[i] - mv);
    red[tid] = s; __syncthreads();
    for (int o = 128; o; o >>= 1) { if (tid < o) red[tid] += red[tid + o]; __syncthreads(); }
    if (tid == 0) {
        int n = r >> 5, t = r & 31;
        int tgt = captions[n * TCAP + t + 1];
        if (tgt != 0) {
            float nll = logf(red[0]) + mv - sr[tgt];
            atomicAdd(out, nll * (1.0f / (float)N_));
        }
    }
}

// ---------------- launch ----------------
extern "C" void kernel_launch(void* const* d_in, const int* in_sizes, int n_in,
                              void* d_out, int out_size) {
    const float* features = (const float*)d_in[0];
    const int*   captions = (const int*)d_in[1];
    const float* W_embed  = (const float*)d_in[2];
    const float* W_proj   = (const float*)d_in[3];
    const float* b_proj   = (const float*)d_in[4];
    const float* Wx       = (const float*)d_in[5];
    const float* Wh       = (const float*)d_in[6];
    const float* Wattn    = (const float*)d_in[7];
    const float* b        = (const float*)d_in[8];
    const float* W_vocab  = (const float*)d_in[9];
    const float* b_vocab  = (const float*)d_in[10];
    float* out = (float*)d_out;

    __nv_bfloat16* pWemb;  cudaGetSymbolAddress((void**)&pWemb,  gb_Wemb);
    __nv_bfloat16* pWx;    cudaGetSymbolAddress((void**)&pWx,    gb_Wx);
    __nv_bfloat16* pWh;    cudaGetSymbolAddress((void**)&pWh,    gb_Wh);
    __nv_bfloat16* pWattn; cudaGetSymbolAddress((void**)&pWattn, gb_Wattn);
    __nv_bfloat16* pWv;    cudaGetSymbolAddress((void**)&pWv,    gb_Wv);

    init_out<<<1, 1>>>(out);
    f2b<<<(V_ * WE_ / 8 + 255) / 256, 256>>>(W_embed, pWemb, V_ * WE_);
    f2b<<<(WE_ * H4_ / 8 + 255) / 256, 256>>>(Wx, pWx, WE_ * H4_);
    f2b<<<(H_ * H4_ / 8 + 255) / 256, 256>>>(Wh, pWh, H_ * H4_);
    f2b<<<(H_ * H4_ / 8 + 255) / 256, 256>>>(Wattn, pWattn, H_ * H4_);
    f2b<<<(H_ * V_ / 8 + 255) / 256, 256>>>(W_vocab, pWv, H_ * V_);
    kA<<<N_, 256>>>(features, W_proj, b_proj);
    gemm_embed<<<dim3(H4_ / 128, (N_ * T_) / 128), 256>>>(captions, b);
    gemm_P<<<dim3(H4_ / 128, (N_ * L_) / 128), 256>>>();
    init_w<<<N_, 256>>>();
    for (int t = 0; t < T_; t++) {
        gemm_zh<<<dim3(H4_ / 128, 4), 256>>>();
        gate_attn<<<N_, 256>>>(t);
    }
    gemm_vocab<<<dim3((V_ + 127) / 128, (N_ * T_) / 128), 256>>>(b_vocab);
    loss_k<<<N_ * T_, 256>>>(captions, out);
}

// round 7
// speedup vs baseline: 4.2674x; 1.0878x over previous
#include <cuda_runtime.h>
#include <cuda_bf16.h>
#include <cstdint>
#include <math.h>

#define N_   128
#define T_   32
#define TCAP 33
#define D_   400
#define WE_  512
#define H_   1024
#define H4_  4096
#define V_   10000
#define L_   16
#define NBLK 128
#define NBX  79
#define NLSE (NBX * 2)

// ---------------- device scratch ----------------
__device__ float g_A[N_ * H_ * L_];                       // [n][h][l]
__device__ float g_Pp[(size_t)N_ * L_ * H4_];             // [blk][n][l][32]
__device__ float g_h0[N_ * H_];                           // fp32 h0
__device__ float g_xproj[(size_t)N_ * T_ * H4_];          // x@Wx + b
__device__ float g_ps[NBLK * N_ * L_];                    // attention partials
__device__ float g_w[N_ * L_];                            // softmax weights
__device__ float2 g_lsep[(size_t)N_ * T_ * NLSE];         // vocab LSE partials
__device__ float g_stgt[N_ * T_];                         // target scores
__device__ unsigned g_barcnt, g_bargen;

// bf16 operands
__device__ __nv_bfloat16 gb_Wemb[(size_t)V_ * WE_];
__device__ __nv_bfloat16 gb_Wx[(size_t)WE_ * H4_];
__device__ __nv_bfloat16 gb_Wh[(size_t)H_ * H4_];
__device__ __nv_bfloat16 gb_Wattn[(size_t)H_ * H4_];
__device__ __nv_bfloat16 gb_Wv[(size_t)H_ * V_];
__device__ __nv_bfloat16 gb_At[N_ * L_ * H_];
__device__ __nv_bfloat16 gb_hbuf[2][N_ * H_];
__device__ __nv_bfloat16 gb_hn[N_ * T_ * H_];

__device__ __forceinline__ float sigf(float x) { return 1.0f / (1.0f + expf(-x)); }

__global__ void init_out(float* out) { out[0] = 0.0f; }
__global__ void bar_init() { g_barcnt = 0u; g_bargen = 0u; }

// ---------------- fp32 -> bf16 ----------------
__global__ __launch_bounds__(256) void f2b(const float* __restrict__ s,
                                           __nv_bfloat16* __restrict__ d, int n) {
    int i = (blockIdx.x * 256 + threadIdx.x) * 8;
    if (i >= n) return;
    float4 v0 = *(const float4*)(s + i);
    float4 v1 = *(const float4*)(s + i + 4);
    union { __nv_bfloat162 h2[4]; uint4 u; } o;
    o.h2[0] = __floats2bfloat162_rn(v0.x, v0.y);
    o.h2[1] = __floats2bfloat162_rn(v0.z, v0.w);
    o.h2[2] = __floats2bfloat162_rn(v1.x, v1.y);
    o.h2[3] = __floats2bfloat162_rn(v1.z, v1.w);
    *(uint4*)(d + i) = o.u;
}

// ---------------- A_flat + A^T + h0 ----------------
__global__ __launch_bounds__(256) void kA(const float* __restrict__ feat,
                                          const float* __restrict__ Wp,
                                          const float* __restrict__ bp) {
    int n = blockIdx.x;
    __shared__ float fsh[D_ * L_];
    const float* f = feat + (size_t)n * D_ * L_;
    for (int i = threadIdx.x; i < D_ * L_; i += 256) fsh[i] = f[i];
    __syncthreads();
    for (int h = threadIdx.x; h < H_; h += 256) {
        float acc[L_];
        float bb = bp[h];
#pragma unroll
        for (int l = 0; l < L_; l++) acc[l] = bb;
        for (int d = 0; d < D_; d++) {
            float wv = Wp[d * H_ + h];
            const float* fr = &fsh[d * L_];
#pragma unroll
            for (int l = 0; l < L_; l++) acc[l] = fmaf(fr[l], wv, acc[l]);
        }
        float s = 0.0f;
        float* Ar = g_A + ((size_t)n * H_ + h) * L_;
#pragma unroll
        for (int l = 0; l < L_; l++) {
            Ar[l] = acc[l];
            gb_At[((size_t)n * L_ + l) * H_ + h] = __float2bfloat16_rn(acc[l]);
            s += acc[l];
        }
        float h0 = s * (1.0f / 16.0f);
        g_h0[n * H_ + h] = h0;
        gb_hbuf[0][n * H_ + h] = __float2bfloat16_rn(h0);
    }
}

// ================= BF16 mma GEMM core =================
__device__ __forceinline__ void ldsm4(uint32_t a, unsigned& r0, unsigned& r1,
                                      unsigned& r2, unsigned& r3) {
    asm volatile("ldmatrix.sync.aligned.m8n8.x4.shared.b16 {%0,%1,%2,%3}, [%4];"
                 : "=r"(r0), "=r"(r1), "=r"(r2), "=r"(r3) : "r"(a));
}
__device__ __forceinline__ void ldsm4t(uint32_t a, unsigned& r0, unsigned& r1,
                                       unsigned& r2, unsigned& r3) {
    asm volatile("ldmatrix.sync.aligned.m8n8.x4.trans.shared.b16 {%0,%1,%2,%3}, [%4];"
                 : "=r"(r0), "=r"(r1), "=r"(r2), "=r"(r3) : "r"(a));
}
__device__ __forceinline__ void bmma(float* c, const unsigned* a,
                                     unsigned b0, unsigned b1) {
    asm volatile("mma.sync.aligned.m16n8k16.row.col.f32.bf16.bf16.f32 "
                 "{%0,%1,%2,%3},{%4,%5,%6,%7},{%8,%9},{%0,%1,%2,%3};"
                 : "+f"(c[0]), "+f"(c[1]), "+f"(c[2]), "+f"(c[3])
                 : "r"(a[0]), "r"(a[1]), "r"(a[2]), "r"(a[3]), "r"(b0), "r"(b1));
}
__device__ __forceinline__ void cpa16(uint32_t dst, const void* src) {
    asm volatile("cp.async.cg.shared.global [%0], [%1], 16;" ::"r"(dst), "l"(src));
}
__device__ __forceinline__ void cpa16z(uint32_t dst, const void* src, unsigned sz) {
    asm volatile("cp.async.cg.shared.global [%0], [%1], 16, %2;"
                 ::"r"(dst), "l"(src), "r"(sz));
}
__device__ __forceinline__ void cp_commit() { asm volatile("cp.async.commit_group;"); }
__device__ __forceinline__ void cp_wait1() { asm volatile("cp.async.wait_group 1;"); }
__device__ __forceinline__ void cp_wait0() { asm volatile("cp.async.wait_group 0;"); }

struct BfgLoader {
    const __nv_bfloat16 *a0, *a1, *b0, *b1;
    uint32_t aoff0, aoff1, boff0, boff1;
    size_t bstep;
    unsigned bsz;
    __device__ __forceinline__ void issue(int it, uint32_t dA, uint32_t dB) const {
        cpa16(dA + aoff0, a0 + it * 32);
        cpa16(dA + aoff1, a1 + it * 32);
        cpa16z(dB + boff0, b0 + (size_t)it * bstep, bsz);
        cpa16z(dB + boff1, b1 + (size_t)it * bstep, bsz);
    }
};

__device__ __forceinline__ void bfg_compute(uint32_t bA, uint32_t bB,
                                            int lane, int wm, int wn,
                                            float acc[2][8][4]) {
    const int l15 = lane & 15, l7 = lane & 7, lhi = lane >> 4;
    const int mA0 = wm * 32 + l15, mA1 = mA0 + 16;
    const uint32_t aR0 = (uint32_t)mA0 * 128, aR1 = (uint32_t)mA1 * 128;
    const int a70 = mA0 & 7, a71 = mA1 & 7;
    const uint32_t bRk = (uint32_t)l15 * 256;
#pragma unroll
    for (int ks = 0; ks < 2; ks++) {
        int c = ks * 2 + lhi;
        unsigned af0[4], af1[4];
        ldsm4(bA + aR0 + (uint32_t)(((c ^ a70) & 7) << 4),
              af0[0], af0[1], af0[2], af0[3]);
        ldsm4(bA + aR1 + (uint32_t)(((c ^ a71) & 7) << 4),
              af1[0], af1[1], af1[2], af1[3]);
#pragma unroll
        for (int p = 0; p < 4; p++) {
            unsigned bf0, bf1, bf2, bf3;
            int g = wn * 8 + p * 2 + lhi;
            ldsm4t(bB + (uint32_t)(ks * 16) * 256 + bRk + (uint32_t)((g ^ l7) << 4),
                   bf0, bf1, bf2, bf3);
            bmma(acc[0][2 * p],     af0, bf0, bf1);
            bmma(acc[0][2 * p + 1], af0, bf2, bf3);
            bmma(acc[1][2 * p],     af1, bf0, bf1);
            bmma(acc[1][2 * p + 1], af1, bf2, bf3);
        }
    }
}

__device__ __forceinline__ void bfg_run(const BfgLoader& ld, int nIter,
                                        uint32_t sA0, uint32_t sB0,
                                        int lane, int wm, int wn,
                                        float acc[2][8][4]) {
    ld.issue(0, sA0, sB0);
    cp_commit();
    for (int it = 0; it < nIter; it++) {
        uint32_t bA = sA0 + (uint32_t)(it & 1) * 16384;
        uint32_t bB = sB0 + (uint32_t)(it & 1) * 8192;
        if (it + 1 < nIter) {
            ld.issue(it + 1, sA0 + (uint32_t)((it + 1) & 1) * 16384,
                     sB0 + (uint32_t)((it + 1) & 1) * 8192);
            cp_commit();
            cp_wait1();
        } else {
            cp_wait0();
        }
        __syncthreads();
        bfg_compute(bA, bB, lane, wm, wn, acc);
        __syncthreads();
    }
}

struct BfgIdx {
    int tid, lane, wid, wm, wn, am, ag, bks, bg;
    uint32_t aoff0, aoff1, boff0, boff1;
    __device__ __forceinline__ BfgIdx() {
        tid = threadIdx.x; lane = tid & 31; wid = tid >> 5;
        wm = wid >> 1; wn = wid & 1;
        am = tid >> 2; ag = tid & 3;
        bks = tid >> 4; bg = tid & 15;
        aoff0 = (uint32_t)am * 128 + (uint32_t)(((ag ^ (am & 7)) & 7) << 4);
        aoff1 = aoff0 + 64 * 128;
        boff0 = (uint32_t)bks * 256 + (uint32_t)((bg ^ (bks & 7)) << 4);
        boff1 = boff0 + 16 * 256;
    }
};

#define BFG_SMEM                                                               \
    __shared__ __align__(16) char sAm[2][16384];                               \
    __shared__ __align__(16) char sBm[2][8192];                                \
    uint32_t sA0 = (uint32_t)__cvta_generic_to_shared(sAm);                    \
    uint32_t sB0 = (uint32_t)__cvta_generic_to_shared(sBm);

// ---- xproj = W_embed[cap] @ Wx + b ----
__global__ __launch_bounds__(256) void gemm_embed(const int* __restrict__ captions,
                                                  const float* __restrict__ bias) {
    int row0 = blockIdx.y * 128, col0 = blockIdx.x * 128;
    BFG_SMEM;
    BfgIdx ix;
    float acc[2][8][4] = {};
    int r0i = row0 + ix.am, r1i = r0i + 64;
    BfgLoader ld;
    ld.a0 = gb_Wemb + (size_t)captions[(r0i >> 5) * TCAP + (r0i & 31)] * WE_ + ix.ag * 8;
    ld.a1 = gb_Wemb + (size_t)captions[(r1i >> 5) * TCAP + (r1i & 31)] * WE_ + ix.ag * 8;
    ld.b0 = gb_Wx + (size_t)ix.bks * H4_ + col0 + ix.bg * 8;
    ld.b1 = ld.b0 + (size_t)16 * H4_;
    ld.aoff0 = ix.aoff0; ld.aoff1 = ix.aoff1; ld.boff0 = ix.boff0; ld.boff1 = ix.boff1;
    ld.bstep = (size_t)32 * H4_; ld.bsz = 16;
    bfg_run(ld, WE_ / 32, sA0, sB0, ix.lane, ix.wm, ix.wn, acc);
    int eg = ix.lane >> 2, ec = (ix.lane & 3) * 2;
#pragma unroll
    for (int mt = 0; mt < 2; mt++)
#pragma unroll
        for (int nt = 0; nt < 8; nt++) {
            int row = row0 + ix.wm * 32 + mt * 16 + eg;
            int col = col0 + ix.wn * 64 + nt * 8 + ec;
            float b0v = bias[col], b1v = bias[col + 1];
            *(float2*)&g_xproj[(size_t)row * H4_ + col] =
                make_float2(acc[mt][nt][0] + b0v, acc[mt][nt][1] + b1v);
            *(float2*)&g_xproj[(size_t)(row + 8) * H4_ + col] =
                make_float2(acc[mt][nt][2] + b0v, acc[mt][nt][3] + b1v);
        }
}

// ---- P = A^T @ Wattn, written block-major into g_Pp ----
__global__ __launch_bounds__(256) void gemm_P() {
    int row0 = blockIdx.y * 128, col0 = blockIdx.x * 128;
    BFG_SMEM;
    BfgIdx ix;
    float acc[2][8][4] = {};
    BfgLoader ld;
    ld.a0 = gb_At + (size_t)(row0 + ix.am) * H_ + ix.ag * 8;
    ld.a1 = ld.a0 + (size_t)64 * H_;
    ld.b0 = gb_Wattn + (size_t)ix.bks * H4_ + col0 + ix.bg * 8;
    ld.b1 = ld.b0 + (size_t)16 * H4_;
    ld.aoff0 = ix.aoff0; ld.aoff1 = ix.aoff1; ld.boff0 = ix.boff0; ld.boff1 = ix.boff1;
    ld.bstep = (size_t)32 * H4_; ld.bsz = 16;
    bfg_run(ld, H_ / 32, sA0, sB0, ix.lane, ix.wm, ix.wn, acc);
    int eg = ix.lane >> 2, ec = (ix.lane & 3) * 2;
#pragma unroll
    for (int mt = 0; mt < 2; mt++)
#pragma unroll
        for (int nt = 0; nt < 8; nt++) {
            int row = row0 + ix.wm * 32 + mt * 16 + eg;        // = n*16 + l
            int col = col0 + ix.wn * 64 + nt * 8 + ec;
            int n = row >> 4, l = row & 15;
            int gate = col >> 10, rem = col & 1023;
            int bblk = rem >> 3, c32 = gate * 8 + (rem & 7);
            size_t base = (((size_t)bblk * 128 + n) * 16 + l) * 32 + c32;
            *(float2*)&g_Pp[base] = make_float2(acc[mt][nt][0], acc[mt][nt][1]);
            int row2 = row + 8, n2 = row2 >> 4, l2 = row2 & 15;
            size_t base2 = (((size_t)bblk * 128 + n2) * 16 + l2) * 32 + c32;
            *(float2*)&g_Pp[base2] = make_float2(acc[mt][nt][2], acc[mt][nt][3]);
        }
}

// ---- LSE merge helper ----
__device__ __forceinline__ void lsemerge(float& m, float& s, float om, float os) {
    float M = fmaxf(m, om);
    if (M == -INFINITY) { s = 0.0f; return; }
    float t1 = (m == -INFINITY) ? 0.0f : s * expf(m - M);
    float t2 = (om == -INFINITY) ? 0.0f : os * expf(om - M);
    m = M; s = t1 + t2;
}

// ---- scores = hn @ W_vocab + b : fused LSE partials + target harvest ----
__global__ __launch_bounds__(256) void gemm_vocab(const float* __restrict__ bv,
                                                  const int* __restrict__ captions) {
    int row0 = blockIdx.y * 128, col0 = blockIdx.x * 128;
    BFG_SMEM;
    BfgIdx ix;
    float acc[2][8][4] = {};
    BfgLoader ld;
    ld.a0 = gb_hn + (size_t)(row0 + ix.am) * H_ + ix.ag * 8;
    ld.a1 = ld.a0 + (size_t)64 * H_;
    int bcol = col0 + ix.bg * 8;
    ld.bsz = (bcol + 8 <= V_) ? 16u : 0u;
    ld.b0 = gb_Wv + (size_t)ix.bks * V_ + ((bcol + 8 <= V_) ? bcol : 0);
    ld.b1 = ld.b0 + (size_t)16 * V_;
    ld.aoff0 = ix.aoff0; ld.aoff1 = ix.aoff1; ld.boff0 = ix.boff0; ld.boff1 = ix.boff1;
    ld.bstep = (size_t)32 * V_;
    bfg_run(ld, H_ / 32, sA0, sB0, ix.lane, ix.wm, ix.wn, acc);
    int eg = ix.lane >> 2, ec = (ix.lane & 3) * 2;
    float bvr[8][2];
#pragma unroll
    for (int nt = 0; nt < 8; nt++) {
        int col = col0 + ix.wn * 64 + nt * 8 + ec;
        bvr[nt][0] = (col < V_) ? bv[col] : 0.0f;
        bvr[nt][1] = (col + 1 < V_) ? bv[col + 1] : 0.0f;
    }
#pragma unroll
    for (int mt = 0; mt < 2; mt++)
#pragma unroll
        for (int qn = 0; qn < 2; qn++) {
            int row = row0 + ix.wm * 32 + mt * 16 + eg + 8 * qn;
            int tgt = captions[(row >> 5) * TCAP + (row & 31) + 1];
            float m = -INFINITY;
#pragma unroll
            for (int nt = 0; nt < 8; nt++)
#pragma unroll
                for (int j = 0; j < 2; j++) {
                    int col = col0 + ix.wn * 64 + nt * 8 + ec + j;
                    if (col < V_) {
                        float v = acc[mt][nt][2 * qn + j] + bvr[nt][j];
                        m = fmaxf(m, v);
                        if (col == tgt) g_stgt[row] = v;
                    }
                }
            float s = 0.0f;
#pragma unroll
            for (int nt = 0; nt < 8; nt++)
#pragma unroll
                for (int j = 0; j < 2; j++) {
                    int col = col0 + ix.wn * 64 + nt * 8 + ec + j;
                    if (col < V_)
                        s += expf(acc[mt][nt][2 * qn + j] + bvr[nt][j] - m);
                }
#pragma unroll
            for (int off = 1; off <= 2; off <<= 1) {
                float om = __shfl_xor_sync(0xffffffffu, m, off);
                float os = __shfl_xor_sync(0xffffffffu, s, off);
                lsemerge(m, s, om, os);
            }
            if ((ix.lane & 3) == 0)
                g_lsep[(size_t)row * NLSE + blockIdx.x * 2 + ix.wn] = make_float2(m, s);
        }
}

// ---- loss: merge LSE partials, nll on targets ----
__global__ __launch_bounds__(256) void loss_f(const int* __restrict__ captions,
                                              float* __restrict__ out) {
    int r = blockIdx.x * 32 + (threadIdx.x >> 3);
    int j8 = threadIdx.x & 7;
    float m = -INFINITY, s = 0.0f;
    for (int j = j8; j < NLSE; j += 8) {
        float2 p = g_lsep[(size_t)r * NLSE + j];
        lsemerge(m, s, p.x, p.y);
    }
#pragma unroll
    for (int off = 1; off <= 4; off <<= 1) {
        float om = __shfl_xor_sync(0xffffffffu, m, off);
        float os = __shfl_xor_sync(0xffffffffu, s, off);
        lsemerge(m, s, om, os);
    }
    if (j8 == 0) {
        int n = r >> 5, t = r & 31;
        int tgt = captions[n * TCAP + t + 1];
        if (tgt != 0) {
            float nll = logf(s) + m - g_stgt[r];
            atomicAdd(out, nll * (1.0f / (float)N_));
        }
    }
}

// ================= persistent RNN loop =================
// smem: [0,81920) Wh slice (1024 rows x 80B)
//       [81920,147456) h staging 2 x 32KB
//       [147456,163840) zx float[4096]
//       [163840,172032) w_s float[2048]
//       [172032,172544) reduce scratch
#define SM_WH   0
#define SM_H    81920
#define SM_ZX   147456
#define SM_WS   163840
#define SM_RED  172032
#define SM_TOT  172544

extern __shared__ char sm_raw[];

__device__ __forceinline__ void gbar(unsigned& gen) {
    __threadfence();
    __syncthreads();
    if (threadIdx.x == 0) {
        gen++;
        unsigned a = atomicAdd(&g_barcnt, 1u);
        if (a == NBLK - 1) {
            g_barcnt = 0u;
            __threadfence();
            g_bargen = gen;
        } else {
            while (*(volatile unsigned*)&g_bargen < gen) __nanosleep(64);
        }
    }
    __threadfence();
    __syncthreads();
}

__global__ __launch_bounds__(256, 1) void rnn_loop() {
    const int tid = threadIdx.x, bid = blockIdx.x;
    const int lane = tid & 31, w = tid >> 5;
    const int l15 = lane & 15, lhi = lane >> 4;
    uint32_t smb = (uint32_t)__cvta_generic_to_shared(sm_raw);
    uint32_t whb = smb + SM_WH, hb = smb + SM_H;
    float* sZX = (float*)(sm_raw + SM_ZX);
    float* sWs = (float*)(sm_raw + SM_WS);
    float* sRed = (float*)(sm_raw + SM_RED);

    // ---- load Wh slice (32 cols: 4 gates x 8 h) into smem, stride-80 rows ----
    for (int i = tid; i < 4096; i += 256) {
        int k = i >> 2, g = i & 3;
        cpa16(whb + (uint32_t)k * 80 + g * 16,
              gb_Wh + (size_t)k * H4_ + g * 1024 + bid * 8);
    }
    cp_commit(); cp_wait0();
    __syncthreads();

    // ---- init h/c registers from h0 ----
    float hreg[2][2], creg[2][2];
#pragma unroll
    for (int qn = 0; qn < 2; qn++) {
        int n = 16 * w + (lane >> 2) + 8 * qn;
#pragma unroll
        for (int qh = 0; qh < 2; qh++) {
            float hv = g_h0[n * H_ + bid * 8 + (lane & 3) * 2 + qh];
            hreg[qn][qh] = hv; creg[qn][qh] = hv;
        }
    }

    unsigned gen = 0;

    // ---- score partial helper (inlined twice via lambda-like macro) ----
    auto score_partial = [&]() {
        float sc0[16], sc1[16];
#pragma unroll
        for (int l = 0; l < 16; l++) { sc0[l] = 0.f; sc1[l] = 0.f; }
#pragma unroll
        for (int qn = 0; qn < 2; qn++) {
            float* sc = qn ? sc1 : sc0;
            int n = 16 * w + (lane >> 2) + 8 * qn;
#pragma unroll
            for (int qh = 0; qh < 2; qh++) {
                int hidx = bid * 8 + (lane & 3) * 2 + qh;
                float h = hreg[qn][qh];
                const float4* Ar = (const float4*)&g_A[((size_t)n * H_ + hidx) * L_];
#pragma unroll
                for (int j = 0; j < 4; j++) {
                    float4 a = Ar[j];
                    sc[4 * j + 0] += h * a.x; sc[4 * j + 1] += h * a.y;
                    sc[4 * j + 2] += h * a.z; sc[4 * j + 3] += h * a.w;
                }
            }
        }
#pragma unroll
        for (int off = 1; off <= 2; off <<= 1)
#pragma unroll
            for (int l = 0; l < 16; l++) {
                sc0[l] += __shfl_xor_sync(0xffffffffu, sc0[l], off);
                sc1[l] += __shfl_xor_sync(0xffffffffu, sc1[l], off);
            }
        if ((lane & 3) == 0) {
            int n0 = 16 * w + (lane >> 2);
            float4* d0 = (float4*)&g_ps[((size_t)bid * 128 + n0) * 16];
            d0[0] = make_float4(sc0[0], sc0[1], sc0[2], sc0[3]);
            d0[1] = make_float4(sc0[4], sc0[5], sc0[6], sc0[7]);
            d0[2] = make_float4(sc0[8], sc0[9], sc0[10], sc0[11]);
            d0[3] = make_float4(sc0[12], sc0[13], sc0[14], sc0[15]);
            float4* d1 = (float4*)&g_ps[((size_t)bid * 128 + n0 + 8) * 16];
            d1[0] = make_float4(sc1[0], sc1[1], sc1[2], sc1[3]);
            d1[1] = make_float4(sc1[4], sc1[5], sc1[6], sc1[7]);
            d1[2] = make_float4(sc1[8], sc1[9], sc1[10], sc1[11]);
            d1[3] = make_float4(sc1[12], sc1[13], sc1[14], sc1[15]);
        }
    };

    auto wreduce = [&]() {
        if (tid < 128) {
            const float4* p = (const float4*)&g_ps[((size_t)tid * 128 + bid) * 16];
            float4 v0 = __ldcg(p), v1 = __ldcg(p + 1), v2 = __ldcg(p + 2), v3 = __ldcg(p + 3);
            float v[16] = {v0.x, v0.y, v0.z, v0.w, v1.x, v1.y, v1.z, v1.w,
                           v2.x, v2.y, v2.z, v2.w, v3.x, v3.y, v3.z, v3.w};
#pragma unroll
            for (int off = 16; off >= 1; off >>= 1)
#pragma unroll
                for (int l = 0; l < 16; l++)
                    v[l] += __shfl_xor_sync(0xffffffffu, v[l], off);
            if ((tid & 31) == 0)
#pragma unroll
                for (int l = 0; l < 16; l++) sRed[(tid >> 5) * 16 + l] = v[l];
        }
        __syncthreads();
        if (tid == 0) {
            float sv[16];
            float mx = -INFINITY;
#pragma unroll
            for (int l = 0; l < 16; l++) {
                sv[l] = (sRed[l] + sRed[16 + l] + sRed[32 + l] + sRed[48 + l]) * 0.03125f;
                mx = fmaxf(mx, sv[l]);
            }
            float se = 0.0f;
#pragma unroll
            for (int l = 0; l < 16; l++) { sv[l] = expf(sv[l] - mx); se += sv[l]; }
            float inv = 1.0f / se;
#pragma unroll
            for (int l = 0; l < 16; l++) g_w[bid * 16 + l] = sv[l] * inv;
        }
        __syncthreads();
    };

    // ---- initial attention weights from h0 ----
    score_partial();
    gbar(gen);
    wreduce();
    gbar(gen);

    for (int t = 0; t < T_; t++) {
        const int cur = t & 1, nxt = cur ^ 1;
        const __nv_bfloat16* hsrc = gb_hbuf[cur];

        // prefetch h chunk 0
        {
            uint32_t dst = hb;
#pragma unroll
            for (int i = 0; i < 8; i++) {
                int id = tid + 256 * i;
                int n = id >> 4, g = id & 15;
                uint32_t off = (uint32_t)n * 256 + ((g & 8) << 4) + ((((g & 7) ^ (n & 7))) << 4);
                cpa16(dst + off, hsrc + (size_t)n * H_ + g * 8);
            }
            cp_commit();
        }

        // ---- zx = xproj(t) + w . Pp ----
        for (int i = tid; i < 2048; i += 256) sWs[i] = __ldcg(&g_w[i]);
        __syncthreads();
        for (int v = tid; v < 4096; v += 256) {
            int n = v >> 5, c32 = v & 31;
            int gcol = (c32 >> 3) * 1024 + bid * 8 + (c32 & 7);
            float a = g_xproj[((size_t)(n * T_ + t)) * H4_ + gcol];
            const float* pp = &g_Pp[(((size_t)bid * 128 + n) * 16) * 32 + c32];
            const float* wn_ = &sWs[n * 16];
#pragma unroll
            for (int l = 0; l < 16; l++) a = fmaf(wn_[l], pp[l * 32], a);
            sZX[v] = a;
        }

        // ---- GEMM z = h @ Wh-slice ----
        float acc[4][4] = {};
        for (int kc = 0; kc < 8; kc++) {
            if (kc < 7) {
                uint32_t dst = hb + (uint32_t)((kc + 1) & 1) * 32768;
#pragma unroll
                for (int i = 0; i < 8; i++) {
                    int id = tid + 256 * i;
                    int n = id >> 4, g = id & 15;
                    uint32_t off = (uint32_t)n * 256 + ((g & 8) << 4) + ((((g & 7) ^ (n & 7))) << 4);
                    cpa16(dst + off, hsrc + (size_t)n * H_ + (kc + 1) * 128 + g * 8);
                }
                cp_commit(); cp_wait1();
            } else {
                cp_wait0();
            }
            __syncthreads();
            uint32_t hbase = hb + (uint32_t)(kc & 1) * 32768;
            int n_ld = 16 * w + l15;
#pragma unroll
            for (int k16 = 0; k16 < 8; k16++) {
                int cf = 2 * k16 + lhi;
                unsigned af[4];
                ldsm4(hbase + (uint32_t)n_ld * 256 + ((cf & 8) << 4) +
                          (uint32_t)(((cf & 7) ^ (n_ld & 7)) << 4),
                      af[0], af[1], af[2], af[3]);
                int kg = kc * 8 + k16;
                uint32_t brow = whb + (uint32_t)(kg * 16 + l15) * 80;
                unsigned b0, b1, b2, b3, b4, b5, b6, b7;
                ldsm4t(brow + (uint32_t)(lhi << 4), b0, b1, b2, b3);
                ldsm4t(brow + (uint32_t)((2 + lhi) << 4), b4, b5, b6, b7);
                bmma(acc[0], af, b0, b1);
                bmma(acc[1], af, b2, b3);
                bmma(acc[2], af, b4, b5);
                bmma(acc[3], af, b6, b7);
            }
            __syncthreads();
        }

        // ---- gates ----
#pragma unroll
        for (int qn = 0; qn < 2; qn++) {
            int n = 16 * w + (lane >> 2) + 8 * qn;
#pragma unroll
            for (int qh = 0; qh < 2; qh++) {
                int hh = (lane & 3) * 2 + qh;
                int q = 2 * qn + qh;
                float zi = acc[0][q] + sZX[n * 32 + hh];
                float zf = acc[1][q] + sZX[n * 32 + 8 + hh];
                float zo = acc[2][q] + sZX[n * 32 + 16 + hh];
                float zg = acc[3][q] + sZX[n * 32 + 24 + hh];
                float c = sigf(zf) * creg[qn][qh] + sigf(zi) * tanhf(zg);
                float hv = sigf(zo) * tanhf(c);
                creg[qn][qh] = c;
                hreg[qn][qh] = hv;
                __nv_bfloat16 hb16 = __float2bfloat16_rn(hv);
                gb_hbuf[nxt][n * H_ + bid * 8 + hh] = hb16;
                gb_hn[((size_t)n * T_ + t) * H_ + bid * 8 + hh] = hb16;
            }
        }

        // ---- attention partials for next step ----
        score_partial();
        gbar(gen);
        wreduce();
        gbar(gen);
    }
}

// ---------------- launch ----------------
extern "C" void kernel_launch(void* const* d_in, const int* in_sizes, int n_in,
                              void* d_out, int out_size) {
    const float* features = (const float*)d_in[0];
    const int*   captions = (const int*)d_in[1];
    const float* W_embed  = (const float*)d_in[2];
    const float* W_proj   = (const float*)d_in[3];
    const float* b_proj   = (const float*)d_in[4];
    const float* Wx       = (const float*)d_in[5];
    const float* Wh       = (const float*)d_in[6];
    const float* Wattn    = (const float*)d_in[7];
    const float* b        = (const float*)d_in[8];
    const float* W_vocab  = (const float*)d_in[9];
    const float* b_vocab  = (const float*)d_in[10];
    float* out = (float*)d_out;

    __nv_bfloat16* pWemb;  cudaGetSymbolAddress((void**)&pWemb,  gb_Wemb);
    __nv_bfloat16* pWx;    cudaGetSymbolAddress((void**)&pWx,    gb_Wx);
    __nv_bfloat16* pWh;    cudaGetSymbolAddress((void**)&pWh,    gb_Wh);
    __nv_bfloat16* pWattn; cudaGetSymbolAddress((void**)&pWattn, gb_Wattn);
    __nv_bfloat16* pWv;    cudaGetSymbolAddress((void**)&pWv,    gb_Wv);

    cudaFuncSetAttribute(rnn_loop, cudaFuncAttributeMaxDynamicSharedMemorySize, SM_TOT);

    init_out<<<1, 1>>>(out);
    bar_init<<<1, 1>>>();
    f2b<<<(V_ * WE_ / 8 + 255) / 256, 256>>>(W_embed, pWemb, V_ * WE_);
    f2b<<<(WE_ * H4_ / 8 + 255) / 256, 256>>>(Wx, pWx, WE_ * H4_);
    f2b<<<(H_ * H4_ / 8 + 255) / 256, 256>>>(Wh, pWh, H_ * H4_);
    f2b<<<(H_ * H4_ / 8 + 255) / 256, 256>>>(Wattn, pWattn, H_ * H4_);
    f2b<<<(H_ * V_ / 8 + 255) / 256, 256>>>(W_vocab, pWv, H_ * V_);
    kA<<<N_, 256>>>(features, W_proj, b_proj);
    gemm_embed<<<dim3(H4_ / 128, (N_ * T_) / 128), 256>>>(captions, b);
    gemm_P<<<dim3(H4_ / 128, (N_ * L_) / 128), 256>>>();
    rnn_loop<<<NBLK, 256, SM_TOT>>>();
    gemm_vocab<<<dim3(NBX, (N_ * T_) / 128), 256>>>(b_vocab, captions);
    loss_f<<<(N_ * T_) / 32, 256>>>(captions, out);
}

// round 8
// speedup vs baseline: 4.3087x; 1.0097x over previous
#include <cuda_runtime.h>
#include <cuda_bf16.h>
#include <cstdint>
#include <math.h>

#define N_   128
#define T_   32
#define TCAP 33
#define D_   400
#define WE_  512
#define H_   1024
#define H4_  4096
#define V_   10000
#define L_   16
#define NBLK 128
#define NBX  79
#define NLSE (NBX * 2)

// ---------------- device scratch ----------------
__device__ float g_A[N_ * H_ * L_];                       // [n][h][l]
__device__ float g_Pp[(size_t)N_ * L_ * H4_];             // [blk][n][l][32]
__device__ float g_h0[N_ * H_];                           // fp32 h0
__device__ float g_xproj[(size_t)N_ * T_ * H4_];          // x@Wx + b
__device__ float g_ps[NBLK * N_ * L_];                    // attention partials
__device__ float g_w[N_ * L_];                            // softmax weights
__device__ float2 g_lsep[(size_t)N_ * T_ * NLSE];         // vocab LSE partials
__device__ float g_stgt[N_ * T_];                         // target scores
__device__ unsigned g_barcnt, g_bargen;

// bf16 operands
__device__ __nv_bfloat16 gb_Wemb[(size_t)V_ * WE_];
__device__ __nv_bfloat16 gb_Wx[(size_t)WE_ * H4_];
__device__ __nv_bfloat16 gb_Wh[(size_t)H_ * H4_];
__device__ __nv_bfloat16 gb_Wattn[(size_t)H_ * H4_];
__device__ __nv_bfloat16 gb_Wv[(size_t)H_ * V_];
__device__ __nv_bfloat16 gb_At[N_ * L_ * H_];
__device__ __nv_bfloat16 gb_hbuf[2][N_ * H_];
__device__ __nv_bfloat16 gb_hn[N_ * T_ * H_];

// fast transcendentals (MUFU)
__device__ __forceinline__ float tanhfast(float x) {
    float y; asm("tanh.approx.f32 %0, %1;" : "=f"(y) : "f"(x)); return y;
}
__device__ __forceinline__ float sigfast(float x) {
    return fmaf(0.5f, tanhfast(0.5f * x), 0.5f);
}

__global__ void init_out(float* out) { out[0] = 0.0f; }
__global__ void bar_init() { g_barcnt = 0u; g_bargen = 0u; }

// ---------------- fp32 -> bf16 ----------------
__global__ __launch_bounds__(256) void f2b(const float* __restrict__ s,
                                           __nv_bfloat16* __restrict__ d, int n) {
    int i = (blockIdx.x * 256 + threadIdx.x) * 8;
    if (i >= n) return;
    float4 v0 = *(const float4*)(s + i);
    float4 v1 = *(const float4*)(s + i + 4);
    union { __nv_bfloat162 h2[4]; uint4 u; } o;
    o.h2[0] = __floats2bfloat162_rn(v0.x, v0.y);
    o.h2[1] = __floats2bfloat162_rn(v0.z, v0.w);
    o.h2[2] = __floats2bfloat162_rn(v1.x, v1.y);
    o.h2[3] = __floats2bfloat162_rn(v1.z, v1.w);
    *(uint4*)(d + i) = o.u;
}

// ---------------- A_flat + A^T + h0 ----------------
__global__ __launch_bounds__(256) void kA(const float* __restrict__ feat,
                                          const float* __restrict__ Wp,
                                          const float* __restrict__ bp) {
    int n = blockIdx.x;
    __shared__ float fsh[D_ * L_];
    const float* f = feat + (size_t)n * D_ * L_;
    for (int i = threadIdx.x; i < D_ * L_; i += 256) fsh[i] = f[i];
    __syncthreads();
    for (int h = threadIdx.x; h < H_; h += 256) {
        float acc[L_];
        float bb = bp[h];
#pragma unroll
        for (int l = 0; l < L_; l++) acc[l] = bb;
        for (int d = 0; d < D_; d++) {
            float wv = Wp[d * H_ + h];
            const float* fr = &fsh[d * L_];
#pragma unroll
            for (int l = 0; l < L_; l++) acc[l] = fmaf(fr[l], wv, acc[l]);
        }
        float s = 0.0f;
        float* Ar = g_A + ((size_t)n * H_ + h) * L_;
#pragma unroll
        for (int l = 0; l < L_; l++) {
            Ar[l] = acc[l];
            gb_At[((size_t)n * L_ + l) * H_ + h] = __float2bfloat16_rn(acc[l]);
            s += acc[l];
        }
        float h0 = s * (1.0f / 16.0f);
        g_h0[n * H_ + h] = h0;
        gb_hbuf[0][n * H_ + h] = __float2bfloat16_rn(h0);
    }
}

// ================= BF16 mma GEMM core =================
__device__ __forceinline__ void ldsm4(uint32_t a, unsigned& r0, unsigned& r1,
                                      unsigned& r2, unsigned& r3) {
    asm volatile("ldmatrix.sync.aligned.m8n8.x4.shared.b16 {%0,%1,%2,%3}, [%4];"
                 : "=r"(r0), "=r"(r1), "=r"(r2), "=r"(r3) : "r"(a));
}
__device__ __forceinline__ void ldsm4t(uint32_t a, unsigned& r0, unsigned& r1,
                                       unsigned& r2, unsigned& r3) {
    asm volatile("ldmatrix.sync.aligned.m8n8.x4.trans.shared.b16 {%0,%1,%2,%3}, [%4];"
                 : "=r"(r0), "=r"(r1), "=r"(r2), "=r"(r3) : "r"(a));
}
__device__ __forceinline__ void bmma(float* c, const unsigned* a,
                                     unsigned b0, unsigned b1) {
    asm volatile("mma.sync.aligned.m16n8k16.row.col.f32.bf16.bf16.f32 "
                 "{%0,%1,%2,%3},{%4,%5,%6,%7},{%8,%9},{%0,%1,%2,%3};"
                 : "+f"(c[0]), "+f"(c[1]), "+f"(c[2]), "+f"(c[3])
                 : "r"(a[0]), "r"(a[1]), "r"(a[2]), "r"(a[3]), "r"(b0), "r"(b1));
}
__device__ __forceinline__ void cpa16(uint32_t dst, const void* src) {
    asm volatile("cp.async.cg.shared.global [%0], [%1], 16;" ::"r"(dst), "l"(src));
}
__device__ __forceinline__ void cpa16z(uint32_t dst, const void* src, unsigned sz) {
    asm volatile("cp.async.cg.shared.global [%0], [%1], 16, %2;"
                 ::"r"(dst), "l"(src), "r"(sz));
}
__device__ __forceinline__ void cp_commit() { asm volatile("cp.async.commit_group;"); }
__device__ __forceinline__ void cp_wait1() { asm volatile("cp.async.wait_group 1;"); }
__device__ __forceinline__ void cp_wait0() { asm volatile("cp.async.wait_group 0;"); }

struct BfgLoader {
    const __nv_bfloat16 *a0, *a1, *b0, *b1;
    uint32_t aoff0, aoff1, boff0, boff1;
    size_t bstep;
    unsigned bsz;
    __device__ __forceinline__ void issue(int it, uint32_t dA, uint32_t dB) const {
        cpa16(dA + aoff0, a0 + it * 32);
        cpa16(dA + aoff1, a1 + it * 32);
        cpa16z(dB + boff0, b0 + (size_t)it * bstep, bsz);
        cpa16z(dB + boff1, b1 + (size_t)it * bstep, bsz);
    }
};

__device__ __forceinline__ void bfg_compute(uint32_t bA, uint32_t bB,
                                            int lane, int wm, int wn,
                                            float acc[2][8][4]) {
    const int l15 = lane & 15, l7 = lane & 7, lhi = lane >> 4;
    const int mA0 = wm * 32 + l15, mA1 = mA0 + 16;
    const uint32_t aR0 = (uint32_t)mA0 * 128, aR1 = (uint32_t)mA1 * 128;
    const int a70 = mA0 & 7, a71 = mA1 & 7;
    const uint32_t bRk = (uint32_t)l15 * 256;
#pragma unroll
    for (int ks = 0; ks < 2; ks++) {
        int c = ks * 2 + lhi;
        unsigned af0[4], af1[4];
        ldsm4(bA + aR0 + (uint32_t)(((c ^ a70) & 7) << 4),
              af0[0], af0[1], af0[2], af0[3]);
        ldsm4(bA + aR1 + (uint32_t)(((c ^ a71) & 7) << 4),
              af1[0], af1[1], af1[2], af1[3]);
#pragma unroll
        for (int p = 0; p < 4; p++) {
            unsigned bf0, bf1, bf2, bf3;
            int g = wn * 8 + p * 2 + lhi;
            ldsm4t(bB + (uint32_t)(ks * 16) * 256 + bRk + (uint32_t)((g ^ l7) << 4),
                   bf0, bf1, bf2, bf3);
            bmma(acc[0][2 * p],     af0, bf0, bf1);
            bmma(acc[0][2 * p + 1], af0, bf2, bf3);
            bmma(acc[1][2 * p],     af1, bf0, bf1);
            bmma(acc[1][2 * p + 1], af1, bf2, bf3);
        }
    }
}

__device__ __forceinline__ void bfg_run(const BfgLoader& ld, int nIter,
                                        uint32_t sA0, uint32_t sB0,
                                        int lane, int wm, int wn,
                                        float acc[2][8][4]) {
    ld.issue(0, sA0, sB0);
    cp_commit();
    for (int it = 0; it < nIter; it++) {
        uint32_t bA = sA0 + (uint32_t)(it & 1) * 16384;
        uint32_t bB = sB0 + (uint32_t)(it & 1) * 8192;
        if (it + 1 < nIter) {
            ld.issue(it + 1, sA0 + (uint32_t)((it + 1) & 1) * 16384,
                     sB0 + (uint32_t)((it + 1) & 1) * 8192);
            cp_commit();
            cp_wait1();
        } else {
            cp_wait0();
        }
        __syncthreads();
        bfg_compute(bA, bB, lane, wm, wn, acc);
        __syncthreads();
    }
}

struct BfgIdx {
    int tid, lane, wid, wm, wn, am, ag, bks, bg;
    uint32_t aoff0, aoff1, boff0, boff1;
    __device__ __forceinline__ BfgIdx() {
        tid = threadIdx.x; lane = tid & 31; wid = tid >> 5;
        wm = wid >> 1; wn = wid & 1;
        am = tid >> 2; ag = tid & 3;
        bks = tid >> 4; bg = tid & 15;
        aoff0 = (uint32_t)am * 128 + (uint32_t)(((ag ^ (am & 7)) & 7) << 4);
        aoff1 = aoff0 + 64 * 128;
        boff0 = (uint32_t)bks * 256 + (uint32_t)((bg ^ (bks & 7)) << 4);
        boff1 = boff0 + 16 * 256;
    }
};

#define BFG_SMEM                                                               \
    __shared__ __align__(16) char sAm[2][16384];                               \
    __shared__ __align__(16) char sBm[2][8192];                                \
    uint32_t sA0 = (uint32_t)__cvta_generic_to_shared(sAm);                    \
    uint32_t sB0 = (uint32_t)__cvta_generic_to_shared(sBm);

// ---- xproj = W_embed[cap] @ Wx + b ----
__global__ __launch_bounds__(256) void gemm_embed(const int* __restrict__ captions,
                                                  const float* __restrict__ bias) {
    int row0 = blockIdx.y * 128, col0 = blockIdx.x * 128;
    BFG_SMEM;
    BfgIdx ix;
    float acc[2][8][4] = {};
    int r0i = row0 + ix.am, r1i = r0i + 64;
    BfgLoader ld;
    ld.a0 = gb_Wemb + (size_t)captions[(r0i >> 5) * TCAP + (r0i & 31)] * WE_ + ix.ag * 8;
    ld.a1 = gb_Wemb + (size_t)captions[(r1i >> 5) * TCAP + (r1i & 31)] * WE_ + ix.ag * 8;
    ld.b0 = gb_Wx + (size_t)ix.bks * H4_ + col0 + ix.bg * 8;
    ld.b1 = ld.b0 + (size_t)16 * H4_;
    ld.aoff0 = ix.aoff0; ld.aoff1 = ix.aoff1; ld.boff0 = ix.boff0; ld.boff1 = ix.boff1;
    ld.bstep = (size_t)32 * H4_; ld.bsz = 16;
    bfg_run(ld, WE_ / 32, sA0, sB0, ix.lane, ix.wm, ix.wn, acc);
    int eg = ix.lane >> 2, ec = (ix.lane & 3) * 2;
#pragma unroll
    for (int mt = 0; mt < 2; mt++)
#pragma unroll
        for (int nt = 0; nt < 8; nt++) {
            int row = row0 + ix.wm * 32 + mt * 16 + eg;
            int col = col0 + ix.wn * 64 + nt * 8 + ec;
            float b0v = bias[col], b1v = bias[col + 1];
            *(float2*)&g_xproj[(size_t)row * H4_ + col] =
                make_float2(acc[mt][nt][0] + b0v, acc[mt][nt][1] + b1v);
            *(float2*)&g_xproj[(size_t)(row + 8) * H4_ + col] =
                make_float2(acc[mt][nt][2] + b0v, acc[mt][nt][3] + b1v);
        }
}

// ---- P = A^T @ Wattn, written block-major into g_Pp ----
__global__ __launch_bounds__(256) void gemm_P() {
    int row0 = blockIdx.y * 128, col0 = blockIdx.x * 128;
    BFG_SMEM;
    BfgIdx ix;
    float acc[2][8][4] = {};
    BfgLoader ld;
    ld.a0 = gb_At + (size_t)(row0 + ix.am) * H_ + ix.ag * 8;
    ld.a1 = ld.a0 + (size_t)64 * H_;
    ld.b0 = gb_Wattn + (size_t)ix.bks * H4_ + col0 + ix.bg * 8;
    ld.b1 = ld.b0 + (size_t)16 * H4_;
    ld.aoff0 = ix.aoff0; ld.aoff1 = ix.aoff1; ld.boff0 = ix.boff0; ld.boff1 = ix.boff1;
    ld.bstep = (size_t)32 * H4_; ld.bsz = 16;
    bfg_run(ld, H_ / 32, sA0, sB0, ix.lane, ix.wm, ix.wn, acc);
    int eg = ix.lane >> 2, ec = (ix.lane & 3) * 2;
#pragma unroll
    for (int mt = 0; mt < 2; mt++)
#pragma unroll
        for (int nt = 0; nt < 8; nt++) {
            int row = row0 + ix.wm * 32 + mt * 16 + eg;        // = n*16 + l
            int col = col0 + ix.wn * 64 + nt * 8 + ec;
            int n = row >> 4, l = row & 15;
            int gate = col >> 10, rem = col & 1023;
            int bblk = rem >> 3, c32 = gate * 8 + (rem & 7);
            size_t base = (((size_t)bblk * 128 + n) * 16 + l) * 32 + c32;
            *(float2*)&g_Pp[base] = make_float2(acc[mt][nt][0], acc[mt][nt][1]);
            int row2 = row + 8, n2 = row2 >> 4, l2 = row2 & 15;
            size_t base2 = (((size_t)bblk * 128 + n2) * 16 + l2) * 32 + c32;
            *(float2*)&g_Pp[base2] = make_float2(acc[mt][nt][2], acc[mt][nt][3]);
        }
}

// ---- LSE merge helper ----
__device__ __forceinline__ void lsemerge(float& m, float& s, float om, float os) {
    float M = fmaxf(m, om);
    if (M == -INFINITY) { s = 0.0f; return; }
    float t1 = (m == -INFINITY) ? 0.0f : s * __expf(m - M);
    float t2 = (om == -INFINITY) ? 0.0f : os * __expf(om - M);
    m = M; s = t1 + t2;
}

// ---- scores = hn @ W_vocab + b : fused LSE partials + target harvest ----
__global__ __launch_bounds__(256) void gemm_vocab(const float* __restrict__ bv,
                                                  const int* __restrict__ captions) {
    int row0 = blockIdx.y * 128, col0 = blockIdx.x * 128;
    BFG_SMEM;
    BfgIdx ix;
    float acc[2][8][4] = {};
    BfgLoader ld;
    ld.a0 = gb_hn + (size_t)(row0 + ix.am) * H_ + ix.ag * 8;
    ld.a1 = ld.a0 + (size_t)64 * H_;
    int bcol = col0 + ix.bg * 8;
    ld.bsz = (bcol + 8 <= V_) ? 16u : 0u;
    ld.b0 = gb_Wv + (size_t)ix.bks * V_ + ((bcol + 8 <= V_) ? bcol : 0);
    ld.b1 = ld.b0 + (size_t)16 * V_;
    ld.aoff0 = ix.aoff0; ld.aoff1 = ix.aoff1; ld.boff0 = ix.boff0; ld.boff1 = ix.boff1;
    ld.bstep = (size_t)32 * V_;
    bfg_run(ld, H_ / 32, sA0, sB0, ix.lane, ix.wm, ix.wn, acc);
    int eg = ix.lane >> 2, ec = (ix.lane & 3) * 2;
    float bvr[8][2];
#pragma unroll
    for (int nt = 0; nt < 8; nt++) {
        int col = col0 + ix.wn * 64 + nt * 8 + ec;
        bvr[nt][0] = (col < V_) ? bv[col] : 0.0f;
        bvr[nt][1] = (col + 1 < V_) ? bv[col + 1] : 0.0f;
    }
#pragma unroll
    for (int mt = 0; mt < 2; mt++)
#pragma unroll
        for (int qn = 0; qn < 2; qn++) {
            int row = row0 + ix.wm * 32 + mt * 16 + eg + 8 * qn;
            int tgt = captions[(row >> 5) * TCAP + (row & 31) + 1];
            float vals[16];
            float m = -INFINITY;
#pragma unroll
            for (int nt = 0; nt < 8; nt++)
#pragma unroll
                for (int j = 0; j < 2; j++) {
                    int col = col0 + ix.wn * 64 + nt * 8 + ec + j;
                    float v = acc[mt][nt][2 * qn + j] + bvr[nt][j];
                    vals[nt * 2 + j] = v;
                    if (col < V_) {
                        m = fmaxf(m, v);
                        if (col == tgt) g_stgt[row] = v;
                    }
                }
            float s = 0.0f;
#pragma unroll
            for (int nt = 0; nt < 8; nt++)
#pragma unroll
                for (int j = 0; j < 2; j++) {
                    int col = col0 + ix.wn * 64 + nt * 8 + ec + j;
                    if (col < V_)
                        s += __expf(vals[nt * 2 + j] - m);
                }
#pragma unroll
            for (int off = 1; off <= 2; off <<= 1) {
                float om = __shfl_xor_sync(0xffffffffu, m, off);
                float os = __shfl_xor_sync(0xffffffffu, s, off);
                lsemerge(m, s, om, os);
            }
            if ((ix.lane & 3) == 0)
                g_lsep[(size_t)row * NLSE + blockIdx.x * 2 + ix.wn] = make_float2(m, s);
        }
}

// ---- loss: merge LSE partials, nll on targets ----
__global__ __launch_bounds__(256) void loss_f(const int* __restrict__ captions,
                                              float* __restrict__ out) {
    int r = blockIdx.x * 32 + (threadIdx.x >> 3);
    int j8 = threadIdx.x & 7;
    float m = -INFINITY, s = 0.0f;
    for (int j = j8; j < NLSE; j += 8) {
        float2 p = g_lsep[(size_t)r * NLSE + j];
        lsemerge(m, s, p.x, p.y);
    }
#pragma unroll
    for (int off = 1; off <= 4; off <<= 1) {
        float om = __shfl_xor_sync(0xffffffffu, m, off);
        float os = __shfl_xor_sync(0xffffffffu, s, off);
        lsemerge(m, s, om, os);
    }
    if (j8 == 0) {
        int n = r >> 5, t = r & 31;
        int tgt = captions[n * TCAP + t + 1];
        if (tgt != 0) {
            float nll = logf(s) + m - g_stgt[r];
            atomicAdd(out, nll * (1.0f / (float)N_));
        }
    }
}

// ================= persistent RNN loop =================
#define SM_WH   0
#define SM_H    81920
#define SM_ZX   147456
#define SM_WS   163840
#define SM_RED  172032
#define SM_TOT  172544

extern __shared__ char sm_raw[];

__device__ __forceinline__ void gbar(unsigned& gen) {
    __threadfence();
    __syncthreads();
    if (threadIdx.x == 0) {
        gen++;
        unsigned a = atomicAdd(&g_barcnt, 1u);
        if (a == NBLK - 1) {
            g_barcnt = 0u;
            __threadfence();
            g_bargen = gen;
        } else {
            while (*(volatile unsigned*)&g_bargen < gen) __nanosleep(64);
        }
    }
    __threadfence();
    __syncthreads();
}

__global__ __launch_bounds__(256, 1) void rnn_loop() {
    const int tid = threadIdx.x, bid = blockIdx.x;
    const int lane = tid & 31, w = tid >> 5;
    const int l15 = lane & 15, lhi = lane >> 4;
    uint32_t smb = (uint32_t)__cvta_generic_to_shared(sm_raw);
    uint32_t whb = smb + SM_WH, hb = smb + SM_H;
    float* sZX = (float*)(sm_raw + SM_ZX);
    float* sWs = (float*)(sm_raw + SM_WS);
    float* sRed = (float*)(sm_raw + SM_RED);

    for (int i = tid; i < 4096; i += 256) {
        int k = i >> 2, g = i & 3;
        cpa16(whb + (uint32_t)k * 80 + g * 16,
              gb_Wh + (size_t)k * H4_ + g * 1024 + bid * 8);
    }
    cp_commit(); cp_wait0();
    __syncthreads();

    float hreg[2][2], creg[2][2];
#pragma unroll
    for (int qn = 0; qn < 2; qn++) {
        int n = 16 * w + (lane >> 2) + 8 * qn;
#pragma unroll
        for (int qh = 0; qh < 2; qh++) {
            float hv = g_h0[n * H_ + bid * 8 + (lane & 3) * 2 + qh];
            hreg[qn][qh] = hv; creg[qn][qh] = hv;
        }
    }

    unsigned gen = 0;

    auto score_partial = [&]() {
        float sc0[16], sc1[16];
#pragma unroll
        for (int l = 0; l < 16; l++) { sc0[l] = 0.f; sc1[l] = 0.f; }
#pragma unroll
        for (int qn = 0; qn < 2; qn++) {
            float* sc = qn ? sc1 : sc0;
            int n = 16 * w + (lane >> 2) + 8 * qn;
#pragma unroll
            for (int qh = 0; qh < 2; qh++) {
                int hidx = bid * 8 + (lane & 3) * 2 + qh;
                float h = hreg[qn][qh];
                const float4* Ar = (const float4*)&g_A[((size_t)n * H_ + hidx) * L_];
#pragma unroll
                for (int j = 0; j < 4; j++) {
                    float4 a = Ar[j];
                    sc[4 * j + 0] += h * a.x; sc[4 * j + 1] += h * a.y;
                    sc[4 * j + 2] += h * a.z; sc[4 * j + 3] += h * a.w;
                }
            }
        }
#pragma unroll
        for (int off = 1; off <= 2; off <<= 1)
#pragma unroll
            for (int l = 0; l < 16; l++) {
                sc0[l] += __shfl_xor_sync(0xffffffffu, sc0[l], off);
                sc1[l] += __shfl_xor_sync(0xffffffffu, sc1[l], off);
            }
        if ((lane & 3) == 0) {
            int n0 = 16 * w + (lane >> 2);
            float4* d0 = (float4*)&g_ps[((size_t)bid * 128 + n0) * 16];
            d0[0] = make_float4(sc0[0], sc0[1], sc0[2], sc0[3]);
            d0[1] = make_float4(sc0[4], sc0[5], sc0[6], sc0[7]);
            d0[2] = make_float4(sc0[8], sc0[9], sc0[10], sc0[11]);
            d0[3] = make_float4(sc0[12], sc0[13], sc0[14], sc0[15]);
            float4* d1 = (float4*)&g_ps[((size_t)bid * 128 + n0 + 8) * 16];
            d1[0] = make_float4(sc1[0], sc1[1], sc1[2], sc1[3]);
            d1[1] = make_float4(sc1[4], sc1[5], sc1[6], sc1[7]);
            d1[2] = make_float4(sc1[8], sc1[9], sc1[10], sc1[11]);
            d1[3] = make_float4(sc1[12], sc1[13], sc1[14], sc1[15]);
        }
    };

    auto wreduce = [&]() {
        if (tid < 128) {
            const float4* p = (const float4*)&g_ps[((size_t)tid * 128 + bid) * 16];
            float4 v0 = __ldcg(p), v1 = __ldcg(p + 1), v2 = __ldcg(p + 2), v3 = __ldcg(p + 3);
            float v[16] = {v0.x, v0.y, v0.z, v0.w, v1.x, v1.y, v1.z, v1.w,
                           v2.x, v2.y, v2.z, v2.w, v3.x, v3.y, v3.z, v3.w};
#pragma unroll
            for (int off = 16; off >= 1; off >>= 1)
#pragma unroll
                for (int l = 0; l < 16; l++)
                    v[l] += __shfl_xor_sync(0xffffffffu, v[l], off);
            if ((tid & 31) == 0)
#pragma unroll
                for (int l = 0; l < 16; l++) sRed[(tid >> 5) * 16 + l] = v[l];
        }
        __syncthreads();
        if (tid == 0) {
            float sv[16];
            float mx = -INFINITY;
#pragma unroll
            for (int l = 0; l < 16; l++) {
                sv[l] = (sRed[l] + sRed[16 + l] + sRed[32 + l] + sRed[48 + l]) * 0.03125f;
                mx = fmaxf(mx, sv[l]);
            }
            float se = 0.0f;
#pragma unroll
            for (int l = 0; l < 16; l++) { sv[l] = __expf(sv[l] - mx); se += sv[l]; }
            float inv = 1.0f / se;
#pragma unroll
            for (int l = 0; l < 16; l++) g_w[bid * 16 + l] = sv[l] * inv;
        }
        __syncthreads();
    };

    score_partial();
    gbar(gen);
    wreduce();
    gbar(gen);

    for (int t = 0; t < T_; t++) {
        const int cur = t & 1, nxt = cur ^ 1;
        const __nv_bfloat16* hsrc = gb_hbuf[cur];

        {
            uint32_t dst = hb;
#pragma unroll
            for (int i = 0; i < 8; i++) {
                int id = tid + 256 * i;
                int n = id >> 4, g = id & 15;
                uint32_t off = (uint32_t)n * 256 + ((g & 8) << 4) + ((((g & 7) ^ (n & 7))) << 4);
                cpa16(dst + off, hsrc + (size_t)n * H_ + g * 8);
            }
            cp_commit();
        }

        for (int i = tid; i < 2048; i += 256) sWs[i] = __ldcg(&g_w[i]);
        __syncthreads();
        for (int v = tid; v < 4096; v += 256) {
            int n = v >> 5, c32 = v & 31;
            int gcol = (c32 >> 3) * 1024 + bid * 8 + (c32 & 7);
            float a = g_xproj[((size_t)(n * T_ + t)) * H4_ + gcol];
            const float* pp = &g_Pp[(((size_t)bid * 128 + n) * 16) * 32 + c32];
            const float* wn_ = &sWs[n * 16];
#pragma unroll
            for (int l = 0; l < 16; l++) a = fmaf(wn_[l], pp[l * 32], a);
            sZX[v] = a;
        }

        float acc[4][4] = {};
        for (int kc = 0; kc < 8; kc++) {
            if (kc < 7) {
                uint32_t dst = hb + (uint32_t)((kc + 1) & 1) * 32768;
#pragma unroll
                for (int i = 0; i < 8; i++) {
                    int id = tid + 256 * i;
                    int n = id >> 4, g = id & 15;
                    uint32_t off = (uint32_t)n * 256 + ((g & 8) << 4) + ((((g & 7) ^ (n & 7))) << 4);
                    cpa16(dst + off, hsrc + (size_t)n * H_ + (kc + 1) * 128 + g * 8);
                }
                cp_commit(); cp_wait1();
            } else {
                cp_wait0();
            }
            __syncthreads();
            uint32_t hbase = hb + (uint32_t)(kc & 1) * 32768;
            int n_ld = 16 * w + l15;
#pragma unroll
            for (int k16 = 0; k16 < 8; k16++) {
                int cf = 2 * k16 + lhi;
                unsigned af[4];
                ldsm4(hbase + (uint32_t)n_ld * 256 + ((cf & 8) << 4) +
                          (uint32_t)(((cf & 7) ^ (n_ld & 7)) << 4),
                      af[0], af[1], af[2], af[3]);
                int kg = kc * 8 + k16;
                uint32_t brow = whb + (uint32_t)(kg * 16 + l15) * 80;
                unsigned b0, b1, b2, b3, b4, b5, b6, b7;
                ldsm4t(brow + (uint32_t)(lhi << 4), b0, b1, b2, b3);
                ldsm4t(brow + (uint32_t)((2 + lhi) << 4), b4, b5, b6, b7);
                bmma(acc[0], af, b0, b1);
                bmma(acc[1], af, b2, b3);
                bmma(acc[2], af, b4, b5);
                bmma(acc[3], af, b6, b7);
            }
            __syncthreads();
        }

#pragma unroll
        for (int qn = 0; qn < 2; qn++) {
            int n = 16 * w + (lane >> 2) + 8 * qn;
#pragma unroll
            for (int qh = 0; qh < 2; qh++) {
                int hh = (lane & 3) * 2 + qh;
                int q = 2 * qn + qh;
                float zi = acc[0][q] + sZX[n * 32 + hh];
                float zf = acc[1][q] + sZX[n * 32 + 8 + hh];
                float zo = acc[2][q] + sZX[n * 32 + 16 + hh];
                float zg = acc[3][q] + sZX[n * 32 + 24 + hh];
                float c = sigfast(zf) * creg[qn][qh] + sigfast(zi) * tanhfast(zg);
                float hv = sigfast(zo) * tanhfast(c);
                creg[qn][qh] = c;
                hreg[qn][qh] = hv;
                __nv_bfloat16 hb16 = __float2bfloat16_rn(hv);
                gb_hbuf[nxt][n * H_ + bid * 8 + hh] = hb16;
                gb_hn[((size_t)n * T_ + t) * H_ + bid * 8 + hh] = hb16;
            }
        }

        score_partial();
        gbar(gen);
        wreduce();
        gbar(gen);
    }
}

// ---------------- launch ----------------
extern "C" void kernel_launch(void* const* d_in, const int* in_sizes, int n_in,
                              void* d_out, int out_size) {
    const float* features = (const float*)d_in[0];
    const int*   captions = (const int*)d_in[1];
    const float* W_embed  = (const float*)d_in[2];
    const float* W_proj   = (const float*)d_in[3];
    const float* b_proj   = (const float*)d_in[4];
    const float* Wx       = (const float*)d_in[5];
    const float* Wh       = (const float*)d_in[6];
    const float* Wattn    = (const float*)d_in[7];
    const float* b        = (const float*)d_in[8];
    const float* W_vocab  = (const float*)d_in[9];
    const float* b_vocab  = (const float*)d_in[10];
    float* out = (float*)d_out;

    __nv_bfloat16* pWemb;  cudaGetSymbolAddress((void**)&pWemb,  gb_Wemb);
    __nv_bfloat16* pWx;    cudaGetSymbolAddress((void**)&pWx,    gb_Wx);
    __nv_bfloat16* pWh;    cudaGetSymbolAddress((void**)&pWh,    gb_Wh);
    __nv_bfloat16* pWattn; cudaGetSymbolAddress((void**)&pWattn, gb_Wattn);
    __nv_bfloat16* pWv;    cudaGetSymbolAddress((void**)&pWv,    gb_Wv);

    cudaFuncSetAttribute(rnn_loop, cudaFuncAttributeMaxDynamicSharedMemorySize, SM_TOT);

    init_out<<<1, 1>>>(out);
    bar_init<<<1, 1>>>();
    f2b<<<(V_ * WE_ / 8 + 255) / 256, 256>>>(W_embed, pWemb, V_ * WE_);
    f2b<<<(WE_ * H4_ / 8 + 255) / 256, 256>>>(Wx, pWx, WE_ * H4_);
    f2b<<<(H_ * H4_ / 8 + 255) / 256, 256>>>(Wh, pWh, H_ * H4_);
    f2b<<<(H_ * H4_ / 8 + 255) / 256, 256>>>(Wattn, pWattn, H_ * H4_);
    f2b<<<(H_ * V_ / 8 + 255) / 256, 256>>>(W_vocab, pWv, H_ * V_);
    kA<<<N_, 256>>>(features, W_proj, b_proj);
    gemm_embed<<<dim3(H4_ / 128, (N_ * T_) / 128), 256>>>(captions, b);
    gemm_P<<<dim3(H4_ / 128, (N_ * L_) / 128), 256>>>();
    rnn_loop<<<NBLK, 256, SM_TOT>>>();
    gemm_vocab<<<dim3(NBX, (N_ * T_) / 128), 256>>>(b_vocab, captions);
    loss_f<<<(N_ * T_) / 32, 256>>>(captions, out);
}

// round 10
// speedup vs baseline: 4.3096x; 1.0002x over previous
#include <cuda_runtime.h>
#include <cuda_bf16.h>
#include <cstdint>
#include <math.h>

#define N_   128
#define T_   32
#define TCAP 33
#define D_   400
#define WE_  512
#define H_   1024
#define H4_  4096
#define V_   10000
#define L_   16
#define NBLK 128
#define NBX  79
#define NLSE (NBX * 2)

// ---------------- device scratch ----------------
__device__ float g_A[N_ * H_ * L_];                       // [n][h][l]
__device__ float g_Pp[(size_t)N_ * L_ * H4_];             // [blk][n][l][32]
__device__ float g_h0[N_ * H_];
__device__ float g_xproj[(size_t)N_ * T_ * H4_];
__device__ float g_ps[NBLK * N_ * L_];
__device__ float g_w[N_ * L_];
__device__ float2 g_lsep[(size_t)N_ * T_ * NLSE];
__device__ float g_stgt[N_ * T_];
__device__ unsigned g_barcnt, g_bargen;

// bf16 operands
__device__ __nv_bfloat16 gb_Wemb[(size_t)V_ * WE_];
__device__ __nv_bfloat16 gb_Wx[(size_t)WE_ * H4_];
__device__ __nv_bfloat16 gb_Wh[(size_t)H_ * H4_];
__device__ __nv_bfloat16 gb_Wattn[(size_t)H_ * H4_];
__device__ __nv_bfloat16 gb_Wv[(size_t)H_ * V_];
__device__ __nv_bfloat16 gb_At[N_ * L_ * H_];
__device__ __nv_bfloat16 gb_hbuf[2][N_ * H_];
__device__ __nv_bfloat16 gb_hn[N_ * T_ * H_];

// fast transcendentals (MUFU)
__device__ __forceinline__ float tanhfast(float x) {
    float y; asm("tanh.approx.f32 %0, %1;" : "=f"(y) : "f"(x)); return y;
}
__device__ __forceinline__ float sigfast(float x) {
    return fmaf(0.5f, tanhfast(0.5f * x), 0.5f);
}

__global__ void init_out(float* out) { out[0] = 0.0f; }
__global__ void bar_init() { g_barcnt = 0u; g_bargen = 0u; }

// ---------------- fp32 -> bf16 ----------------
__global__ __launch_bounds__(256) void f2b(const float* __restrict__ s,
                                           __nv_bfloat16* __restrict__ d, int n) {
    int i = (blockIdx.x * 256 + threadIdx.x) * 8;
    if (i >= n) return;
    float4 v0 = *(const float4*)(s + i);
    float4 v1 = *(const float4*)(s + i + 4);
    union { __nv_bfloat162 h2[4]; uint4 u; } o;
    o.h2[0] = __floats2bfloat162_rn(v0.x, v0.y);
    o.h2[1] = __floats2bfloat162_rn(v0.z, v0.w);
    o.h2[2] = __floats2bfloat162_rn(v1.x, v1.y);
    o.h2[3] = __floats2bfloat162_rn(v1.z, v1.w);
    *(uint4*)(d + i) = o.u;
}

// ---------------- A_flat + A^T + h0 ----------------
__global__ __launch_bounds__(256) void kA(const float* __restrict__ feat,
                                          const float* __restrict__ Wp,
                                          const float* __restrict__ bp) {
    int n = blockIdx.x;
    __shared__ float fsh[D_ * L_];
    const float* f = feat + (size_t)n * D_ * L_;
    for (int i = threadIdx.x; i < D_ * L_; i += 256) fsh[i] = f[i];
    __syncthreads();
    for (int h = threadIdx.x; h < H_; h += 256) {
        float acc[L_];
        float bb = bp[h];
#pragma unroll
        for (int l = 0; l < L_; l++) acc[l] = bb;
        for (int d = 0; d < D_; d++) {
            float wv = Wp[d * H_ + h];
            const float* fr = &fsh[d * L_];
#pragma unroll
            for (int l = 0; l < L_; l++) acc[l] = fmaf(fr[l], wv, acc[l]);
        }
        float s = 0.0f;
        float* Ar = g_A + ((size_t)n * H_ + h) * L_;
#pragma unroll
        for (int l = 0; l < L_; l++) {
            Ar[l] = acc[l];
            gb_At[((size_t)n * L_ + l) * H_ + h] = __float2bfloat16_rn(acc[l]);
            s += acc[l];
        }
        float h0 = s * (1.0f / 16.0f);
        g_h0[n * H_ + h] = h0;
        gb_hbuf[0][n * H_ + h] = __float2bfloat16_rn(h0);
    }
}

// ================= BF16 mma GEMM core =================
__device__ __forceinline__ void ldsm4(uint32_t a, unsigned& r0, unsigned& r1,
                                      unsigned& r2, unsigned& r3) {
    asm volatile("ldmatrix.sync.aligned.m8n8.x4.shared.b16 {%0,%1,%2,%3}, [%4];"
                 : "=r"(r0), "=r"(r1), "=r"(r2), "=r"(r3) : "r"(a));
}
__device__ __forceinline__ void ldsm4t(uint32_t a, unsigned& r0, unsigned& r1,
                                       unsigned& r2, unsigned& r3) {
    asm volatile("ldmatrix.sync.aligned.m8n8.x4.trans.shared.b16 {%0,%1,%2,%3}, [%4];"
                 : "=r"(r0), "=r"(r1), "=r"(r2), "=r"(r3) : "r"(a));
}
__device__ __forceinline__ void bmma(float* c, const unsigned* a,
                                     unsigned b0, unsigned b1) {
    asm volatile("mma.sync.aligned.m16n8k16.row.col.f32.bf16.bf16.f32 "
                 "{%0,%1,%2,%3},{%4,%5,%6,%7},{%8,%9},{%0,%1,%2,%3};"
                 : "+f"(c[0]), "+f"(c[1]), "+f"(c[2]), "+f"(c[3])
                 : "r"(a[0]), "r"(a[1]), "r"(a[2]), "r"(a[3]), "r"(b0), "r"(b1));
}
__device__ __forceinline__ void cpa16(uint32_t dst, const void* src) {
    asm volatile("cp.async.cg.shared.global [%0], [%1], 16;" ::"r"(dst), "l"(src));
}
__device__ __forceinline__ void cpa16z(uint32_t dst, const void* src, unsigned sz) {
    asm volatile("cp.async.cg.shared.global [%0], [%1], 16, %2;"
                 ::"r"(dst), "l"(src), "r"(sz));
}
__device__ __forceinline__ void cp_commit() { asm volatile("cp.async.commit_group;"); }
__device__ __forceinline__ void cp_wait1() { asm volatile("cp.async.wait_group 1;"); }
__device__ __forceinline__ void cp_wait0() { asm volatile("cp.async.wait_group 0;"); }

struct BfgLoader {
    const __nv_bfloat16 *a0, *a1, *b0, *b1;
    uint32_t aoff0, aoff1, boff0, boff1;
    size_t bstep;
    unsigned bsz;
    __device__ __forceinline__ void issue(int it, uint32_t dA, uint32_t dB) const {
        cpa16(dA + aoff0, a0 + it * 32);
        cpa16(dA + aoff1, a1 + it * 32);
        cpa16z(dB + boff0, b0 + (size_t)it * bstep, bsz);
        cpa16z(dB + boff1, b1 + (size_t)it * bstep, bsz);
    }
};

__device__ __forceinline__ void bfg_compute(uint32_t bA, uint32_t bB,
                                            int lane, int wm, int wn,
                                            float acc[2][8][4]) {
    const int l15 = lane & 15, l7 = lane & 7, lhi = lane >> 4;
    const int mA0 = wm * 32 + l15, mA1 = mA0 + 16;
    const uint32_t aR0 = (uint32_t)mA0 * 128, aR1 = (uint32_t)mA1 * 128;
    const int a70 = mA0 & 7, a71 = mA1 & 7;
    const uint32_t bRk = (uint32_t)l15 * 256;
#pragma unroll
    for (int ks = 0; ks < 2; ks++) {
        int c = ks * 2 + lhi;
        unsigned af0[4], af1[4];
        ldsm4(bA + aR0 + (uint32_t)(((c ^ a70) & 7) << 4),
              af0[0], af0[1], af0[2], af0[3]);
        ldsm4(bA + aR1 + (uint32_t)(((c ^ a71) & 7) << 4),
              af1[0], af1[1], af1[2], af1[3]);
#pragma unroll
        for (int p = 0; p < 4; p++) {
            unsigned bf0, bf1, bf2, bf3;
            int g = wn * 8 + p * 2 + lhi;
            ldsm4t(bB + (uint32_t)(ks * 16) * 256 + bRk + (uint32_t)((g ^ l7) << 4),
                   bf0, bf1, bf2, bf3);
            bmma(acc[0][2 * p],     af0, bf0, bf1);
            bmma(acc[0][2 * p + 1], af0, bf2, bf3);
            bmma(acc[1][2 * p],     af1, bf0, bf1);
            bmma(acc[1][2 * p + 1], af1, bf2, bf3);
        }
    }
}

__device__ __forceinline__ void bfg_run(const BfgLoader& ld, int nIter,
                                        uint32_t sA0, uint32_t sB0,
                                        int lane, int wm, int wn,
                                        float acc[2][8][4]) {
    ld.issue(0, sA0, sB0);
    cp_commit();
    for (int it = 0; it < nIter; it++) {
        uint32_t bA = sA0 + (uint32_t)(it & 1) * 16384;
        uint32_t bB = sB0 + (uint32_t)(it & 1) * 8192;
        if (it + 1 < nIter) {
            ld.issue(it + 1, sA0 + (uint32_t)((it + 1) & 1) * 16384,
                     sB0 + (uint32_t)((it + 1) & 1) * 8192);
            cp_commit();
            cp_wait1();
        } else {
            cp_wait0();
        }
        __syncthreads();
        bfg_compute(bA, bB, lane, wm, wn, acc);
        __syncthreads();
    }
}

struct BfgIdx {
    int tid, lane, wid, wm, wn, am, ag, bks, bg;
    uint32_t aoff0, aoff1, boff0, boff1;
    __device__ __forceinline__ BfgIdx() {
        tid = threadIdx.x; lane = tid & 31; wid = tid >> 5;
        wm = wid >> 1; wn = wid & 1;
        am = tid >> 2; ag = tid & 3;
        bks = tid >> 4; bg = tid & 15;
        aoff0 = (uint32_t)am * 128 + (uint32_t)(((ag ^ (am & 7)) & 7) << 4);
        aoff1 = aoff0 + 64 * 128;
        boff0 = (uint32_t)bks * 256 + (uint32_t)((bg ^ (bks & 7)) << 4);
        boff1 = boff0 + 16 * 256;
    }
};

#define BFG_SMEM                                                               \
    __shared__ __align__(16) char sAm[2][16384];                               \
    __shared__ __align__(16) char sBm[2][8192];                                \
    uint32_t sA0 = (uint32_t)__cvta_generic_to_shared(sAm);                    \
    uint32_t sB0 = (uint32_t)__cvta_generic_to_shared(sBm);

// ---- xproj = W_embed[cap] @ Wx + b ----
__global__ __launch_bounds__(256) void gemm_embed(const int* __restrict__ captions,
                                                  const float* __restrict__ bias) {
    int row0 = blockIdx.y * 128, col0 = blockIdx.x * 128;
    BFG_SMEM;
    BfgIdx ix;
    float acc[2][8][4] = {};
    int r0i = row0 + ix.am, r1i = r0i + 64;
    BfgLoader ld;
    ld.a0 = gb_Wemb + (size_t)captions[(r0i >> 5) * TCAP + (r0i & 31)] * WE_ + ix.ag * 8;
    ld.a1 = gb_Wemb + (size_t)captions[(r1i >> 5) * TCAP + (r1i & 31)] * WE_ + ix.ag * 8;
    ld.b0 = gb_Wx + (size_t)ix.bks * H4_ + col0 + ix.bg * 8;
    ld.b1 = ld.b0 + (size_t)16 * H4_;
    ld.aoff0 = ix.aoff0; ld.aoff1 = ix.aoff1; ld.boff0 = ix.boff0; ld.boff1 = ix.boff1;
    ld.bstep = (size_t)32 * H4_; ld.bsz = 16;
    bfg_run(ld, WE_ / 32, sA0, sB0, ix.lane, ix.wm, ix.wn, acc);
    int eg = ix.lane >> 2, ec = (ix.lane & 3) * 2;
#pragma unroll
    for (int mt = 0; mt < 2; mt++)
#pragma unroll
        for (int nt = 0; nt < 8; nt++) {
            int row = row0 + ix.wm * 32 + mt * 16 + eg;
            int col = col0 + ix.wn * 64 + nt * 8 + ec;
            float b0v = bias[col], b1v = bias[col + 1];
            *(float2*)&g_xproj[(size_t)row * H4_ + col] =
                make_float2(acc[mt][nt][0] + b0v, acc[mt][nt][1] + b1v);
            *(float2*)&g_xproj[(size_t)(row + 8) * H4_ + col] =
                make_float2(acc[mt][nt][2] + b0v, acc[mt][nt][3] + b1v);
        }
}

// ---- P = A^T @ Wattn, written block-major into g_Pp ----
__global__ __launch_bounds__(256) void gemm_P() {
    int row0 = blockIdx.y * 128, col0 = blockIdx.x * 128;
    BFG_SMEM;
    BfgIdx ix;
    float acc[2][8][4] = {};
    BfgLoader ld;
    ld.a0 = gb_At + (size_t)(row0 + ix.am) * H_ + ix.ag * 8;
    ld.a1 = ld.a0 + (size_t)64 * H_;
    ld.b0 = gb_Wattn + (size_t)ix.bks * H4_ + col0 + ix.bg * 8;
    ld.b1 = ld.b0 + (size_t)16 * H4_;
    ld.aoff0 = ix.aoff0; ld.aoff1 = ix.aoff1; ld.boff0 = ix.boff0; ld.boff1 = ix.boff1;
    ld.bstep = (size_t)32 * H4_; ld.bsz = 16;
    bfg_run(ld, H_ / 32, sA0, sB0, ix.lane, ix.wm, ix.wn, acc);
    int eg = ix.lane >> 2, ec = (ix.lane & 3) * 2;
#pragma unroll
    for (int mt = 0; mt < 2; mt++)
#pragma unroll
        for (int nt = 0; nt < 8; nt++) {
            int row = row0 + ix.wm * 32 + mt * 16 + eg;        // = n*16 + l
            int col = col0 + ix.wn * 64 + nt * 8 + ec;
            int n = row >> 4, l = row & 15;
            int gate = col >> 10, rem = col & 1023;
            int bblk = rem >> 3, c32 = gate * 8 + (rem & 7);
            size_t base = (((size_t)bblk * 128 + n) * 16 + l) * 32 + c32;
            *(float2*)&g_Pp[base] = make_float2(acc[mt][nt][0], acc[mt][nt][1]);
            int row2 = row + 8, n2 = row2 >> 4, l2 = row2 & 15;
            size_t base2 = (((size_t)bblk * 128 + n2) * 16 + l2) * 32 + c32;
            *(float2*)&g_Pp[base2] = make_float2(acc[mt][nt][2], acc[mt][nt][3]);
        }
}

// ---- LSE merge helper ----
__device__ __forceinline__ void lsemerge(float& m, float& s, float om, float os) {
    float M = fmaxf(m, om);
    if (M == -INFINITY) { s = 0.0f; return; }
    float t1 = (m == -INFINITY) ? 0.0f : s * __expf(m - M);
    float t2 = (om == -INFINITY) ? 0.0f : os * __expf(om - M);
    m = M; s = t1 + t2;
}

// ---- scores = hn @ W_vocab + b : fused LSE partials + target harvest ----
__global__ __launch_bounds__(256) void gemm_vocab(const float* __restrict__ bv,
                                                  const int* __restrict__ captions) {
    int row0 = blockIdx.y * 128, col0 = blockIdx.x * 128;
    BFG_SMEM;
    BfgIdx ix;
    float acc[2][8][4] = {};
    BfgLoader ld;
    ld.a0 = gb_hn + (size_t)(row0 + ix.am) * H_ + ix.ag * 8;
    ld.a1 = ld.a0 + (size_t)64 * H_;
    int bcol = col0 + ix.bg * 8;
    ld.bsz = (bcol + 8 <= V_) ? 16u : 0u;
    ld.b0 = gb_Wv + (size_t)ix.bks * V_ + ((bcol + 8 <= V_) ? bcol : 0);
    ld.b1 = ld.b0 + (size_t)16 * V_;
    ld.aoff0 = ix.aoff0; ld.aoff1 = ix.aoff1; ld.boff0 = ix.boff0; ld.boff1 = ix.boff1;
    ld.bstep = (size_t)32 * V_;
    bfg_run(ld, H_ / 32, sA0, sB0, ix.lane, ix.wm, ix.wn, acc);
    int eg = ix.lane >> 2, ec = (ix.lane & 3) * 2;
    float bvr[8][2];
#pragma unroll
    for (int nt = 0; nt < 8; nt++) {
        int col = col0 + ix.wn * 64 + nt * 8 + ec;
        bvr[nt][0] = (col < V_) ? bv[col] : 0.0f;
        bvr[nt][1] = (col + 1 < V_) ? bv[col + 1] : 0.0f;
    }
#pragma unroll
    for (int mt = 0; mt < 2; mt++)
#pragma unroll
        for (int qn = 0; qn < 2; qn++) {
            int row = row0 + ix.wm * 32 + mt * 16 + eg + 8 * qn;
            int tgt = captions[(row >> 5) * TCAP + (row & 31) + 1];
            float vals[16];
            float m = -INFINITY;
#pragma unroll
            for (int nt = 0; nt < 8; nt++)
#pragma unroll
                for (int j = 0; j < 2; j++) {
                    int col = col0 + ix.wn * 64 + nt * 8 + ec + j;
                    float v = acc[mt][nt][2 * qn + j] + bvr[nt][j];
                    vals[nt * 2 + j] = v;
                    if (col < V_) {
                        m = fmaxf(m, v);
                        if (col == tgt) g_stgt[row] = v;
                    }
                }
            float s = 0.0f;
#pragma unroll
            for (int nt = 0; nt < 8; nt++)
#pragma unroll
                for (int j = 0; j < 2; j++) {
                    int col = col0 + ix.wn * 64 + nt * 8 + ec + j;
                    if (col < V_)
                        s += __expf(vals[nt * 2 + j] - m);
                }
#pragma unroll
            for (int off = 1; off <= 2; off <<= 1) {
                float om = __shfl_xor_sync(0xffffffffu, m, off);
                float os = __shfl_xor_sync(0xffffffffu, s, off);
                lsemerge(m, s, om, os);
            }
            if ((ix.lane & 3) == 0)
                g_lsep[(size_t)row * NLSE + blockIdx.x * 2 + ix.wn] = make_float2(m, s);
        }
}

// ---- loss: merge LSE partials, nll on targets ----
__global__ __launch_bounds__(256) void loss_f(const int* __restrict__ captions,
                                              float* __restrict__ out) {
    int r = blockIdx.x * 32 + (threadIdx.x >> 3);
    int j8 = threadIdx.x & 7;
    float m = -INFINITY, s = 0.0f;
    for (int j = j8; j < NLSE; j += 8) {
        float2 p = g_lsep[(size_t)r * NLSE + j];
        lsemerge(m, s, p.x, p.y);
    }
#pragma unroll
    for (int off = 1; off <= 4; off <<= 1) {
        float om = __shfl_xor_sync(0xffffffffu, m, off);
        float os = __shfl_xor_sync(0xffffffffu, s, off);
        lsemerge(m, s, om, os);
    }
    if (j8 == 0) {
        int n = r >> 5, t = r & 31;
        int tgt = captions[n * TCAP + t + 1];
        if (tgt != 0) {
            float nll = logf(s) + m - g_stgt[r];
            atomicAdd(out, nll * (1.0f / (float)N_));
        }
    }
}

// ================= persistent RNN loop (reordered barriers) =================
#define SM_WH   0
#define SM_H    81920
#define SM_ZX   147456
#define SM_WS   163840
#define SM_RED  172032
#define SM_TOT  172544

extern __shared__ char sm_raw[];

__device__ __forceinline__ void gbar(unsigned& gen) {
    __threadfence();
    __syncthreads();
    if (threadIdx.x == 0) {
        gen++;
        unsigned a = atomicAdd(&g_barcnt, 1u);
        if (a == NBLK - 1) {
            g_barcnt = 0u;
            __threadfence();
            g_bargen = gen;
        } else {
            while (*(volatile unsigned*)&g_bargen < gen) __nanosleep(64);
        }
    }
    __threadfence();
    __syncthreads();
}

__global__ __launch_bounds__(256, 1) void rnn_loop() {
    const int tid = threadIdx.x, bid = blockIdx.x;
    const int lane = tid & 31, w = tid >> 5;
    const int l15 = lane & 15, lhi = lane >> 4;
    uint32_t smb = (uint32_t)__cvta_generic_to_shared(sm_raw);
    uint32_t whb = smb + SM_WH, hb = smb + SM_H;
    float* sZX = (float*)(sm_raw + SM_ZX);
    float* sWs = (float*)(sm_raw + SM_WS);
    float* sRed = (float*)(sm_raw + SM_RED);

    for (int i = tid; i < 4096; i += 256) {
        int k = i >> 2, g = i & 3;
        cpa16(whb + (uint32_t)k * 80 + g * 16,
              gb_Wh + (size_t)k * H4_ + g * 1024 + bid * 8);
    }
    cp_commit(); cp_wait0();
    __syncthreads();

    float hreg[2][2], creg[2][2];
#pragma unroll
    for (int qn = 0; qn < 2; qn++) {
        int n = 16 * w + (lane >> 2) + 8 * qn;
#pragma unroll
        for (int qh = 0; qh < 2; qh++) {
            float hv = g_h0[n * H_ + bid * 8 + (lane & 3) * 2 + qh];
            hreg[qn][qh] = hv; creg[qn][qh] = hv;
        }
    }

    unsigned gen = 0;

    auto score_partial = [&]() {
        float sc0[16], sc1[16];
#pragma unroll
        for (int l = 0; l < 16; l++) { sc0[l] = 0.f; sc1[l] = 0.f; }
#pragma unroll
        for (int qn = 0; qn < 2; qn++) {
            float* sc = qn ? sc1 : sc0;
            int n = 16 * w + (lane >> 2) + 8 * qn;
#pragma unroll
            for (int qh = 0; qh < 2; qh++) {
                int hidx = bid * 8 + (lane & 3) * 2 + qh;
                float h = hreg[qn][qh];
                const float4* Ar = (const float4*)&g_A[((size_t)n * H_ + hidx) * L_];
#pragma unroll
                for (int j = 0; j < 4; j++) {
                    float4 a = Ar[j];
                    sc[4 * j + 0] += h * a.x; sc[4 * j + 1] += h * a.y;
                    sc[4 * j + 2] += h * a.z; sc[4 * j + 3] += h * a.w;
                }
            }
        }
#pragma unroll
        for (int off = 1; off <= 2; off <<= 1)
#pragma unroll
            for (int l = 0; l < 16; l++) {
                sc0[l] += __shfl_xor_sync(0xffffffffu, sc0[l], off);
                sc1[l] += __shfl_xor_sync(0xffffffffu, sc1[l], off);
            }
        if ((lane & 3) == 0) {
            int n0 = 16 * w + (lane >> 2);
            float4* d0 = (float4*)&g_ps[((size_t)bid * 128 + n0) * 16];
            d0[0] = make_float4(sc0[0], sc0[1], sc0[2], sc0[3]);
            d0[1] = make_float4(sc0[4], sc0[5], sc0[6], sc0[7]);
            d0[2] = make_float4(sc0[8], sc0[9], sc0[10], sc0[11]);
            d0[3] = make_float4(sc0[12], sc0[13], sc0[14], sc0[15]);
            float4* d1 = (float4*)&g_ps[((size_t)bid * 128 + n0 + 8) * 16];
            d1[0] = make_float4(sc1[0], sc1[1], sc1[2], sc1[3]);
            d1[1] = make_float4(sc1[4], sc1[5], sc1[6], sc1[7]);
            d1[2] = make_float4(sc1[8], sc1[9], sc1[10], sc1[11]);
            d1[3] = make_float4(sc1[12], sc1[13], sc1[14], sc1[15]);
        }
    };

    auto wreduce = [&]() {
        if (tid < 128) {
            const float4* p = (const float4*)&g_ps[((size_t)tid * 128 + bid) * 16];
            float4 v0 = __ldcg(p), v1 = __ldcg(p + 1), v2 = __ldcg(p + 2), v3 = __ldcg(p + 3);
            float v[16] = {v0.x, v0.y, v0.z, v0.w, v1.x, v1.y, v1.z, v1.w,
                           v2.x, v2.y, v2.z, v2.w, v3.x, v3.y, v3.z, v3.w};
#pragma unroll
            for (int off = 16; off >= 1; off >>= 1)
#pragma unroll
                for (int l = 0; l < 16; l++)
                    v[l] += __shfl_xor_sync(0xffffffffu, v[l], off);
            if ((tid & 31) == 0)
#pragma unroll
                for (int l = 0; l < 16; l++) sRed[(tid >> 5) * 16 + l] = v[l];
        }
        __syncthreads();
        if (tid == 0) {
            float sv[16];
            float mx = -INFINITY;
#pragma unroll
            for (int l = 0; l < 16; l++) {
                sv[l] = (sRed[l] + sRed[16 + l] + sRed[32 + l] + sRed[48 + l]) * 0.03125f;
                mx = fmaxf(mx, sv[l]);
            }
            float se = 0.0f;
#pragma unroll
            for (int l = 0; l < 16; l++) { sv[l] = __expf(sv[l] - mx); se += sv[l]; }
            float inv = 1.0f / se;
#pragma unroll
            for (int l = 0; l < 16; l++) g_w[bid * 16 + l] = sv[l] * inv;
        }
        __syncthreads();
    };

    // ---- pre-loop: weights for t=0 ----
    score_partial();
    gbar(gen);            // gbar-A: publishes h0-scores (h0 visible from kA)
    wreduce();            // g_w for t=0 written (published by gbar-B inside loop)

    for (int t = 0; t < T_; t++) {
        const int cur = t & 1, nxt = cur ^ 1;
        const __nv_bfloat16* hsrc = gb_hbuf[cur];

        // ---- prefetch h chunk 0, then GEMM z = h @ Wh-slice ----
        {
            uint32_t dst = hb;
#pragma unroll
            for (int i = 0; i < 8; i++) {
                int id = tid + 256 * i;
                int n = id >> 4, g = id & 15;
                uint32_t off = (uint32_t)n * 256 + ((g & 8) << 4) + ((((g & 7) ^ (n & 7))) << 4);
                cpa16(dst + off, hsrc + (size_t)n * H_ + g * 8);
            }
            cp_commit();
        }
        float acc[4][4] = {};
        for (int kc = 0; kc < 8; kc++) {
            if (kc < 7) {
                uint32_t dst = hb + (uint32_t)((kc + 1) & 1) * 32768;
#pragma unroll
                for (int i = 0; i < 8; i++) {
                    int id = tid + 256 * i;
                    int n = id >> 4, g = id & 15;
                    uint32_t off = (uint32_t)n * 256 + ((g & 8) << 4) + ((((g & 7) ^ (n & 7))) << 4);
                    cpa16(dst + off, hsrc + (size_t)n * H_ + (kc + 1) * 128 + g * 8);
                }
                cp_commit(); cp_wait1();
            } else {
                cp_wait0();
            }
            __syncthreads();
            uint32_t hbase = hb + (uint32_t)(kc & 1) * 32768;
            int n_ld = 16 * w + l15;
#pragma unroll
            for (int k16 = 0; k16 < 8; k16++) {
                int cf = 2 * k16 + lhi;
                unsigned af[4];
                ldsm4(hbase + (uint32_t)n_ld * 256 + ((cf & 8) << 4) +
                          (uint32_t)(((cf & 7) ^ (n_ld & 7)) << 4),
                      af[0], af[1], af[2], af[3]);
                int kg = kc * 8 + k16;
                uint32_t brow = whb + (uint32_t)(kg * 16 + l15) * 80;
                unsigned b0, b1, b2, b3, b4, b5, b6, b7;
                ldsm4t(brow + (uint32_t)(lhi << 4), b0, b1, b2, b3);
                ldsm4t(brow + (uint32_t)((2 + lhi) << 4), b4, b5, b6, b7);
                bmma(acc[0], af, b0, b1);
                bmma(acc[1], af, b2, b3);
                bmma(acc[2], af, b4, b5);
                bmma(acc[3], af, b6, b7);
            }
            __syncthreads();
        }

        // ---- gbar-B: publishes g_w (written by wreduce above / in prev iter) ----
        gbar(gen);

        // ---- zx = xproj(t) + w . Pp ----
        for (int i = tid; i < 2048; i += 256) sWs[i] = __ldcg(&g_w[i]);
        __syncthreads();
        for (int v = tid; v < 4096; v += 256) {
            int n = v >> 5, c32 = v & 31;
            int gcol = (c32 >> 3) * 1024 + bid * 8 + (c32 & 7);
            float a = g_xproj[((size_t)(n * T_ + t)) * H4_ + gcol];
            const float* pp = &g_Pp[(((size_t)bid * 128 + n) * 16) * 32 + c32];
            const float* wn_ = &sWs[n * 16];
#pragma unroll
            for (int l = 0; l < 16; l++) a = fmaf(wn_[l], pp[l * 32], a);
            sZX[v] = a;
        }
        __syncthreads();

        // ---- gates ----
#pragma unroll
        for (int qn = 0; qn < 2; qn++) {
            int n = 16 * w + (lane >> 2) + 8 * qn;
#pragma unroll
            for (int qh = 0; qh < 2; qh++) {
                int hh = (lane & 3) * 2 + qh;
                int q = 2 * qn + qh;
                float zi = acc[0][q] + sZX[n * 32 + hh];
                float zf = acc[1][q] + sZX[n * 32 + 8 + hh];
                float zo = acc[2][q] + sZX[n * 32 + 16 + hh];
                float zg = acc[3][q] + sZX[n * 32 + 24 + hh];
                float c = sigfast(zf) * creg[qn][qh] + sigfast(zi) * tanhfast(zg);
                float hv = sigfast(zo) * tanhfast(c);
                creg[qn][qh] = c;
                hreg[qn][qh] = hv;
                __nv_bfloat16 hb16 = __float2bfloat16_rn(hv);
                gb_hbuf[nxt][n * H_ + bid * 8 + hh] = hb16;
                gb_hn[((size_t)n * T_ + t) * H_ + bid * 8 + hh] = hb16;
            }
        }

        // ---- scores + reduce for NEXT step (skipped on the last) ----
        if (t < T_ - 1) {
            score_partial();
            gbar(gen);        // gbar-A: publishes new h + partials
            wreduce();        // g_w for t+1 (published by next iter's gbar-B)
        }
    }
}

// ---------------- launch ----------------
extern "C" void kernel_launch(void* const* d_in, const int* in_sizes, int n_in,
                              void* d_out, int out_size) {
    const float* features = (const float*)d_in[0];
    const int*   captions = (const int*)d_in[1];
    const float* W_embed  = (const float*)d_in[2];
    const float* W_proj   = (const float*)d_in[3];
    const float* b_proj   = (const float*)d_in[4];
    const float* Wx       = (const float*)d_in[5];
    const float* Wh       = (const float*)d_in[6];
    const float* Wattn    = (const float*)d_in[7];
    const float* b        = (const float*)d_in[8];
    const float* W_vocab  = (const float*)d_in[9];
    const float* b_vocab  = (const float*)d_in[10];
    float* out = (float*)d_out;

    __nv_bfloat16* pWemb;  cudaGetSymbolAddress((void**)&pWemb,  gb_Wemb);
    __nv_bfloat16* pWx;    cudaGetSymbolAddress((void**)&pWx,    gb_Wx);
    __nv_bfloat16* pWh;    cudaGetSymbolAddress((void**)&pWh,    gb_Wh);
    __nv_bfloat16* pWattn; cudaGetSymbolAddress((void**)&pWattn, gb_Wattn);
    __nv_bfloat16* pWv;    cudaGetSymbolAddress((void**)&pWv,    gb_Wv);

    cudaFuncSetAttribute(rnn_loop, cudaFuncAttributeMaxDynamicSharedMemorySize, SM_TOT);

    init_out<<<1, 1>>>(out);
    bar_init<<<1, 1>>>();
    f2b<<<(V_ * WE_ / 8 + 255) / 256, 256>>>(W_embed, pWemb, V_ * WE_);
    f2b<<<(WE_ * H4_ / 8 + 255) / 256, 256>>>(Wx, pWx, WE_ * H4_);
    f2b<<<(H_ * H4_ / 8 + 255) / 256, 256>>>(Wh, pWh, H_ * H4_);
    f2b<<<(H_ * H4_ / 8 + 255) / 256, 256>>>(Wattn, pWattn, H_ * H4_);
    f2b<<<(H_ * V_ / 8 + 255) / 256, 256>>>(W_vocab, pWv, H_ * V_);
    kA<<<N_, 256>>>(features, W_proj, b_proj);
    gemm_embed<<<dim3(H4_ / 128, (N_ * T_) / 128), 256>>>(captions, b);
    gemm_P<<<dim3(H4_ / 128, (N_ * L_) / 128), 256>>>();
    rnn_loop<<<NBLK, 256, SM_TOT>>>();
    gemm_vocab<<<dim3(NBX, (N_ * T_) / 128), 256>>>(b_vocab, captions);
    loss_f<<<(N_ * T_) / 32, 256>>>(captions, out);
}

// round 11
// speedup vs baseline: 4.6502x; 1.0790x over previous
#include <cuda_runtime.h>
#include <cuda_bf16.h>
#include <cstdint>
#include <math.h>

#define N_   128
#define T_   32
#define TCAP 33
#define D_   400
#define WE_  512
#define H_   1024
#define H4_  4096
#define V_   10000
#define L_   16
#define NBLK 128
#define NBX  79
#define NLSE (NBX * 2)

// ---------------- device scratch ----------------
__device__ float g_A[N_ * H_ * L_];                       // [n][h][l]
__device__ float g_h0[N_ * H_];
__device__ float g_xproj[(size_t)N_ * T_ * H4_];
__device__ float g_ps[NBLK * N_ * L_];
__device__ float g_w[N_ * L_];
__device__ float2 g_lsep[(size_t)N_ * T_ * NLSE];
__device__ float g_stgt[N_ * T_];
__device__ __align__(16) unsigned g_flags[NBLK];

// bf16 operands
__device__ __nv_bfloat16 gb_Wemb[(size_t)V_ * WE_];
__device__ __nv_bfloat16 gb_Wx[(size_t)WE_ * H4_];
__device__ __nv_bfloat16 gb_Wh[(size_t)H_ * H4_];
__device__ __nv_bfloat16 gb_Wattn[(size_t)H_ * H4_];
__device__ __nv_bfloat16 gb_Wv[(size_t)H_ * V_];
__device__ __nv_bfloat16 gb_At[N_ * L_ * H_];
__device__ __nv_bfloat16 gb_hbuf[2][N_ * H_];
__device__ __nv_bfloat16 gb_hn[N_ * T_ * H_];
__device__ __nv_bfloat16 gb_Pp[(size_t)N_ * L_ * H4_];    // [blk][n][c32][l] bf16

// fast transcendentals (MUFU)
__device__ __forceinline__ float tanhfast(float x) {
    float y; asm("tanh.approx.f32 %0, %1;" : "=f"(y) : "f"(x)); return y;
}
__device__ __forceinline__ float sigfast(float x) {
    return fmaf(0.5f, tanhfast(0.5f * x), 0.5f);
}

// ---------------- combined init (out + flags) ----------------
__global__ void combo_init(float* out) {
    if (threadIdx.x == 0) out[0] = 0.0f;
    if (threadIdx.x < NBLK) g_flags[threadIdx.x] = 0u;
}

// ---------------- all fp32 -> bf16 conversions in ONE kernel ----------------
// region sizes in 8-elem units:
//   Wemb 640000 | Wx 262144 | Wh 524288 | Wattn 524288 | Wv 1280000
#define R0 640000u
#define R1 (R0 + 262144u)
#define R2 (R1 + 524288u)
#define R3 (R2 + 524288u)
#define R4 (R3 + 1280000u)
__global__ __launch_bounds__(256) void f2b_all(const float* __restrict__ Wemb,
                                               const float* __restrict__ Wx,
                                               const float* __restrict__ Wh,
                                               const float* __restrict__ Wattn,
                                               const float* __restrict__ Wv) {
    unsigned i8 = blockIdx.x * 256 + threadIdx.x;
    const float* s; __nv_bfloat16* d; unsigned base;
    if (i8 < R0)      { s = Wemb;  d = gb_Wemb;  base = 0; }
    else if (i8 < R1) { s = Wx;    d = gb_Wx;    base = R0; }
    else if (i8 < R2) { s = Wh;    d = gb_Wh;    base = R1; }
    else if (i8 < R3) { s = Wattn; d = gb_Wattn; base = R2; }
    else if (i8 < R4) { s = Wv;    d = gb_Wv;    base = R3; }
    else return;
    size_t off = (size_t)(i8 - base) * 8;
    float4 v0 = *(const float4*)(s + off);
    float4 v1 = *(const float4*)(s + off + 4);
    union { __nv_bfloat162 h2[4]; uint4 u; } o;
    o.h2[0] = __floats2bfloat162_rn(v0.x, v0.y);
    o.h2[1] = __floats2bfloat162_rn(v0.z, v0.w);
    o.h2[2] = __floats2bfloat162_rn(v1.x, v1.y);
    o.h2[3] = __floats2bfloat162_rn(v1.z, v1.w);
    *(uint4*)(d + off) = o.u;
}

// ---------------- A_flat + A^T + h0 ----------------
__global__ __launch_bounds__(256) void kA(const float* __restrict__ feat,
                                          const float* __restrict__ Wp,
                                          const float* __restrict__ bp) {
    int n = blockIdx.x;
    __shared__ float fsh[D_ * L_];
    const float* f = feat + (size_t)n * D_ * L_;
    for (int i = threadIdx.x; i < D_ * L_; i += 256) fsh[i] = f[i];
    __syncthreads();
    for (int h = threadIdx.x; h < H_; h += 256) {
        float acc[L_];
        float bb = bp[h];
#pragma unroll
        for (int l = 0; l < L_; l++) acc[l] = bb;
        for (int d = 0; d < D_; d++) {
            float wv = Wp[d * H_ + h];
            const float* fr = &fsh[d * L_];
#pragma unroll
            for (int l = 0; l < L_; l++) acc[l] = fmaf(fr[l], wv, acc[l]);
        }
        float s = 0.0f;
        float* Ar = g_A + ((size_t)n * H_ + h) * L_;
#pragma unroll
        for (int l = 0; l < L_; l++) {
            Ar[l] = acc[l];
            gb_At[((size_t)n * L_ + l) * H_ + h] = __float2bfloat16_rn(acc[l]);
            s += acc[l];
        }
        float h0 = s * (1.0f / 16.0f);
        g_h0[n * H_ + h] = h0;
        gb_hbuf[0][n * H_ + h] = __float2bfloat16_rn(h0);
    }
}

// ================= BF16 mma GEMM core =================
__device__ __forceinline__ void ldsm4(uint32_t a, unsigned& r0, unsigned& r1,
                                      unsigned& r2, unsigned& r3) {
    asm volatile("ldmatrix.sync.aligned.m8n8.x4.shared.b16 {%0,%1,%2,%3}, [%4];"
                 : "=r"(r0), "=r"(r1), "=r"(r2), "=r"(r3) : "r"(a));
}
__device__ __forceinline__ void ldsm4t(uint32_t a, unsigned& r0, unsigned& r1,
                                       unsigned& r2, unsigned& r3) {
    asm volatile("ldmatrix.sync.aligned.m8n8.x4.trans.shared.b16 {%0,%1,%2,%3}, [%4];"
                 : "=r"(r0), "=r"(r1), "=r"(r2), "=r"(r3) : "r"(a));
}
__device__ __forceinline__ void bmma(float* c, const unsigned* a,
                                     unsigned b0, unsigned b1) {
    asm volatile("mma.sync.aligned.m16n8k16.row.col.f32.bf16.bf16.f32 "
                 "{%0,%1,%2,%3},{%4,%5,%6,%7},{%8,%9},{%0,%1,%2,%3};"
                 : "+f"(c[0]), "+f"(c[1]), "+f"(c[2]), "+f"(c[3])
                 : "r"(a[0]), "r"(a[1]), "r"(a[2]), "r"(a[3]), "r"(b0), "r"(b1));
}
__device__ __forceinline__ void cpa16(uint32_t dst, const void* src) {
    asm volatile("cp.async.cg.shared.global [%0], [%1], 16;" ::"r"(dst), "l"(src));
}
__device__ __forceinline__ void cpa16z(uint32_t dst, const void* src, unsigned sz) {
    asm volatile("cp.async.cg.shared.global [%0], [%1], 16, %2;"
                 ::"r"(dst), "l"(src), "r"(sz));
}
__device__ __forceinline__ void cp_commit() { asm volatile("cp.async.commit_group;"); }
__device__ __forceinline__ void cp_wait1() { asm volatile("cp.async.wait_group 1;"); }
__device__ __forceinline__ void cp_wait0() { asm volatile("cp.async.wait_group 0;"); }

struct BfgLoader {
    const __nv_bfloat16 *a0, *a1, *b0, *b1;
    uint32_t aoff0, aoff1, boff0, boff1;
    size_t bstep;
    unsigned bsz;
    __device__ __forceinline__ void issue(int it, uint32_t dA, uint32_t dB) const {
        cpa16(dA + aoff0, a0 + it * 32);
        cpa16(dA + aoff1, a1 + it * 32);
        cpa16z(dB + boff0, b0 + (size_t)it * bstep, bsz);
        cpa16z(dB + boff1, b1 + (size_t)it * bstep, bsz);
    }
};

__device__ __forceinline__ void bfg_compute(uint32_t bA, uint32_t bB,
                                            int lane, int wm, int wn,
                                            float acc[2][8][4]) {
    const int l15 = lane & 15, l7 = lane & 7, lhi = lane >> 4;
    const int mA0 = wm * 32 + l15, mA1 = mA0 + 16;
    const uint32_t aR0 = (uint32_t)mA0 * 128, aR1 = (uint32_t)mA1 * 128;
    const int a70 = mA0 & 7, a71 = mA1 & 7;
    const uint32_t bRk = (uint32_t)l15 * 256;
#pragma unroll
    for (int ks = 0; ks < 2; ks++) {
        int c = ks * 2 + lhi;
        unsigned af0[4], af1[4];
        ldsm4(bA + aR0 + (uint32_t)(((c ^ a70) & 7) << 4),
              af0[0], af0[1], af0[2], af0[3]);
        ldsm4(bA + aR1 + (uint32_t)(((c ^ a71) & 7) << 4),
              af1[0], af1[1], af1[2], af1[3]);
#pragma unroll
        for (int p = 0; p < 4; p++) {
            unsigned bf0, bf1, bf2, bf3;
            int g = wn * 8 + p * 2 + lhi;
            ldsm4t(bB + (uint32_t)(ks * 16) * 256 + bRk + (uint32_t)((g ^ l7) << 4),
                   bf0, bf1, bf2, bf3);
            bmma(acc[0][2 * p],     af0, bf0, bf1);
            bmma(acc[0][2 * p + 1], af0, bf2, bf3);
            bmma(acc[1][2 * p],     af1, bf0, bf1);
            bmma(acc[1][2 * p + 1], af1, bf2, bf3);
        }
    }
}

__device__ __forceinline__ void bfg_run(const BfgLoader& ld, int nIter,
                                        uint32_t sA0, uint32_t sB0,
                                        int lane, int wm, int wn,
                                        float acc[2][8][4]) {
    ld.issue(0, sA0, sB0);
    cp_commit();
    for (int it = 0; it < nIter; it++) {
        uint32_t bA = sA0 + (uint32_t)(it & 1) * 16384;
        uint32_t bB = sB0 + (uint32_t)(it & 1) * 8192;
        if (it + 1 < nIter) {
            ld.issue(it + 1, sA0 + (uint32_t)((it + 1) & 1) * 16384,
                     sB0 + (uint32_t)((it + 1) & 1) * 8192);
            cp_commit();
            cp_wait1();
        } else {
            cp_wait0();
        }
        __syncthreads();
        bfg_compute(bA, bB, lane, wm, wn, acc);
        __syncthreads();
    }
}

struct BfgIdx {
    int tid, lane, wid, wm, wn, am, ag, bks, bg;
    uint32_t aoff0, aoff1, boff0, boff1;
    __device__ __forceinline__ BfgIdx() {
        tid = threadIdx.x; lane = tid & 31; wid = tid >> 5;
        wm = wid >> 1; wn = wid & 1;
        am = tid >> 2; ag = tid & 3;
        bks = tid >> 4; bg = tid & 15;
        aoff0 = (uint32_t)am * 128 + (uint32_t)(((ag ^ (am & 7)) & 7) << 4);
        aoff1 = aoff0 + 64 * 128;
        boff0 = (uint32_t)bks * 256 + (uint32_t)((bg ^ (bks & 7)) << 4);
        boff1 = boff0 + 16 * 256;
    }
};

#define BFG_SMEM                                                               \
    __shared__ __align__(16) char sAm[2][16384];                               \
    __shared__ __align__(16) char sBm[2][8192];                                \
    uint32_t sA0 = (uint32_t)__cvta_generic_to_shared(sAm);                    \
    uint32_t sB0 = (uint32_t)__cvta_generic_to_shared(sBm);

// ---- xproj = W_embed[cap] @ Wx + b ----
__global__ __launch_bounds__(256) void gemm_embed(const int* __restrict__ captions,
                                                  const float* __restrict__ bias) {
    int row0 = blockIdx.y * 128, col0 = blockIdx.x * 128;
    BFG_SMEM;
    BfgIdx ix;
    float acc[2][8][4] = {};
    int r0i = row0 + ix.am, r1i = r0i + 64;
    BfgLoader ld;
    ld.a0 = gb_Wemb + (size_t)captions[(r0i >> 5) * TCAP + (r0i & 31)] * WE_ + ix.ag * 8;
    ld.a1 = gb_Wemb + (size_t)captions[(r1i >> 5) * TCAP + (r1i & 31)] * WE_ + ix.ag * 8;
    ld.b0 = gb_Wx + (size_t)ix.bks * H4_ + col0 + ix.bg * 8;
    ld.b1 = ld.b0 + (size_t)16 * H4_;
    ld.aoff0 = ix.aoff0; ld.aoff1 = ix.aoff1; ld.boff0 = ix.boff0; ld.boff1 = ix.boff1;
    ld.bstep = (size_t)32 * H4_; ld.bsz = 16;
    bfg_run(ld, WE_ / 32, sA0, sB0, ix.lane, ix.wm, ix.wn, acc);
    int eg = ix.lane >> 2, ec = (ix.lane & 3) * 2;
#pragma unroll
    for (int mt = 0; mt < 2; mt++)
#pragma unroll
        for (int nt = 0; nt < 8; nt++) {
            int row = row0 + ix.wm * 32 + mt * 16 + eg;
            int col = col0 + ix.wn * 64 + nt * 8 + ec;
            float b0v = bias[col], b1v = bias[col + 1];
            *(float2*)&g_xproj[(size_t)row * H4_ + col] =
                make_float2(acc[mt][nt][0] + b0v, acc[mt][nt][1] + b1v);
            *(float2*)&g_xproj[(size_t)(row + 8) * H4_ + col] =
                make_float2(acc[mt][nt][2] + b0v, acc[mt][nt][3] + b1v);
        }
}

// ---- P = A^T @ Wattn, written bf16 block-major [blk][n][c32][l] ----
__global__ __launch_bounds__(256) void gemm_P() {
    int row0 = blockIdx.y * 128, col0 = blockIdx.x * 128;
    BFG_SMEM;
    BfgIdx ix;
    float acc[2][8][4] = {};
    BfgLoader ld;
    ld.a0 = gb_At + (size_t)(row0 + ix.am) * H_ + ix.ag * 8;
    ld.a1 = ld.a0 + (size_t)64 * H_;
    ld.b0 = gb_Wattn + (size_t)ix.bks * H4_ + col0 + ix.bg * 8;
    ld.b1 = ld.b0 + (size_t)16 * H4_;
    ld.aoff0 = ix.aoff0; ld.aoff1 = ix.aoff1; ld.boff0 = ix.boff0; ld.boff1 = ix.boff1;
    ld.bstep = (size_t)32 * H4_; ld.bsz = 16;
    bfg_run(ld, H_ / 32, sA0, sB0, ix.lane, ix.wm, ix.wn, acc);
    int eg = ix.lane >> 2, ec = (ix.lane & 3) * 2;
#pragma unroll
    for (int mt = 0; mt < 2; mt++)
#pragma unroll
        for (int nt = 0; nt < 8; nt++) {
            int row = row0 + ix.wm * 32 + mt * 16 + eg;        // = n*16 + l, l in 0..7
            int col = col0 + ix.wn * 64 + nt * 8 + ec;
            int n = row >> 4, l = row & 15;
            int gate = col >> 10, rem = col & 1023;
            int bblk = rem >> 3, c32 = gate * 8 + (rem & 7);
            size_t base = (((size_t)bblk * 128 + n) * 32 + c32) * 16 + l;
            gb_Pp[base]          = __float2bfloat16_rn(acc[mt][nt][0]);
            gb_Pp[base + 16]     = __float2bfloat16_rn(acc[mt][nt][1]);  // c32+1
            gb_Pp[base + 8]      = __float2bfloat16_rn(acc[mt][nt][2]);  // l+8
            gb_Pp[base + 16 + 8] = __float2bfloat16_rn(acc[mt][nt][3]);
        }
}

// ---- LSE merge helper ----
__device__ __forceinline__ void lsemerge(float& m, float& s, float om, float os) {
    float M = fmaxf(m, om);
    if (M == -INFINITY) { s = 0.0f; return; }
    float t1 = (m == -INFINITY) ? 0.0f : s * __expf(m - M);
    float t2 = (om == -INFINITY) ? 0.0f : os * __expf(om - M);
    m = M; s = t1 + t2;
}

// ---- scores = hn @ W_vocab + b : fused LSE partials + target harvest ----
__global__ __launch_bounds__(256) void gemm_vocab(const float* __restrict__ bv,
                                                  const int* __restrict__ captions) {
    int row0 = blockIdx.y * 128, col0 = blockIdx.x * 128;
    BFG_SMEM;
    BfgIdx ix;
    float acc[2][8][4] = {};
    BfgLoader ld;
    ld.a0 = gb_hn + (size_t)(row0 + ix.am) * H_ + ix.ag * 8;
    ld.a1 = ld.a0 + (size_t)64 * H_;
    int bcol = col0 + ix.bg * 8;
    ld.bsz = (bcol + 8 <= V_) ? 16u : 0u;
    ld.b0 = gb_Wv + (size_t)ix.bks * V_ + ((bcol + 8 <= V_) ? bcol : 0);
    ld.b1 = ld.b0 + (size_t)16 * V_;
    ld.aoff0 = ix.aoff0; ld.aoff1 = ix.aoff1; ld.boff0 = ix.boff0; ld.boff1 = ix.boff1;
    ld.bstep = (size_t)32 * V_;
    bfg_run(ld, H_ / 32, sA0, sB0, ix.lane, ix.wm, ix.wn, acc);
    int eg = ix.lane >> 2, ec = (ix.lane & 3) * 2;
    float bvr[8][2];
#pragma unroll
    for (int nt = 0; nt < 8; nt++) {
        int col = col0 + ix.wn * 64 + nt * 8 + ec;
        bvr[nt][0] = (col < V_) ? bv[col] : 0.0f;
        bvr[nt][1] = (col + 1 < V_) ? bv[col + 1] : 0.0f;
    }
#pragma unroll
    for (int mt = 0; mt < 2; mt++)
#pragma unroll
        for (int qn = 0; qn < 2; qn++) {
            int row = row0 + ix.wm * 32 + mt * 16 + eg + 8 * qn;
            int tgt = captions[(row >> 5) * TCAP + (row & 31) + 1];
            float vals[16];
            float m = -INFINITY;
#pragma unroll
            for (int nt = 0; nt < 8; nt++)
#pragma unroll
                for (int j = 0; j < 2; j++) {
                    int col = col0 + ix.wn * 64 + nt * 8 + ec + j;
                    float v = acc[mt][nt][2 * qn + j] + bvr[nt][j];
                    vals[nt * 2 + j] = v;
                    if (col < V_) {
                        m = fmaxf(m, v);
                        if (col == tgt) g_stgt[row] = v;
                    }
                }
            float s = 0.0f;
#pragma unroll
            for (int nt = 0; nt < 8; nt++)
#pragma unroll
                for (int j = 0; j < 2; j++) {
                    int col = col0 + ix.wn * 64 + nt * 8 + ec + j;
                    if (col < V_)
                        s += __expf(vals[nt * 2 + j] - m);
                }
#pragma unroll
            for (int off = 1; off <= 2; off <<= 1) {
                float om = __shfl_xor_sync(0xffffffffu, m, off);
                float os = __shfl_xor_sync(0xffffffffu, s, off);
                lsemerge(m, s, om, os);
            }
            if ((ix.lane & 3) == 0)
                g_lsep[(size_t)row * NLSE + blockIdx.x * 2 + ix.wn] = make_float2(m, s);
        }
}

// ---- loss: merge LSE partials, nll on targets ----
__global__ __launch_bounds__(256) void loss_f(const int* __restrict__ captions,
                                              float* __restrict__ out) {
    int r = blockIdx.x * 32 + (threadIdx.x >> 3);
    int j8 = threadIdx.x & 7;
    float m = -INFINITY, s = 0.0f;
    for (int j = j8; j < NLSE; j += 8) {
        float2 p = g_lsep[(size_t)r * NLSE + j];
        lsemerge(m, s, p.x, p.y);
    }
#pragma unroll
    for (int off = 1; off <= 4; off <<= 1) {
        float om = __shfl_xor_sync(0xffffffffu, m, off);
        float os = __shfl_xor_sync(0xffffffffu, s, off);
        lsemerge(m, s, om, os);
    }
    if (j8 == 0) {
        int n = r >> 5, t = r & 31;
        int tgt = captions[n * TCAP + t + 1];
        if (tgt != 0) {
            float nll = logf(s) + m - g_stgt[r];
            atomicAdd(out, nll * (1.0f / (float)N_));
        }
    }
}

// ================= persistent RNN loop =================
#define SM_WH   0
#define SM_H    81920
#define SM_ZX   147456
#define SM_WS   163840
#define SM_RED  172032
#define SM_TOT  172544

extern __shared__ char sm_raw[];

// contention-free flag barrier: each block stores its own flag, 1 warp polls
__device__ __forceinline__ void gbar(unsigned& gen) {
    gen++;
    __syncthreads();
    __threadfence();
    if (threadIdx.x == 0) __stcg(&g_flags[blockIdx.x], gen);
    if (threadIdx.x < 32) {
        const uint4* f = (const uint4*)g_flags + threadIdx.x;
        for (;;) {
            uint4 v = __ldcg(f);
            if (v.x >= gen && v.y >= gen && v.z >= gen && v.w >= gen) break;
        }
    }
    __threadfence();
    __syncthreads();
}

__global__ __launch_bounds__(256, 1) void rnn_loop() {
    const int tid = threadIdx.x, bid = blockIdx.x;
    const int lane = tid & 31, w = tid >> 5;
    const int l15 = lane & 15, lhi = lane >> 4;
    uint32_t smb = (uint32_t)__cvta_generic_to_shared(sm_raw);
    uint32_t whb = smb + SM_WH, hb = smb + SM_H;
    float* sZX = (float*)(sm_raw + SM_ZX);
    float* sWs = (float*)(sm_raw + SM_WS);
    float* sRed = (float*)(sm_raw + SM_RED);

    for (int i = tid; i < 4096; i += 256) {
        int k = i >> 2, g = i & 3;
        cpa16(whb + (uint32_t)k * 80 + g * 16,
              gb_Wh + (size_t)k * H4_ + g * 1024 + bid * 8);
    }
    cp_commit(); cp_wait0();
    __syncthreads();

    float hreg[2][2], creg[2][2];
#pragma unroll
    for (int qn = 0; qn < 2; qn++) {
        int n = 16 * w + (lane >> 2) + 8 * qn;
#pragma unroll
        for (int qh = 0; qh < 2; qh++) {
            float hv = g_h0[n * H_ + bid * 8 + (lane & 3) * 2 + qh];
            hreg[qn][qh] = hv; creg[qn][qh] = hv;
        }
    }

    unsigned gen = 0;

    auto score_partial = [&]() {
        float sc0[16], sc1[16];
#pragma unroll
        for (int l = 0; l < 16; l++) { sc0[l] = 0.f; sc1[l] = 0.f; }
#pragma unroll
        for (int qn = 0; qn < 2; qn++) {
            float* sc = qn ? sc1 : sc0;
            int n = 16 * w + (lane >> 2) + 8 * qn;
#pragma unroll
            for (int qh = 0; qh < 2; qh++) {
                int hidx = bid * 8 + (lane & 3) * 2 + qh;
                float h = hreg[qn][qh];
                const float4* Ar = (const float4*)&g_A[((size_t)n * H_ + hidx) * L_];
#pragma unroll
                for (int j = 0; j < 4; j++) {
                    float4 a = Ar[j];
                    sc[4 * j + 0] += h * a.x; sc[4 * j + 1] += h * a.y;
                    sc[4 * j + 2] += h * a.z; sc[4 * j + 3] += h * a.w;
                }
            }
        }
#pragma unroll
        for (int off = 1; off <= 2; off <<= 1)
#pragma unroll
            for (int l = 0; l < 16; l++) {
                sc0[l] += __shfl_xor_sync(0xffffffffu, sc0[l], off);
                sc1[l] += __shfl_xor_sync(0xffffffffu, sc1[l], off);
            }
        if ((lane & 3) == 0) {
            int n0 = 16 * w + (lane >> 2);
            float4* d0 = (float4*)&g_ps[((size_t)bid * 128 + n0) * 16];
            d0[0] = make_float4(sc0[0], sc0[1], sc0[2], sc0[3]);
            d0[1] = make_float4(sc0[4], sc0[5], sc0[6], sc0[7]);
            d0[2] = make_float4(sc0[8], sc0[9], sc0[10], sc0[11]);
            d0[3] = make_float4(sc0[12], sc0[13], sc0[14], sc0[15]);
            float4* d1 = (float4*)&g_ps[((size_t)bid * 128 + n0 + 8) * 16];
            d1[0] = make_float4(sc1[0], sc1[1], sc1[2], sc1[3]);
            d1[1] = make_float4(sc1[4], sc1[5], sc1[6], sc1[7]);
            d1[2] = make_float4(sc1[8], sc1[9], sc1[10], sc1[11]);
            d1[3] = make_float4(sc1[12], sc1[13], sc1[14], sc1[15]);
        }
    };

    auto wreduce = [&]() {
        if (tid < 128) {
            const float4* p = (const float4*)&g_ps[((size_t)tid * 128 + bid) * 16];
            float4 v0 = __ldcg(p), v1 = __ldcg(p + 1), v2 = __ldcg(p + 2), v3 = __ldcg(p + 3);
            float v[16] = {v0.x, v0.y, v0.z, v0.w, v1.x, v1.y, v1.z, v1.w,
                           v2.x, v2.y, v2.z, v2.w, v3.x, v3.y, v3.z, v3.w};
#pragma unroll
            for (int off = 16; off >= 1; off >>= 1)
#pragma unroll
                for (int l = 0; l < 16; l++)
                    v[l] += __shfl_xor_sync(0xffffffffu, v[l], off);
            if ((tid & 31) == 0)
#pragma unroll
                for (int l = 0; l < 16; l++) sRed[(tid >> 5) * 16 + l] = v[l];
        }
        __syncthreads();
        if (tid == 0) {
            float sv[16];
            float mx = -INFINITY;
#pragma unroll
            for (int l = 0; l < 16; l++) {
                sv[l] = (sRed[l] + sRed[16 + l] + sRed[32 + l] + sRed[48 + l]) * 0.03125f;
                mx = fmaxf(mx, sv[l]);
            }
            float se = 0.0f;
#pragma unroll
            for (int l = 0; l < 16; l++) { sv[l] = __expf(sv[l] - mx); se += sv[l]; }
            float inv = 1.0f / se;
#pragma unroll
            for (int l = 0; l < 16; l++) g_w[bid * 16 + l] = sv[l] * inv;
        }
        __syncthreads();
    };

    // ---- pre-loop: weights for t=0 ----
    score_partial();
    gbar(gen);            // publishes h0-scores
    wreduce();            // g_w for t=0

    for (int t = 0; t < T_; t++) {
        const int cur = t & 1, nxt = cur ^ 1;
        const __nv_bfloat16* hsrc = gb_hbuf[cur];

        // ---- prefetch h chunk 0, then GEMM z = h @ Wh-slice ----
        {
            uint32_t dst = hb;
#pragma unroll
            for (int i = 0; i < 8; i++) {
                int id = tid + 256 * i;
                int n = id >> 4, g = id & 15;
                uint32_t off = (uint32_t)n * 256 + ((g & 8) << 4) + ((((g & 7) ^ (n & 7))) << 4);
                cpa16(dst + off, hsrc + (size_t)n * H_ + g * 8);
            }
            cp_commit();
        }
        float acc[4][4] = {};
        for (int kc = 0; kc < 8; kc++) {
            if (kc < 7) {
                uint32_t dst = hb + (uint32_t)((kc + 1) & 1) * 32768;
#pragma unroll
                for (int i = 0; i < 8; i++) {
                    int id = tid + 256 * i;
                    int n = id >> 4, g = id & 15;
                    uint32_t off = (uint32_t)n * 256 + ((g & 8) << 4) + ((((g & 7) ^ (n & 7))) << 4);
                    cpa16(dst + off, hsrc + (size_t)n * H_ + (kc + 1) * 128 + g * 8);
                }
                cp_commit(); cp_wait1();
            } else {
                cp_wait0();
            }
            __syncthreads();
            uint32_t hbase = hb + (uint32_t)(kc & 1) * 32768;
            int n_ld = 16 * w + l15;
#pragma unroll
            for (int k16 = 0; k16 < 8; k16++) {
                int cf = 2 * k16 + lhi;
                unsigned af[4];
                ldsm4(hbase + (uint32_t)n_ld * 256 + ((cf & 8) << 4) +
                          (uint32_t)(((cf & 7) ^ (n_ld & 7)) << 4),
                      af[0], af[1], af[2], af[3]);
                int kg = kc * 8 + k16;
                uint32_t brow = whb + (uint32_t)(kg * 16 + l15) * 80;
                unsigned b0, b1, b2, b3, b4, b5, b6, b7;
                ldsm4t(brow + (uint32_t)(lhi << 4), b0, b1, b2, b3);
                ldsm4t(brow + (uint32_t)((2 + lhi) << 4), b4, b5, b6, b7);
                bmma(acc[0], af, b0, b1);
                bmma(acc[1], af, b2, b3);
                bmma(acc[2], af, b4, b5);
                bmma(acc[3], af, b6, b7);
            }
            __syncthreads();
        }

        // ---- barrier publishes g_w from wreduce ----
        gbar(gen);

        // ---- zx = xproj(t) + w . Pp (bf16, [n][c32][l] layout) ----
        for (int i = tid; i < 2048; i += 256) sWs[i] = __ldcg(&g_w[i]);
        __syncthreads();
        for (int v = tid; v < 4096; v += 256) {
            int n = v >> 5, c32 = v & 31;
            int gcol = (c32 >> 3) * 1024 + bid * 8 + (c32 & 7);
            float a = g_xproj[((size_t)(n * T_ + t)) * H4_ + gcol];
            const __nv_bfloat16* pp = &gb_Pp[(((size_t)bid * 128 + n) * 32 + c32) * 16];
            uint4 p0 = *(const uint4*)pp;
            uint4 p1 = *(const uint4*)(pp + 8);
            const float* wn_ = &sWs[n * 16];
            const __nv_bfloat162* h2a = (const __nv_bfloat162*)&p0;
            const __nv_bfloat162* h2b = (const __nv_bfloat162*)&p1;
#pragma unroll
            for (int j = 0; j < 4; j++) {
                float2 fa = __bfloat1622float2(h2a[j]);
                float2 fb = __bfloat1622float2(h2b[j]);
                a = fmaf(wn_[2 * j], fa.x, a);
                a = fmaf(wn_[2 * j + 1], fa.y, a);
                a = fmaf(wn_[8 + 2 * j], fb.x, a);
                a = fmaf(wn_[8 + 2 * j + 1], fb.y, a);
            }
            sZX[v] = a;
        }
        __syncthreads();

        // ---- gates ----
#pragma unroll
        for (int qn = 0; qn < 2; qn++) {
            int n = 16 * w + (lane >> 2) + 8 * qn;
#pragma unroll
            for (int qh = 0; qh < 2; qh++) {
                int hh = (lane & 3) * 2 + qh;
                int q = 2 * qn + qh;
                float zi = acc[0][q] + sZX[n * 32 + hh];
                float zf = acc[1][q] + sZX[n * 32 + 8 + hh];
                float zo = acc[2][q] + sZX[n * 32 + 16 + hh];
                float zg = acc[3][q] + sZX[n * 32 + 24 + hh];
                float c = sigfast(zf) * creg[qn][qh] + sigfast(zi) * tanhfast(zg);
                float hv = sigfast(zo) * tanhfast(c);
                creg[qn][qh] = c;
                hreg[qn][qh] = hv;
                __nv_bfloat16 hb16 = __float2bfloat16_rn(hv);
                gb_hbuf[nxt][n * H_ + bid * 8 + hh] = hb16;
                gb_hn[((size_t)n * T_ + t) * H_ + bid * 8 + hh] = hb16;
            }
        }

        // ---- scores + reduce for NEXT step (skipped on the last) ----
        if (t < T_ - 1) {
            score_partial();
            gbar(gen);        // publishes new h + partials
            wreduce();        // g_w for t+1
        }
    }
}

// ---------------- launch ----------------
extern "C" void kernel_launch(void* const* d_in, const int* in_sizes, int n_in,
                              void* d_out, int out_size) {
    const float* features = (const float*)d_in[0];
    const int*   captions = (const int*)d_in[1];
    const float* W_embed  = (const float*)d_in[2];
    const float* W_proj   = (const float*)d_in[3];
    const float* b_proj   = (const float*)d_in[4];
    const float* Wx       = (const float*)d_in[5];
    const float* Wh       = (const float*)d_in[6];
    const float* Wattn    = (const float*)d_in[7];
    const float* b        = (const float*)d_in[8];
    const float* W_vocab  = (const float*)d_in[9];
    const float* b_vocab  = (const float*)d_in[10];
    float* out = (float*)d_out;

    cudaFuncSetAttribute(rnn_loop, cudaFuncAttributeMaxDynamicSharedMemorySize, SM_TOT);

    combo_init<<<1, 128>>>(out);                                   // launch 0
    f2b_all<<<(R4 + 255) / 256, 256>>>(W_embed, Wx, Wh, Wattn, W_vocab); // 1
    kA<<<N_, 256>>>(features, W_proj, b_proj);                     // 2
    gemm_embed<<<dim3(H4_ / 128, (N_ * T_) / 128), 256>>>(captions, b); // 3
    gemm_P<<<dim3(H4_ / 128, (N_ * L_) / 128), 256>>>();           // 4
    rnn_loop<<<NBLK, 256, SM_TOT>>>();                             // 5  <- ncu -s 5
    gemm_vocab<<<dim3(NBX, (N_ * T_) / 128), 256>>>(b_vocab, captions); // 6
    loss_f<<<(N_ * T_) / 32, 256>>>(captions, out);                // 7
}

// round 12
// speedup vs baseline: 4.8172x; 1.0359x over previous
#include <cuda_runtime.h>
#include <cuda_bf16.h>
#include <cstdint>
#include <math.h>

#define N_   128
#define T_   32
#define TCAP 33
#define D_   400
#define WE_  512
#define H_   1024
#define H4_  4096
#define V_   10000
#define L_   16
#define NBLK 128
#define NBX  79
#define NLSE (NBX * 2)

// ---------------- device scratch ----------------
__device__ float g_A[N_ * H_ * L_];                       // [n][h][l]
__device__ float g_h0[N_ * H_];
__device__ float g_xproj[(size_t)N_ * T_ * H4_];
__device__ float g_ps[NBLK * N_ * L_];
__device__ float g_w[N_ * L_];
__device__ float2 g_lsep[(size_t)N_ * T_ * NLSE];
__device__ float g_stgt[N_ * T_];
__device__ __align__(128) unsigned g_flags[NBLK * 8];     // 1 flag / 32B sector

// bf16 operands
__device__ __nv_bfloat16 gb_Wemb[(size_t)V_ * WE_];
__device__ __nv_bfloat16 gb_Wx[(size_t)WE_ * H4_];
__device__ __nv_bfloat16 gb_Wh[(size_t)H_ * H4_];
__device__ __nv_bfloat16 gb_Wattn[(size_t)H_ * H4_];
__device__ __nv_bfloat16 gb_Wv[(size_t)H_ * V_];
__device__ __nv_bfloat16 gb_At[N_ * L_ * H_];
__device__ __nv_bfloat16 gb_hbuf[2][N_ * H_];
__device__ __nv_bfloat16 gb_hn[N_ * T_ * H_];
__device__ __nv_bfloat16 gb_Pp[(size_t)N_ * L_ * H4_];    // [blk][n][c32][l] bf16

extern __shared__ char sm_raw[];

// fast transcendentals (MUFU)
__device__ __forceinline__ float tanhfast(float x) {
    float y; asm("tanh.approx.f32 %0, %1;" : "=f"(y) : "f"(x)); return y;
}
__device__ __forceinline__ float sigfast(float x) {
    return fmaf(0.5f, tanhfast(0.5f * x), 0.5f);
}

// ---------------- combined init (out + flags) ----------------
__global__ void combo_init(float* out) {
    if (threadIdx.x == 0) out[0] = 0.0f;
    for (int i = threadIdx.x; i < NBLK * 8; i += 256) g_flags[i] = 0u;
}

// ---------------- all fp32 -> bf16 conversions in ONE kernel ----------------
#define R0 640000u
#define R1 (R0 + 262144u)
#define R2 (R1 + 524288u)
#define R3 (R2 + 524288u)
#define R4 (R3 + 1280000u)
__global__ __launch_bounds__(256) void f2b_all(const float* __restrict__ Wemb,
                                               const float* __restrict__ Wx,
                                               const float* __restrict__ Wh,
                                               const float* __restrict__ Wattn,
                                               const float* __restrict__ Wv) {
    unsigned i8 = blockIdx.x * 256 + threadIdx.x;
    const float* s; __nv_bfloat16* d; unsigned base;
    if (i8 < R0)      { s = Wemb;  d = gb_Wemb;  base = 0; }
    else if (i8 < R1) { s = Wx;    d = gb_Wx;    base = R0; }
    else if (i8 < R2) { s = Wh;    d = gb_Wh;    base = R1; }
    else if (i8 < R3) { s = Wattn; d = gb_Wattn; base = R2; }
    else if (i8 < R4) { s = Wv;    d = gb_Wv;    base = R3; }
    else return;
    size_t off = (size_t)(i8 - base) * 8;
    float4 v0 = *(const float4*)(s + off);
    float4 v1 = *(const float4*)(s + off + 4);
    union { __nv_bfloat162 h2[4]; uint4 u; } o;
    o.h2[0] = __floats2bfloat162_rn(v0.x, v0.y);
    o.h2[1] = __floats2bfloat162_rn(v0.z, v0.w);
    o.h2[2] = __floats2bfloat162_rn(v1.x, v1.y);
    o.h2[3] = __floats2bfloat162_rn(v1.z, v1.w);
    *(uint4*)(d + off) = o.u;
}

// ---------------- A_flat + A^T + h0 ----------------
__global__ __launch_bounds__(256) void kA(const float* __restrict__ feat,
                                          const float* __restrict__ Wp,
                                          const float* __restrict__ bp) {
    int n = blockIdx.x;
    __shared__ float fsh[D_ * L_];
    const float* f = feat + (size_t)n * D_ * L_;
    for (int i = threadIdx.x; i < D_ * L_; i += 256) fsh[i] = f[i];
    __syncthreads();
    for (int h = threadIdx.x; h < H_; h += 256) {
        float acc[L_];
        float bb = bp[h];
#pragma unroll
        for (int l = 0; l < L_; l++) acc[l] = bb;
        for (int d = 0; d < D_; d++) {
            float wv = Wp[d * H_ + h];
            const float* fr = &fsh[d * L_];
#pragma unroll
            for (int l = 0; l < L_; l++) acc[l] = fmaf(fr[l], wv, acc[l]);
        }
        float s = 0.0f;
        float* Ar = g_A + ((size_t)n * H_ + h) * L_;
#pragma unroll
        for (int l = 0; l < L_; l++) {
            Ar[l] = acc[l];
            gb_At[((size_t)n * L_ + l) * H_ + h] = __float2bfloat16_rn(acc[l]);
            s += acc[l];
        }
        float h0 = s * (1.0f / 16.0f);
        g_h0[n * H_ + h] = h0;
        gb_hbuf[0][n * H_ + h] = __float2bfloat16_rn(h0);
    }
}

// ================= BF16 mma GEMM core =================
__device__ __forceinline__ void ldsm4(uint32_t a, unsigned& r0, unsigned& r1,
                                      unsigned& r2, unsigned& r3) {
    asm volatile("ldmatrix.sync.aligned.m8n8.x4.shared.b16 {%0,%1,%2,%3}, [%4];"
                 : "=r"(r0), "=r"(r1), "=r"(r2), "=r"(r3) : "r"(a));
}
__device__ __forceinline__ void ldsm4t(uint32_t a, unsigned& r0, unsigned& r1,
                                       unsigned& r2, unsigned& r3) {
    asm volatile("ldmatrix.sync.aligned.m8n8.x4.trans.shared.b16 {%0,%1,%2,%3}, [%4];"
                 : "=r"(r0), "=r"(r1), "=r"(r2), "=r"(r3) : "r"(a));
}
__device__ __forceinline__ void bmma(float* c, const unsigned* a,
                                     unsigned b0, unsigned b1) {
    asm volatile("mma.sync.aligned.m16n8k16.row.col.f32.bf16.bf16.f32 "
                 "{%0,%1,%2,%3},{%4,%5,%6,%7},{%8,%9},{%0,%1,%2,%3};"
                 : "+f"(c[0]), "+f"(c[1]), "+f"(c[2]), "+f"(c[3])
                 : "r"(a[0]), "r"(a[1]), "r"(a[2]), "r"(a[3]), "r"(b0), "r"(b1));
}
__device__ __forceinline__ void cpa16(uint32_t dst, const void* src) {
    asm volatile("cp.async.cg.shared.global [%0], [%1], 16;" ::"r"(dst), "l"(src));
}
__device__ __forceinline__ void cpa16z(uint32_t dst, const void* src, unsigned sz) {
    asm volatile("cp.async.cg.shared.global [%0], [%1], 16, %2;"
                 ::"r"(dst), "l"(src), "r"(sz));
}
__device__ __forceinline__ void cp_commit() { asm volatile("cp.async.commit_group;"); }
__device__ __forceinline__ void cp_wait2() { asm volatile("cp.async.wait_group 2;"); }
__device__ __forceinline__ void cp_wait1() { asm volatile("cp.async.wait_group 1;"); }
__device__ __forceinline__ void cp_wait0() { asm volatile("cp.async.wait_group 0;"); }

struct BfgLoader {
    const __nv_bfloat16 *a0, *a1, *b0, *b1;
    uint32_t aoff0, aoff1, boff0, boff1;
    size_t bstep;
    unsigned bsz;
    __device__ __forceinline__ void issue(int it, uint32_t dA, uint32_t dB) const {
        cpa16(dA + aoff0, a0 + it * 32);
        cpa16(dA + aoff1, a1 + it * 32);
        cpa16z(dB + boff0, b0 + (size_t)it * bstep, bsz);
        cpa16z(dB + boff1, b1 + (size_t)it * bstep, bsz);
    }
};

__device__ __forceinline__ void bfg_compute(uint32_t bA, uint32_t bB,
                                            int lane, int wm, int wn,
                                            float acc[2][8][4]) {
    const int l15 = lane & 15, l7 = lane & 7, lhi = lane >> 4;
    const int mA0 = wm * 32 + l15, mA1 = mA0 + 16;
    const uint32_t aR0 = (uint32_t)mA0 * 128, aR1 = (uint32_t)mA1 * 128;
    const int a70 = mA0 & 7, a71 = mA1 & 7;
    const uint32_t bRk = (uint32_t)l15 * 256;
#pragma unroll
    for (int ks = 0; ks < 2; ks++) {
        int c = ks * 2 + lhi;
        unsigned af0[4], af1[4];
        ldsm4(bA + aR0 + (uint32_t)(((c ^ a70) & 7) << 4),
              af0[0], af0[1], af0[2], af0[3]);
        ldsm4(bA + aR1 + (uint32_t)(((c ^ a71) & 7) << 4),
              af1[0], af1[1], af1[2], af1[3]);
#pragma unroll
        for (int p = 0; p < 4; p++) {
            unsigned bf0, bf1, bf2, bf3;
            int g = wn * 8 + p * 2 + lhi;
            ldsm4t(bB + (uint32_t)(ks * 16) * 256 + bRk + (uint32_t)((g ^ l7) << 4),
                   bf0, bf1, bf2, bf3);
            bmma(acc[0][2 * p],     af0, bf0, bf1);
            bmma(acc[0][2 * p + 1], af0, bf2, bf3);
            bmma(acc[1][2 * p],     af1, bf0, bf1);
            bmma(acc[1][2 * p + 1], af1, bf2, bf3);
        }
    }
}

// 3-stage pipeline
__device__ __forceinline__ void bfg_run(const BfgLoader& ld, int nIter,
                                        uint32_t sA0, uint32_t sB0,
                                        int lane, int wm, int wn,
                                        float acc[2][8][4]) {
    ld.issue(0, sA0, sB0);
    cp_commit();
    if (nIter > 1) { ld.issue(1, sA0 + 16384, sB0 + 8192); cp_commit(); }
    for (int it = 0; it < nIter; it++) {
        int b = it % 3;
        if (it + 2 < nIter) {
            int b2 = (it + 2) % 3;
            ld.issue(it + 2, sA0 + (uint32_t)b2 * 16384, sB0 + (uint32_t)b2 * 8192);
            cp_commit();
            cp_wait2();
        } else if (it + 1 < nIter) {
            cp_wait1();
        } else {
            cp_wait0();
        }
        __syncthreads();
        bfg_compute(sA0 + (uint32_t)b * 16384, sB0 + (uint32_t)b * 8192,
                    lane, wm, wn, acc);
        __syncthreads();
    }
}

struct BfgIdx {
    int tid, lane, wid, wm, wn, am, ag, bks, bg;
    uint32_t aoff0, aoff1, boff0, boff1;
    __device__ __forceinline__ BfgIdx() {
        tid = threadIdx.x; lane = tid & 31; wid = tid >> 5;
        wm = wid >> 1; wn = wid & 1;
        am = tid >> 2; ag = tid & 3;
        bks = tid >> 4; bg = tid & 15;
        aoff0 = (uint32_t)am * 128 + (uint32_t)(((ag ^ (am & 7)) & 7) << 4);
        aoff1 = aoff0 + 64 * 128;
        boff0 = (uint32_t)bks * 256 + (uint32_t)((bg ^ (bks & 7)) << 4);
        boff1 = boff0 + 16 * 256;
    }
};

#define BFG_DYNSMEM 73728
#define BFG_SMEM                                                               \
    uint32_t smb_ = (uint32_t)__cvta_generic_to_shared(sm_raw);                \
    uint32_t sA0 = smb_;                                                       \
    uint32_t sB0 = smb_ + 3 * 16384;

// ---- xproj = W_embed[cap] @ Wx + b ----
__global__ __launch_bounds__(256) void gemm_embed(const int* __restrict__ captions,
                                                  const float* __restrict__ bias) {
    int row0 = blockIdx.y * 128, col0 = blockIdx.x * 128;
    BFG_SMEM;
    BfgIdx ix;
    float acc[2][8][4] = {};
    int r0i = row0 + ix.am, r1i = r0i + 64;
    BfgLoader ld;
    ld.a0 = gb_Wemb + (size_t)captions[(r0i >> 5) * TCAP + (r0i & 31)] * WE_ + ix.ag * 8;
    ld.a1 = gb_Wemb + (size_t)captions[(r1i >> 5) * TCAP + (r1i & 31)] * WE_ + ix.ag * 8;
    ld.b0 = gb_Wx + (size_t)ix.bks * H4_ + col0 + ix.bg * 8;
    ld.b1 = ld.b0 + (size_t)16 * H4_;
    ld.aoff0 = ix.aoff0; ld.aoff1 = ix.aoff1; ld.boff0 = ix.boff0; ld.boff1 = ix.boff1;
    ld.bstep = (size_t)32 * H4_; ld.bsz = 16;
    bfg_run(ld, WE_ / 32, sA0, sB0, ix.lane, ix.wm, ix.wn, acc);
    int eg = ix.lane >> 2, ec = (ix.lane & 3) * 2;
#pragma unroll
    for (int mt = 0; mt < 2; mt++)
#pragma unroll
        for (int nt = 0; nt < 8; nt++) {
            int row = row0 + ix.wm * 32 + mt * 16 + eg;
            int col = col0 + ix.wn * 64 + nt * 8 + ec;
            float b0v = bias[col], b1v = bias[col + 1];
            *(float2*)&g_xproj[(size_t)row * H4_ + col] =
                make_float2(acc[mt][nt][0] + b0v, acc[mt][nt][1] + b1v);
            *(float2*)&g_xproj[(size_t)(row + 8) * H4_ + col] =
                make_float2(acc[mt][nt][2] + b0v, acc[mt][nt][3] + b1v);
        }
}

// ---- P = A^T @ Wattn, written bf16 block-major [blk][n][c32][l] ----
__global__ __launch_bounds__(256) void gemm_P() {
    int row0 = blockIdx.y * 128, col0 = blockIdx.x * 128;
    BFG_SMEM;
    BfgIdx ix;
    float acc[2][8][4] = {};
    BfgLoader ld;
    ld.a0 = gb_At + (size_t)(row0 + ix.am) * H_ + ix.ag * 8;
    ld.a1 = ld.a0 + (size_t)64 * H_;
    ld.b0 = gb_Wattn + (size_t)ix.bks * H4_ + col0 + ix.bg * 8;
    ld.b1 = ld.b0 + (size_t)16 * H4_;
    ld.aoff0 = ix.aoff0; ld.aoff1 = ix.aoff1; ld.boff0 = ix.boff0; ld.boff1 = ix.boff1;
    ld.bstep = (size_t)32 * H4_; ld.bsz = 16;
    bfg_run(ld, H_ / 32, sA0, sB0, ix.lane, ix.wm, ix.wn, acc);
    int eg = ix.lane >> 2, ec = (ix.lane & 3) * 2;
#pragma unroll
    for (int mt = 0; mt < 2; mt++)
#pragma unroll
        for (int nt = 0; nt < 8; nt++) {
            int row = row0 + ix.wm * 32 + mt * 16 + eg;        // = n*16 + l, l in 0..7
            int col = col0 + ix.wn * 64 + nt * 8 + ec;
            int n = row >> 4, l = row & 15;
            int gate = col >> 10, rem = col & 1023;
            int bblk = rem >> 3, c32 = gate * 8 + (rem & 7);
            size_t base = (((size_t)bblk * 128 + n) * 32 + c32) * 16 + l;
            gb_Pp[base]          = __float2bfloat16_rn(acc[mt][nt][0]);
            gb_Pp[base + 16]     = __float2bfloat16_rn(acc[mt][nt][1]);  // c32+1
            gb_Pp[base + 8]      = __float2bfloat16_rn(acc[mt][nt][2]);  // l+8
            gb_Pp[base + 16 + 8] = __float2bfloat16_rn(acc[mt][nt][3]);
        }
}

// ---- LSE merge helper ----
__device__ __forceinline__ void lsemerge(float& m, float& s, float om, float os) {
    float M = fmaxf(m, om);
    if (M == -INFINITY) { s = 0.0f; return; }
    float t1 = (m == -INFINITY) ? 0.0f : s * __expf(m - M);
    float t2 = (om == -INFINITY) ? 0.0f : os * __expf(om - M);
    m = M; s = t1 + t2;
}

// ---- scores = hn @ W_vocab + b : fused LSE partials + target harvest ----
__global__ __launch_bounds__(256) void gemm_vocab(const float* __restrict__ bv,
                                                  const int* __restrict__ captions) {
    int row0 = blockIdx.y * 128, col0 = blockIdx.x * 128;
    BFG_SMEM;
    BfgIdx ix;
    float acc[2][8][4] = {};
    BfgLoader ld;
    ld.a0 = gb_hn + (size_t)(row0 + ix.am) * H_ + ix.ag * 8;
    ld.a1 = ld.a0 + (size_t)64 * H_;
    int bcol = col0 + ix.bg * 8;
    ld.bsz = (bcol + 8 <= V_) ? 16u : 0u;
    ld.b0 = gb_Wv + (size_t)ix.bks * V_ + ((bcol + 8 <= V_) ? bcol : 0);
    ld.b1 = ld.b0 + (size_t)16 * V_;
    ld.aoff0 = ix.aoff0; ld.aoff1 = ix.aoff1; ld.boff0 = ix.boff0; ld.boff1 = ix.boff1;
    ld.bstep = (size_t)32 * V_;
    bfg_run(ld, H_ / 32, sA0, sB0, ix.lane, ix.wm, ix.wn, acc);
    int eg = ix.lane >> 2, ec = (ix.lane & 3) * 2;
    float bvr[8][2];
#pragma unroll
    for (int nt = 0; nt < 8; nt++) {
        int col = col0 + ix.wn * 64 + nt * 8 + ec;
        bvr[nt][0] = (col < V_) ? bv[col] : 0.0f;
        bvr[nt][1] = (col + 1 < V_) ? bv[col + 1] : 0.0f;
    }
#pragma unroll
    for (int mt = 0; mt < 2; mt++)
#pragma unroll
        for (int qn = 0; qn < 2; qn++) {
            int row = row0 + ix.wm * 32 + mt * 16 + eg + 8 * qn;
            int tgt = captions[(row >> 5) * TCAP + (row & 31) + 1];
            float vals[16];
            float m = -INFINITY;
#pragma unroll
            for (int nt = 0; nt < 8; nt++)
#pragma unroll
                for (int j = 0; j < 2; j++) {
                    int col = col0 + ix.wn * 64 + nt * 8 + ec + j;
                    float v = acc[mt][nt][2 * qn + j] + bvr[nt][j];
                    vals[nt * 2 + j] = v;
                    if (col < V_) {
                        m = fmaxf(m, v);
                        if (col == tgt) g_stgt[row] = v;
                    }
                }
            float s = 0.0f;
#pragma unroll
            for (int nt = 0; nt < 8; nt++)
#pragma unroll
                for (int j = 0; j < 2; j++) {
                    int col = col0 + ix.wn * 64 + nt * 8 + ec + j;
                    if (col < V_)
                        s += __expf(vals[nt * 2 + j] - m);
                }
#pragma unroll
            for (int off = 1; off <= 2; off <<= 1) {
                float om = __shfl_xor_sync(0xffffffffu, m, off);
                float os = __shfl_xor_sync(0xffffffffu, s, off);
                lsemerge(m, s, om, os);
            }
            if ((ix.lane & 3) == 0)
                g_lsep[(size_t)row * NLSE + blockIdx.x * 2 + ix.wn] = make_float2(m, s);
        }
}

// ---- loss: merge LSE partials, nll on targets ----
__global__ __launch_bounds__(256) void loss_f(const int* __restrict__ captions,
                                              float* __restrict__ out) {
    int r = blockIdx.x * 32 + (threadIdx.x >> 3);
    int j8 = threadIdx.x & 7;
    float m = -INFINITY, s = 0.0f;
    for (int j = j8; j < NLSE; j += 8) {
        float2 p = g_lsep[(size_t)r * NLSE + j];
        lsemerge(m, s, p.x, p.y);
    }
#pragma unroll
    for (int off = 1; off <= 4; off <<= 1) {
        float om = __shfl_xor_sync(0xffffffffu, m, off);
        float os = __shfl_xor_sync(0xffffffffu, s, off);
        lsemerge(m, s, om, os);
    }
    if (j8 == 0) {
        int n = r >> 5, t = r & 31;
        int tgt = captions[n * TCAP + t + 1];
        if (tgt != 0) {
            float nll = logf(s) + m - g_stgt[r];
            atomicAdd(out, nll * (1.0f / (float)N_));
        }
    }
}

// ================= persistent RNN loop =================
// smem: Wh 81920 | h 3x32768 | zx 16384 | ws 8192 | red 512
#define SM_WH   0
#define SM_H    81920
#define SM_ZX   180224
#define SM_WS   196608
#define SM_RED  204800
#define SM_TOT  205312

// contention-free flag barrier: 1 flag / 32B sector
__device__ __forceinline__ void gbar(unsigned& gen) {
    gen++;
    __syncthreads();
    __threadfence();
    if (threadIdx.x == 0) __stcg(&g_flags[blockIdx.x * 8], gen);
    if (threadIdx.x < 32) {
        for (;;) {
            unsigned v0 = __ldcg(&g_flags[threadIdx.x * 8]);
            unsigned v1 = __ldcg(&g_flags[(threadIdx.x + 32) * 8]);
            unsigned v2 = __ldcg(&g_flags[(threadIdx.x + 64) * 8]);
            unsigned v3 = __ldcg(&g_flags[(threadIdx.x + 96) * 8]);
            if (v0 >= gen && v1 >= gen && v2 >= gen && v3 >= gen) break;
        }
    }
    __threadfence();
    __syncthreads();
}

__global__ __launch_bounds__(256, 1) void rnn_loop() {
    const int tid = threadIdx.x, bid = blockIdx.x;
    const int lane = tid & 31, w = tid >> 5;
    const int l15 = lane & 15, lhi = lane >> 4;
    uint32_t smb = (uint32_t)__cvta_generic_to_shared(sm_raw);
    uint32_t whb = smb + SM_WH, hb = smb + SM_H;
    float* sZX = (float*)(sm_raw + SM_ZX);
    float* sWs = (float*)(sm_raw + SM_WS);
    float* sRed = (float*)(sm_raw + SM_RED);

    for (int i = tid; i < 4096; i += 256) {
        int k = i >> 2, g = i & 3;
        cpa16(whb + (uint32_t)k * 80 + g * 16,
              gb_Wh + (size_t)k * H4_ + g * 1024 + bid * 8);
    }
    cp_commit(); cp_wait0();
    __syncthreads();

    float hreg[2][2], creg[2][2];
#pragma unroll
    for (int qn = 0; qn < 2; qn++) {
        int n = 16 * w + (lane >> 2) + 8 * qn;
#pragma unroll
        for (int qh = 0; qh < 2; qh++) {
            float hv = g_h0[n * H_ + bid * 8 + (lane & 3) * 2 + qh];
            hreg[qn][qh] = hv; creg[qn][qh] = hv;
        }
    }

    unsigned gen = 0;

    auto issue_h = [&](const __nv_bfloat16* hsrc, int kc, uint32_t dst) {
#pragma unroll
        for (int i = 0; i < 8; i++) {
            int id = tid + 256 * i;
            int n = id >> 4, g = id & 15;
            uint32_t off = (uint32_t)n * 256 + ((g & 8) << 4) + ((((g & 7) ^ (n & 7))) << 4);
            cpa16(dst + off, hsrc + (size_t)n * H_ + kc * 128 + g * 8);
        }
        cp_commit();
    };

    auto score_partial = [&]() {
        float sc0[16], sc1[16];
#pragma unroll
        for (int l = 0; l < 16; l++) { sc0[l] = 0.f; sc1[l] = 0.f; }
#pragma unroll
        for (int qn = 0; qn < 2; qn++) {
            float* sc = qn ? sc1 : sc0;
            int n = 16 * w + (lane >> 2) + 8 * qn;
#pragma unroll
            for (int qh = 0; qh < 2; qh++) {
                int hidx = bid * 8 + (lane & 3) * 2 + qh;
                float h = hreg[qn][qh];
                const float4* Ar = (const float4*)&g_A[((size_t)n * H_ + hidx) * L_];
#pragma unroll
                for (int j = 0; j < 4; j++) {
                    float4 a = Ar[j];
                    sc[4 * j + 0] += h * a.x; sc[4 * j + 1] += h * a.y;
                    sc[4 * j + 2] += h * a.z; sc[4 * j + 3] += h * a.w;
                }
            }
        }
#pragma unroll
        for (int off = 1; off <= 2; off <<= 1)
#pragma unroll
            for (int l = 0; l < 16; l++) {
                sc0[l] += __shfl_xor_sync(0xffffffffu, sc0[l], off);
                sc1[l] += __shfl_xor_sync(0xffffffffu, sc1[l], off);
            }
        if ((lane & 3) == 0) {
            int n0 = 16 * w + (lane >> 2);
            float4* d0 = (float4*)&g_ps[((size_t)bid * 128 + n0) * 16];
            d0[0] = make_float4(sc0[0], sc0[1], sc0[2], sc0[3]);
            d0[1] = make_float4(sc0[4], sc0[5], sc0[6], sc0[7]);
            d0[2] = make_float4(sc0[8], sc0[9], sc0[10], sc0[11]);
            d0[3] = make_float4(sc0[12], sc0[13], sc0[14], sc0[15]);
            float4* d1 = (float4*)&g_ps[((size_t)bid * 128 + n0 + 8) * 16];
            d1[0] = make_float4(sc1[0], sc1[1], sc1[2], sc1[3]);
            d1[1] = make_float4(sc1[4], sc1[5], sc1[6], sc1[7]);
            d1[2] = make_float4(sc1[8], sc1[9], sc1[10], sc1[11]);
            d1[3] = make_float4(sc1[12], sc1[13], sc1[14], sc1[15]);
        }
    };

    auto wreduce = [&]() {
        if (tid < 128) {
            const float4* p = (const float4*)&g_ps[((size_t)tid * 128 + bid) * 16];
            float4 v0 = __ldcg(p), v1 = __ldcg(p + 1), v2 = __ldcg(p + 2), v3 = __ldcg(p + 3);
            float v[16] = {v0.x, v0.y, v0.z, v0.w, v1.x, v1.y, v1.z, v1.w,
                           v2.x, v2.y, v2.z, v2.w, v3.x, v3.y, v3.z, v3.w};
#pragma unroll
            for (int off = 16; off >= 1; off >>= 1)
#pragma unroll
                for (int l = 0; l < 16; l++)
                    v[l] += __shfl_xor_sync(0xffffffffu, v[l], off);
            if ((tid & 31) == 0)
#pragma unroll
                for (int l = 0; l < 16; l++) sRed[(tid >> 5) * 16 + l] = v[l];
        }
        __syncthreads();
        if (tid == 0) {
            float sv[16];
            float mx = -INFINITY;
#pragma unroll
            for (int l = 0; l < 16; l++) {
                sv[l] = (sRed[l] + sRed[16 + l] + sRed[32 + l] + sRed[48 + l]) * 0.03125f;
                mx = fmaxf(mx, sv[l]);
            }
            float se = 0.0f;
#pragma unroll
            for (int l = 0; l < 16; l++) { sv[l] = __expf(sv[l] - mx); se += sv[l]; }
            float inv = 1.0f / se;
#pragma unroll
            for (int l = 0; l < 16; l++) g_w[bid * 16 + l] = sv[l] * inv;
        }
        __syncthreads();
    };

    // ---- pre-loop: weights for t=0 ----
    score_partial();
    gbar(gen);            // publishes h0-scores
    wreduce();            // g_w for t=0

    for (int t = 0; t < T_; t++) {
        const int cur = t & 1, nxt = cur ^ 1;
        const __nv_bfloat16* hsrc = gb_hbuf[cur];

        // ---- GEMM z = h @ Wh-slice, 3-deep chunk pipeline ----
        issue_h(hsrc, 0, hb);
        issue_h(hsrc, 1, hb + 32768);
        float acc[4][4] = {};
        for (int kc = 0; kc < 8; kc++) {
            int b = kc % 3;
            if (kc + 2 < 8) {
                issue_h(hsrc, kc + 2, hb + (uint32_t)((kc + 2) % 3) * 32768);
                cp_wait2();
            } else if (kc + 1 < 8) {
                cp_wait1();
            } else {
                cp_wait0();
            }
            __syncthreads();
            uint32_t hbase = hb + (uint32_t)b * 32768;
            int n_ld = 16 * w + l15;
#pragma unroll
            for (int k16 = 0; k16 < 8; k16++) {
                int cf = 2 * k16 + lhi;
                unsigned af[4];
                ldsm4(hbase + (uint32_t)n_ld * 256 + ((cf & 8) << 4) +
                          (uint32_t)(((cf & 7) ^ (n_ld & 7)) << 4),
                      af[0], af[1], af[2], af[3]);
                int kg = kc * 8 + k16;
                uint32_t brow = whb + (uint32_t)(kg * 16 + l15) * 80;
                unsigned b0, b1, b2, b3, b4, b5, b6, b7;
                ldsm4t(brow + (uint32_t)(lhi << 4), b0, b1, b2, b3);
                ldsm4t(brow + (uint32_t)((2 + lhi) << 4), b4, b5, b6, b7);
                bmma(acc[0], af, b0, b1);
                bmma(acc[1], af, b2, b3);
                bmma(acc[2], af, b4, b5);
                bmma(acc[3], af, b6, b7);
            }
            __syncthreads();
        }

        // ---- preload xproj into sZX (before the barrier) ----
        for (int v = tid; v < 4096; v += 256) {
            int n = v >> 5, c32 = v & 31;
            int gcol = (c32 >> 3) * 1024 + bid * 8 + (c32 & 7);
            sZX[v] = g_xproj[((size_t)(n * T_ + t)) * H4_ + gcol];
        }

        // ---- barrier publishes g_w from wreduce ----
        gbar(gen);

        // ---- zx += w . Pp (bf16, [n][c32][l] layout) ----
        for (int i = tid; i < 2048; i += 256) sWs[i] = __ldcg(&g_w[i]);
        __syncthreads();
        for (int v = tid; v < 4096; v += 256) {
            int n = v >> 5, c32 = v & 31;
            float a = sZX[v];
            const __nv_bfloat16* pp = &gb_Pp[(((size_t)bid * 128 + n) * 32 + c32) * 16];
            uint4 p0 = *(const uint4*)pp;
            uint4 p1 = *(const uint4*)(pp + 8);
            const float* wn_ = &sWs[n * 16];
            const __nv_bfloat162* h2a = (const __nv_bfloat162*)&p0;
            const __nv_bfloat162* h2b = (const __nv_bfloat162*)&p1;
#pragma unroll
            for (int j = 0; j < 4; j++) {
                float2 fa = __bfloat1622float2(h2a[j]);
                float2 fb = __bfloat1622float2(h2b[j]);
                a = fmaf(wn_[2 * j], fa.x, a);
                a = fmaf(wn_[2 * j + 1], fa.y, a);
                a = fmaf(wn_[8 + 2 * j], fb.x, a);
                a = fmaf(wn_[8 + 2 * j + 1], fb.y, a);
            }
            sZX[v] = a;
        }
        __syncthreads();

        // ---- gates ----
#pragma unroll
        for (int qn = 0; qn < 2; qn++) {
            int n = 16 * w + (lane >> 2) + 8 * qn;
#pragma unroll
            for (int qh = 0; qh < 2; qh++) {
                int hh = (lane & 3) * 2 + qh;
                int q = 2 * qn + qh;
                float zi = acc[0][q] + sZX[n * 32 + hh];
                float zf = acc[1][q] + sZX[n * 32 + 8 + hh];
                float zo = acc[2][q] + sZX[n * 32 + 16 + hh];
                float zg = acc[3][q] + sZX[n * 32 + 24 + hh];
                float c = sigfast(zf) * creg[qn][qh] + sigfast(zi) * tanhfast(zg);
                float hv = sigfast(zo) * tanhfast(c);
                creg[qn][qh] = c;
                hreg[qn][qh] = hv;
                __nv_bfloat16 hb16 = __float2bfloat16_rn(hv);
                gb_hbuf[nxt][n * H_ + bid * 8 + hh] = hb16;
                gb_hn[((size_t)n * T_ + t) * H_ + bid * 8 + hh] = hb16;
            }
        }

        // ---- scores + reduce for NEXT step (skipped on the last) ----
        if (t < T_ - 1) {
            score_partial();
            gbar(gen);        // publishes new h + partials
            wreduce();        // g_w for t+1
        }
    }
}

// ---------------- launch ----------------
extern "C" void kernel_launch(void* const* d_in, const int* in_sizes, int n_in,
                              void* d_out, int out_size) {
    const float* features = (const float*)d_in[0];
    const int*   captions = (const int*)d_in[1];
    const float* W_embed  = (const float*)d_in[2];
    const float* W_proj   = (const float*)d_in[3];
    const float* b_proj   = (const float*)d_in[4];
    const float* Wx       = (const float*)d_in[5];
    const float* Wh       = (const float*)d_in[6];
    const float* Wattn    = (const float*)d_in[7];
    const float* b        = (const float*)d_in[8];
    const float* W_vocab  = (const float*)d_in[9];
    const float* b_vocab  = (const float*)d_in[10];
    float* out = (float*)d_out;

    cudaFuncSetAttribute(rnn_loop, cudaFuncAttributeMaxDynamicSharedMemorySize, SM_TOT);
    cudaFuncSetAttribute(gemm_embed, cudaFuncAttributeMaxDynamicSharedMemorySize, BFG_DYNSMEM);
    cudaFuncSetAttribute(gemm_P, cudaFuncAttributeMaxDynamicSharedMemorySize, BFG_DYNSMEM);
    cudaFuncSetAttribute(gemm_vocab, cudaFuncAttributeMaxDynamicSharedMemorySize, BFG_DYNSMEM);

    combo_init<<<1, 256>>>(out);
    f2b_all<<<(R4 + 255) / 256, 256>>>(W_embed, Wx, Wh, Wattn, W_vocab);
    kA<<<N_, 256>>>(features, W_proj, b_proj);
    gemm_embed<<<dim3(H4_ / 128, (N_ * T_) / 128), 256, BFG_DYNSMEM>>>(captions, b);
    gemm_P<<<dim3(H4_ / 128, (N_ * L_) / 128), 256, BFG_DYNSMEM>>>();
    rnn_loop<<<NBLK, 256, SM_TOT>>>();
    gemm_vocab<<<dim3(NBX, (N_ * T_) / 128), 256, BFG_DYNSMEM>>>(b_vocab, captions);
    loss_f<<<(N_ * T_) / 32, 256>>>(captions, out);
}

// round 13
// speedup vs baseline: 4.9562x; 1.0289x over previous
#include <cuda_runtime.h>
#include <cuda_bf16.h>
#include <cstdint>
#include <math.h>

#define N_   128
#define T_   32
#define TCAP 33
#define D_   400
#define WE_  512
#define H_   1024
#define H4_  4096
#define V_   10000
#define L_   16
#define NBLK 128
#define NBX  79
#define NLSE (NBX * 2)

// ---------------- device scratch ----------------
__device__ float g_A[N_ * H_ * L_];                       // [n][h][l]
__device__ float g_h0[N_ * H_];
__device__ float g_xproj[(size_t)N_ * T_ * H4_];
__device__ float g_ps[NBLK * N_ * L_];
__device__ float g_w[N_ * L_];
__device__ float2 g_lsep[(size_t)N_ * T_ * NLSE];
__device__ float g_stgt[N_ * T_];
__device__ __align__(128) unsigned g_flags[NBLK * 8];     // 1 flag / 32B sector

// bf16 operands
__device__ __nv_bfloat16 gb_Wemb[(size_t)V_ * WE_];
__device__ __nv_bfloat16 gb_Wx[(size_t)WE_ * H4_];
__device__ __nv_bfloat16 gb_Wh[(size_t)H_ * H4_];
__device__ __nv_bfloat16 gb_Wattn[(size_t)H_ * H4_];
__device__ __nv_bfloat16 gb_Wv[(size_t)H_ * V_];
__device__ __nv_bfloat16 gb_At[N_ * L_ * H_];
__device__ __nv_bfloat16 gb_hbuf[2][N_ * H_];
__device__ __nv_bfloat16 gb_hn[N_ * T_ * H_];
__device__ __nv_bfloat16 gb_Pp[(size_t)N_ * L_ * H4_];    // [blk][n][c32][l] bf16

extern __shared__ char sm_raw[];

// fast transcendentals (MUFU)
__device__ __forceinline__ float tanhfast(float x) {
    float y; asm("tanh.approx.f32 %0, %1;" : "=f"(y) : "f"(x)); return y;
}
__device__ __forceinline__ float sigfast(float x) {
    return fmaf(0.5f, tanhfast(0.5f * x), 0.5f);
}

// ---------------- combined init (out + flags) ----------------
__global__ void combo_init(float* out) {
    if (threadIdx.x == 0) out[0] = 0.0f;
    for (int i = threadIdx.x; i < NBLK * 8; i += 256) g_flags[i] = 0u;
}

// ---------------- all fp32 -> bf16 conversions in ONE kernel ----------------
#define R0 640000u
#define R1 (R0 + 262144u)
#define R2 (R1 + 524288u)
#define R3 (R2 + 524288u)
#define R4 (R3 + 1280000u)
__global__ __launch_bounds__(256) void f2b_all(const float* __restrict__ Wemb,
                                               const float* __restrict__ Wx,
                                               const float* __restrict__ Wh,
                                               const float* __restrict__ Wattn,
                                               const float* __restrict__ Wv) {
    unsigned i8 = blockIdx.x * 256 + threadIdx.x;
    const float* s; __nv_bfloat16* d; unsigned base;
    if (i8 < R0)      { s = Wemb;  d = gb_Wemb;  base = 0; }
    else if (i8 < R1) { s = Wx;    d = gb_Wx;    base = R0; }
    else if (i8 < R2) { s = Wh;    d = gb_Wh;    base = R1; }
    else if (i8 < R3) { s = Wattn; d = gb_Wattn; base = R2; }
    else if (i8 < R4) { s = Wv;    d = gb_Wv;    base = R3; }
    else return;
    size_t off = (size_t)(i8 - base) * 8;
    float4 v0 = *(const float4*)(s + off);
    float4 v1 = *(const float4*)(s + off + 4);
    union { __nv_bfloat162 h2[4]; uint4 u; } o;
    o.h2[0] = __floats2bfloat162_rn(v0.x, v0.y);
    o.h2[1] = __floats2bfloat162_rn(v0.z, v0.w);
    o.h2[2] = __floats2bfloat162_rn(v1.x, v1.y);
    o.h2[3] = __floats2bfloat162_rn(v1.z, v1.w);
    *(uint4*)(d + off) = o.u;
}

// ---------------- A_flat + A^T + h0 ----------------
__global__ __launch_bounds__(256) void kA(const float* __restrict__ feat,
                                          const float* __restrict__ Wp,
                                          const float* __restrict__ bp) {
    int n = blockIdx.x;
    __shared__ float fsh[D_ * L_];
    const float* f = feat + (size_t)n * D_ * L_;
    for (int i = threadIdx.x; i < D_ * L_; i += 256) fsh[i] = f[i];
    __syncthreads();
    for (int h = threadIdx.x; h < H_; h += 256) {
        float acc[L_];
        float bb = bp[h];
#pragma unroll
        for (int l = 0; l < L_; l++) acc[l] = bb;
        for (int d = 0; d < D_; d++) {
            float wv = Wp[d * H_ + h];
            const float* fr = &fsh[d * L_];
#pragma unroll
            for (int l = 0; l < L_; l++) acc[l] = fmaf(fr[l], wv, acc[l]);
        }
        float s = 0.0f;
        float* Ar = g_A + ((size_t)n * H_ + h) * L_;
#pragma unroll
        for (int l = 0; l < L_; l++) {
            Ar[l] = acc[l];
            gb_At[((size_t)n * L_ + l) * H_ + h] = __float2bfloat16_rn(acc[l]);
            s += acc[l];
        }
        float h0 = s * (1.0f / 16.0f);
        g_h0[n * H_ + h] = h0;
        gb_hbuf[0][n * H_ + h] = __float2bfloat16_rn(h0);
    }
}

// ================= BF16 mma GEMM core (2-stage, static smem) =================
__device__ __forceinline__ void ldsm4(uint32_t a, unsigned& r0, unsigned& r1,
                                      unsigned& r2, unsigned& r3) {
    asm volatile("ldmatrix.sync.aligned.m8n8.x4.shared.b16 {%0,%1,%2,%3}, [%4];"
                 : "=r"(r0), "=r"(r1), "=r"(r2), "=r"(r3) : "r"(a));
}
__device__ __forceinline__ void ldsm4t(uint32_t a, unsigned& r0, unsigned& r1,
                                       unsigned& r2, unsigned& r3) {
    asm volatile("ldmatrix.sync.aligned.m8n8.x4.trans.shared.b16 {%0,%1,%2,%3}, [%4];"
                 : "=r"(r0), "=r"(r1), "=r"(r2), "=r"(r3) : "r"(a));
}
__device__ __forceinline__ void bmma(float* c, const unsigned* a,
                                     unsigned b0, unsigned b1) {
    asm volatile("mma.sync.aligned.m16n8k16.row.col.f32.bf16.bf16.f32 "
                 "{%0,%1,%2,%3},{%4,%5,%6,%7},{%8,%9},{%0,%1,%2,%3};"
                 : "+f"(c[0]), "+f"(c[1]), "+f"(c[2]), "+f"(c[3])
                 : "r"(a[0]), "r"(a[1]), "r"(a[2]), "r"(a[3]), "r"(b0), "r"(b1));
}
__device__ __forceinline__ void cpa16(uint32_t dst, const void* src) {
    asm volatile("cp.async.cg.shared.global [%0], [%1], 16;" ::"r"(dst), "l"(src));
}
__device__ __forceinline__ void cpa16z(uint32_t dst, const void* src, unsigned sz) {
    asm volatile("cp.async.cg.shared.global [%0], [%1], 16, %2;"
                 ::"r"(dst), "l"(src), "r"(sz));
}
__device__ __forceinline__ void cp_commit() { asm volatile("cp.async.commit_group;"); }
__device__ __forceinline__ void cp_wait2() { asm volatile("cp.async.wait_group 2;"); }
__device__ __forceinline__ void cp_wait1() { asm volatile("cp.async.wait_group 1;"); }
__device__ __forceinline__ void cp_wait0() { asm volatile("cp.async.wait_group 0;"); }

struct BfgLoader {
    const __nv_bfloat16 *a0, *a1, *b0, *b1;
    uint32_t aoff0, aoff1, boff0, boff1;
    size_t bstep;
    unsigned bsz;
    __device__ __forceinline__ void issue(int it, uint32_t dA, uint32_t dB) const {
        cpa16(dA + aoff0, a0 + it * 32);
        cpa16(dA + aoff1, a1 + it * 32);
        cpa16z(dB + boff0, b0 + (size_t)it * bstep, bsz);
        cpa16z(dB + boff1, b1 + (size_t)it * bstep, bsz);
    }
};

__device__ __forceinline__ void bfg_compute(uint32_t bA, uint32_t bB,
                                            int lane, int wm, int wn,
                                            float acc[2][8][4]) {
    const int l15 = lane & 15, l7 = lane & 7, lhi = lane >> 4;
    const int mA0 = wm * 32 + l15, mA1 = mA0 + 16;
    const uint32_t aR0 = (uint32_t)mA0 * 128, aR1 = (uint32_t)mA1 * 128;
    const int a70 = mA0 & 7, a71 = mA1 & 7;
    const uint32_t bRk = (uint32_t)l15 * 256;
#pragma unroll
    for (int ks = 0; ks < 2; ks++) {
        int c = ks * 2 + lhi;
        unsigned af0[4], af1[4];
        ldsm4(bA + aR0 + (uint32_t)(((c ^ a70) & 7) << 4),
              af0[0], af0[1], af0[2], af0[3]);
        ldsm4(bA + aR1 + (uint32_t)(((c ^ a71) & 7) << 4),
              af1[0], af1[1], af1[2], af1[3]);
#pragma unroll
        for (int p = 0; p < 4; p++) {
            unsigned bf0, bf1, bf2, bf3;
            int g = wn * 8 + p * 2 + lhi;
            ldsm4t(bB + (uint32_t)(ks * 16) * 256 + bRk + (uint32_t)((g ^ l7) << 4),
                   bf0, bf1, bf2, bf3);
            bmma(acc[0][2 * p],     af0, bf0, bf1);
            bmma(acc[0][2 * p + 1], af0, bf2, bf3);
            bmma(acc[1][2 * p],     af1, bf0, bf1);
            bmma(acc[1][2 * p + 1], af1, bf2, bf3);
        }
    }
}

__device__ __forceinline__ void bfg_run(const BfgLoader& ld, int nIter,
                                        uint32_t sA0, uint32_t sB0,
                                        int lane, int wm, int wn,
                                        float acc[2][8][4]) {
    ld.issue(0, sA0, sB0);
    cp_commit();
    for (int it = 0; it < nIter; it++) {
        uint32_t bA = sA0 + (uint32_t)(it & 1) * 16384;
        uint32_t bB = sB0 + (uint32_t)(it & 1) * 8192;
        if (it + 1 < nIter) {
            ld.issue(it + 1, sA0 + (uint32_t)((it + 1) & 1) * 16384,
                     sB0 + (uint32_t)((it + 1) & 1) * 8192);
            cp_commit();
            cp_wait1();
        } else {
            cp_wait0();
        }
        __syncthreads();
        bfg_compute(bA, bB, lane, wm, wn, acc);
        __syncthreads();
    }
}

struct BfgIdx {
    int tid, lane, wid, wm, wn, am, ag, bks, bg;
    uint32_t aoff0, aoff1, boff0, boff1;
    __device__ __forceinline__ BfgIdx() {
        tid = threadIdx.x; lane = tid & 31; wid = tid >> 5;
        wm = wid >> 1; wn = wid & 1;
        am = tid >> 2; ag = tid & 3;
        bks = tid >> 4; bg = tid & 15;
        aoff0 = (uint32_t)am * 128 + (uint32_t)(((ag ^ (am & 7)) & 7) << 4);
        aoff1 = aoff0 + 64 * 128;
        boff0 = (uint32_t)bks * 256 + (uint32_t)((bg ^ (bks & 7)) << 4);
        boff1 = boff0 + 16 * 256;
    }
};

#define BFG_SMEM                                                               \
    __shared__ __align__(16) char sAm[2][16384];                               \
    __shared__ __align__(16) char sBm[2][8192];                                \
    uint32_t sA0 = (uint32_t)__cvta_generic_to_shared(sAm);                    \
    uint32_t sB0 = (uint32_t)__cvta_generic_to_shared(sBm);

// ---- xproj = W_embed[cap] @ Wx + b ----
__global__ __launch_bounds__(256) void gemm_embed(const int* __restrict__ captions,
                                                  const float* __restrict__ bias) {
    int row0 = blockIdx.y * 128, col0 = blockIdx.x * 128;
    BFG_SMEM;
    BfgIdx ix;
    float acc[2][8][4] = {};
    int r0i = row0 + ix.am, r1i = r0i + 64;
    BfgLoader ld;
    ld.a0 = gb_Wemb + (size_t)captions[(r0i >> 5) * TCAP + (r0i & 31)] * WE_ + ix.ag * 8;
    ld.a1 = gb_Wemb + (size_t)captions[(r1i >> 5) * TCAP + (r1i & 31)] * WE_ + ix.ag * 8;
    ld.b0 = gb_Wx + (size_t)ix.bks * H4_ + col0 + ix.bg * 8;
    ld.b1 = ld.b0 + (size_t)16 * H4_;
    ld.aoff0 = ix.aoff0; ld.aoff1 = ix.aoff1; ld.boff0 = ix.boff0; ld.boff1 = ix.boff1;
    ld.bstep = (size_t)32 * H4_; ld.bsz = 16;
    bfg_run(ld, WE_ / 32, sA0, sB0, ix.lane, ix.wm, ix.wn, acc);
    int eg = ix.lane >> 2, ec = (ix.lane & 3) * 2;
#pragma unroll
    for (int mt = 0; mt < 2; mt++)
#pragma unroll
        for (int nt = 0; nt < 8; nt++) {
            int row = row0 + ix.wm * 32 + mt * 16 + eg;
            int col = col0 + ix.wn * 64 + nt * 8 + ec;
            float b0v = bias[col], b1v = bias[col + 1];
            *(float2*)&g_xproj[(size_t)row * H4_ + col] =
                make_float2(acc[mt][nt][0] + b0v, acc[mt][nt][1] + b1v);
            *(float2*)&g_xproj[(size_t)(row + 8) * H4_ + col] =
                make_float2(acc[mt][nt][2] + b0v, acc[mt][nt][3] + b1v);
        }
}

// ---- P = A^T @ Wattn, written bf16 block-major [blk][n][c32][l] ----
__global__ __launch_bounds__(256) void gemm_P() {
    int row0 = blockIdx.y * 128, col0 = blockIdx.x * 128;
    BFG_SMEM;
    BfgIdx ix;
    float acc[2][8][4] = {};
    BfgLoader ld;
    ld.a0 = gb_At + (size_t)(row0 + ix.am) * H_ + ix.ag * 8;
    ld.a1 = ld.a0 + (size_t)64 * H_;
    ld.b0 = gb_Wattn + (size_t)ix.bks * H4_ + col0 + ix.bg * 8;
    ld.b1 = ld.b0 + (size_t)16 * H4_;
    ld.aoff0 = ix.aoff0; ld.aoff1 = ix.aoff1; ld.boff0 = ix.boff0; ld.boff1 = ix.boff1;
    ld.bstep = (size_t)32 * H4_; ld.bsz = 16;
    bfg_run(ld, H_ / 32, sA0, sB0, ix.lane, ix.wm, ix.wn, acc);
    int eg = ix.lane >> 2, ec = (ix.lane & 3) * 2;
#pragma unroll
    for (int mt = 0; mt < 2; mt++)
#pragma unroll
        for (int nt = 0; nt < 8; nt++) {
            int row = row0 + ix.wm * 32 + mt * 16 + eg;        // = n*16 + l, l in 0..7
            int col = col0 + ix.wn * 64 + nt * 8 + ec;
            int n = row >> 4, l = row & 15;
            int gate = col >> 10, rem = col & 1023;
            int bblk = rem >> 3, c32 = gate * 8 + (rem & 7);
            size_t base = (((size_t)bblk * 128 + n) * 32 + c32) * 16 + l;
            gb_Pp[base]          = __float2bfloat16_rn(acc[mt][nt][0]);
            gb_Pp[base + 16]     = __float2bfloat16_rn(acc[mt][nt][1]);  // c32+1
            gb_Pp[base + 8]      = __float2bfloat16_rn(acc[mt][nt][2]);  // l+8
            gb_Pp[base + 16 + 8] = __float2bfloat16_rn(acc[mt][nt][3]);
        }
}

// ---- LSE merge helper ----
__device__ __forceinline__ void lsemerge(float& m, float& s, float om, float os) {
    float M = fmaxf(m, om);
    if (M == -INFINITY) { s = 0.0f; return; }
    float t1 = (m == -INFINITY) ? 0.0f : s * __expf(m - M);
    float t2 = (om == -INFINITY) ? 0.0f : os * __expf(om - M);
    m = M; s = t1 + t2;
}

// ---- scores = hn @ W_vocab + b : fused LSE partials + target harvest ----
__global__ __launch_bounds__(256) void gemm_vocab(const float* __restrict__ bv,
                                                  const int* __restrict__ captions) {
    int row0 = blockIdx.y * 128, col0 = blockIdx.x * 128;
    BFG_SMEM;
    BfgIdx ix;
    float acc[2][8][4] = {};
    BfgLoader ld;
    ld.a0 = gb_hn + (size_t)(row0 + ix.am) * H_ + ix.ag * 8;
    ld.a1 = ld.a0 + (size_t)64 * H_;
    int bcol = col0 + ix.bg * 8;
    ld.bsz = (bcol + 8 <= V_) ? 16u : 0u;
    ld.b0 = gb_Wv + (size_t)ix.bks * V_ + ((bcol + 8 <= V_) ? bcol : 0);
    ld.b1 = ld.b0 + (size_t)16 * V_;
    ld.aoff0 = ix.aoff0; ld.aoff1 = ix.aoff1; ld.boff0 = ix.boff0; ld.boff1 = ix.boff1;
    ld.bstep = (size_t)32 * V_;
    bfg_run(ld, H_ / 32, sA0, sB0, ix.lane, ix.wm, ix.wn, acc);
    int eg = ix.lane >> 2, ec = (ix.lane & 3) * 2;
    float bvr[8][2];
#pragma unroll
    for (int nt = 0; nt < 8; nt++) {
        int col = col0 + ix.wn * 64 + nt * 8 + ec;
        bvr[nt][0] = (col < V_) ? bv[col] : 0.0f;
        bvr[nt][1] = (col + 1 < V_) ? bv[col + 1] : 0.0f;
    }
#pragma unroll
    for (int mt = 0; mt < 2; mt++)
#pragma unroll
        for (int qn = 0; qn < 2; qn++) {
            int row = row0 + ix.wm * 32 + mt * 16 + eg + 8 * qn;
            int tgt = captions[(row >> 5) * TCAP + (row & 31) + 1];
            float vals[16];
            float m = -INFINITY;
#pragma unroll
            for (int nt = 0; nt < 8; nt++)
#pragma unroll
                for (int j = 0; j < 2; j++) {
                    int col = col0 + ix.wn * 64 + nt * 8 + ec + j;
                    float v = acc[mt][nt][2 * qn + j] + bvr[nt][j];
                    vals[nt * 2 + j] = v;
                    if (col < V_) {
                        m = fmaxf(m, v);
                        if (col == tgt) g_stgt[row] = v;
                    }
                }
            float s = 0.0f;
#pragma unroll
            for (int nt = 0; nt < 8; nt++)
#pragma unroll
                for (int j = 0; j < 2; j++) {
                    int col = col0 + ix.wn * 64 + nt * 8 + ec + j;
                    if (col < V_)
                        s += __expf(vals[nt * 2 + j] - m);
                }
#pragma unroll
            for (int off = 1; off <= 2; off <<= 1) {
                float om = __shfl_xor_sync(0xffffffffu, m, off);
                float os = __shfl_xor_sync(0xffffffffu, s, off);
                lsemerge(m, s, om, os);
            }
            if ((ix.lane & 3) == 0)
                g_lsep[(size_t)row * NLSE + blockIdx.x * 2 + ix.wn] = make_float2(m, s);
        }
}

// ---- loss: merge LSE partials, nll on targets ----
__global__ __launch_bounds__(256) void loss_f(const int* __restrict__ captions,
                                              float* __restrict__ out) {
    int r = blockIdx.x * 32 + (threadIdx.x >> 3);
    int j8 = threadIdx.x & 7;
    float m = -INFINITY, s = 0.0f;
    for (int j = j8; j < NLSE; j += 8) {
        float2 p = g_lsep[(size_t)r * NLSE + j];
        lsemerge(m, s, p.x, p.y);
    }
#pragma unroll
    for (int off = 1; off <= 4; off <<= 1) {
        float om = __shfl_xor_sync(0xffffffffu, m, off);
        float os = __shfl_xor_sync(0xffffffffu, s, off);
        lsemerge(m, s, om, os);
    }
    if (j8 == 0) {
        int n = r >> 5, t = r & 31;
        int tgt = captions[n * TCAP + t + 1];
        if (tgt != 0) {
            float nll = logf(s) + m - g_stgt[r];
            atomicAdd(out, nll * (1.0f / (float)N_));
        }
    }
}

// ================= persistent RNN loop =================
// smem: Wh 81920 | h 3x32768 | zx 16384 | ws 8192 | red 512
#define SM_WH   0
#define SM_H    81920
#define SM_ZX   180224
#define SM_WS   196608
#define SM_RED  204800
#define SM_TOT  205312

// contention-free flag barrier: 1 flag / 32B sector
__device__ __forceinline__ void gbar(unsigned& gen) {
    gen++;
    __syncthreads();
    __threadfence();
    if (threadIdx.x == 0) __stcg(&g_flags[blockIdx.x * 8], gen);
    if (threadIdx.x < 32) {
        for (;;) {
            unsigned v0 = __ldcg(&g_flags[threadIdx.x * 8]);
            unsigned v1 = __ldcg(&g_flags[(threadIdx.x + 32) * 8]);
            unsigned v2 = __ldcg(&g_flags[(threadIdx.x + 64) * 8]);
            unsigned v3 = __ldcg(&g_flags[(threadIdx.x + 96) * 8]);
            if (v0 >= gen && v1 >= gen && v2 >= gen && v3 >= gen) break;
        }
    }
    __threadfence();
    __syncthreads();
}

__global__ __launch_bounds__(256, 1) void rnn_loop() {
    const int tid = threadIdx.x, bid = blockIdx.x;
    const int lane = tid & 31, w = tid >> 5;
    const int l15 = lane & 15, lhi = lane >> 4;
    uint32_t smb = (uint32_t)__cvta_generic_to_shared(sm_raw);
    uint32_t whb = smb + SM_WH, hb = smb + SM_H;
    float* sZX = (float*)(sm_raw + SM_ZX);
    float* sWs = (float*)(sm_raw + SM_WS);
    float* sRed = (float*)(sm_raw + SM_RED);

    for (int i = tid; i < 4096; i += 256) {
        int k = i >> 2, g = i & 3;
        cpa16(whb + (uint32_t)k * 80 + g * 16,
              gb_Wh + (size_t)k * H4_ + g * 1024 + bid * 8);
    }
    cp_commit(); cp_wait0();
    __syncthreads();

    float hreg[2][2], creg[2][2];
#pragma unroll
    for (int qn = 0; qn < 2; qn++) {
        int n = 16 * w + (lane >> 2) + 8 * qn;
#pragma unroll
        for (int qh = 0; qh < 2; qh++) {
            float hv = g_h0[n * H_ + bid * 8 + (lane & 3) * 2 + qh];
            hreg[qn][qh] = hv; creg[qn][qh] = hv;
        }
    }

    unsigned gen = 0;

    auto issue_h = [&](const __nv_bfloat16* hsrc, int kc, uint32_t dst) {
#pragma unroll
        for (int i = 0; i < 8; i++) {
            int id = tid + 256 * i;
            int n = id >> 4, g = id & 15;
            uint32_t off = (uint32_t)n * 256 + ((g & 8) << 4) + ((((g & 7) ^ (n & 7))) << 4);
            cpa16(dst + off, hsrc + (size_t)n * H_ + kc * 128 + g * 8);
        }
        cp_commit();
    };

    auto score_partial = [&]() {
        float sc0[16], sc1[16];
#pragma unroll
        for (int l = 0; l < 16; l++) { sc0[l] = 0.f; sc1[l] = 0.f; }
#pragma unroll
        for (int qn = 0; qn < 2; qn++) {
            float* sc = qn ? sc1 : sc0;
            int n = 16 * w + (lane >> 2) + 8 * qn;
#pragma unroll
            for (int qh = 0; qh < 2; qh++) {
                int hidx = bid * 8 + (lane & 3) * 2 + qh;
                float h = hreg[qn][qh];
                const float4* Ar = (const float4*)&g_A[((size_t)n * H_ + hidx) * L_];
#pragma unroll
                for (int j = 0; j < 4; j++) {
                    float4 a = Ar[j];
                    sc[4 * j + 0] += h * a.x; sc[4 * j + 1] += h * a.y;
                    sc[4 * j + 2] += h * a.z; sc[4 * j + 3] += h * a.w;
                }
            }
        }
#pragma unroll
        for (int off = 1; off <= 2; off <<= 1)
#pragma unroll
            for (int l = 0; l < 16; l++) {
                sc0[l] += __shfl_xor_sync(0xffffffffu, sc0[l], off);
                sc1[l] += __shfl_xor_sync(0xffffffffu, sc1[l], off);
            }
        if ((lane & 3) == 0) {
            int n0 = 16 * w + (lane >> 2);
            float4* d0 = (float4*)&g_ps[((size_t)bid * 128 + n0) * 16];
            d0[0] = make_float4(sc0[0], sc0[1], sc0[2], sc0[3]);
            d0[1] = make_float4(sc0[4], sc0[5], sc0[6], sc0[7]);
            d0[2] = make_float4(sc0[8], sc0[9], sc0[10], sc0[11]);
            d0[3] = make_float4(sc0[12], sc0[13], sc0[14], sc0[15]);
            float4* d1 = (float4*)&g_ps[((size_t)bid * 128 + n0 + 8) * 16];
            d1[0] = make_float4(sc1[0], sc1[1], sc1[2], sc1[3]);
            d1[1] = make_float4(sc1[4], sc1[5], sc1[6], sc1[7]);
            d1[2] = make_float4(sc1[8], sc1[9], sc1[10], sc1[11]);
            d1[3] = make_float4(sc1[12], sc1[13], sc1[14], sc1[15]);
        }
    };

    auto wreduce = [&]() {
        if (tid < 128) {
            const float4* p = (const float4*)&g_ps[((size_t)tid * 128 + bid) * 16];
            float4 v0 = __ldcg(p), v1 = __ldcg(p + 1), v2 = __ldcg(p + 2), v3 = __ldcg(p + 3);
            float v[16] = {v0.x, v0.y, v0.z, v0.w, v1.x, v1.y, v1.z, v1.w,
                           v2.x, v2.y, v2.z, v2.w, v3.x, v3.y, v3.z, v3.w};
#pragma unroll
            for (int off = 16; off >= 1; off >>= 1)
#pragma unroll
                for (int l = 0; l < 16; l++)
                    v[l] += __shfl_xor_sync(0xffffffffu, v[l], off);
            if ((tid & 31) == 0)
#pragma unroll
                for (int l = 0; l < 16; l++) sRed[(tid >> 5) * 16 + l] = v[l];
        }
        __syncthreads();
        if (tid == 0) {
            float sv[16];
            float mx = -INFINITY;
#pragma unroll
            for (int l = 0; l < 16; l++) {
                sv[l] = (sRed[l] + sRed[16 + l] + sRed[32 + l] + sRed[48 + l]) * 0.03125f;
                mx = fmaxf(mx, sv[l]);
            }
            float se = 0.0f;
#pragma unroll
            for (int l = 0; l < 16; l++) { sv[l] = __expf(sv[l] - mx); se += sv[l]; }
            float inv = 1.0f / se;
#pragma unroll
            for (int l = 0; l < 16; l++) g_w[bid * 16 + l] = sv[l] * inv;
        }
        __syncthreads();
    };

    // ---- pre-loop: weights for t=0 ----
    score_partial();
    gbar(gen);            // publishes h0-scores
    wreduce();            // g_w for t=0

    for (int t = 0; t < T_; t++) {
        const int cur = t & 1, nxt = cur ^ 1;
        const __nv_bfloat16* hsrc = gb_hbuf[cur];

        // ---- GEMM z = h @ Wh-slice, 3-deep chunk pipeline ----
        issue_h(hsrc, 0, hb);
        issue_h(hsrc, 1, hb + 32768);
        float acc[4][4] = {};
        for (int kc = 0; kc < 8; kc++) {
            int b = kc % 3;
            if (kc + 2 < 8) {
                issue_h(hsrc, kc + 2, hb + (uint32_t)((kc + 2) % 3) * 32768);
                cp_wait2();
            } else if (kc + 1 < 8) {
                cp_wait1();
            } else {
                cp_wait0();
            }
            __syncthreads();
            uint32_t hbase = hb + (uint32_t)b * 32768;
            int n_ld = 16 * w + l15;
#pragma unroll
            for (int k16 = 0; k16 < 8; k16++) {
                int cf = 2 * k16 + lhi;
                unsigned af[4];
                ldsm4(hbase + (uint32_t)n_ld * 256 + ((cf & 8) << 4) +
                          (uint32_t)(((cf & 7) ^ (n_ld & 7)) << 4),
                      af[0], af[1], af[2], af[3]);
                int kg = kc * 8 + k16;
                uint32_t brow = whb + (uint32_t)(kg * 16 + l15) * 80;
                unsigned b0, b1, b2, b3, b4, b5, b6, b7;
                ldsm4t(brow + (uint32_t)(lhi << 4), b0, b1, b2, b3);
                ldsm4t(brow + (uint32_t)((2 + lhi) << 4), b4, b5, b6, b7);
                bmma(acc[0], af, b0, b1);
                bmma(acc[1], af, b2, b3);
                bmma(acc[2], af, b4, b5);
                bmma(acc[3], af, b6, b7);
            }
            __syncthreads();
        }

        // ---- preload xproj into sZX (before the barrier) ----
        for (int v = tid; v < 4096; v += 256) {
            int n = v >> 5, c32 = v & 31;
            int gcol = (c32 >> 3) * 1024 + bid * 8 + (c32 & 7);
            sZX[v] = g_xproj[((size_t)(n * T_ + t)) * H4_ + gcol];
        }

        // ---- barrier publishes g_w from wreduce ----
        gbar(gen);

        // ---- zx += w . Pp (bf16, [n][c32][l] layout) ----
        for (int i = tid; i < 2048; i += 256) sWs[i] = __ldcg(&g_w[i]);
        __syncthreads();
        for (int v = tid; v < 4096; v += 256) {
            int n = v >> 5, c32 = v & 31;
            float a = sZX[v];
            const __nv_bfloat16* pp = &gb_Pp[(((size_t)bid * 128 + n) * 32 + c32) * 16];
            uint4 p0 = *(const uint4*)pp;
            uint4 p1 = *(const uint4*)(pp + 8);
            const float* wn_ = &sWs[n * 16];
            const __nv_bfloat162* h2a = (const __nv_bfloat162*)&p0;
            const __nv_bfloat162* h2b = (const __nv_bfloat162*)&p1;
#pragma unroll
            for (int j = 0; j < 4; j++) {
                float2 fa = __bfloat1622float2(h2a[j]);
                float2 fb = __bfloat1622float2(h2b[j]);
                a = fmaf(wn_[2 * j], fa.x, a);
                a = fmaf(wn_[2 * j + 1], fa.y, a);
                a = fmaf(wn_[8 + 2 * j], fb.x, a);
                a = fmaf(wn_[8 + 2 * j + 1], fb.y, a);
            }
            sZX[v] = a;
        }
        __syncthreads();

        // ---- gates ----
#pragma unroll
        for (int qn = 0; qn < 2; qn++) {
            int n = 16 * w + (lane >> 2) + 8 * qn;
#pragma unroll
            for (int qh = 0; qh < 2; qh++) {
                int hh = (lane & 3) * 2 + qh;
                int q = 2 * qn + qh;
                float zi = acc[0][q] + sZX[n * 32 + hh];
                float zf = acc[1][q] + sZX[n * 32 + 8 + hh];
                float zo = acc[2][q] + sZX[n * 32 + 16 + hh];
                float zg = acc[3][q] + sZX[n * 32 + 24 + hh];
                float c = sigfast(zf) * creg[qn][qh] + sigfast(zi) * tanhfast(zg);
                float hv = sigfast(zo) * tanhfast(c);
                creg[qn][qh] = c;
                hreg[qn][qh] = hv;
                __nv_bfloat16 hb16 = __float2bfloat16_rn(hv);
                gb_hbuf[nxt][n * H_ + bid * 8 + hh] = hb16;
                gb_hn[((size_t)n * T_ + t) * H_ + bid * 8 + hh] = hb16;
            }
        }

        // ---- scores + reduce for NEXT step (skipped on the last) ----
        if (t < T_ - 1) {
            score_partial();
            gbar(gen);        // publishes new h + partials
            wreduce();        // g_w for t+1
        }
    }
}

// ---------------- launch ----------------
extern "C" void kernel_launch(void* const* d_in, const int* in_sizes, int n_in,
                              void* d_out, int out_size) {
    const float* features = (const float*)d_in[0];
    const int*   captions = (const int*)d_in[1];
    const float* W_embed  = (const float*)d_in[2];
    const float* W_proj   = (const float*)d_in[3];
    const float* b_proj   = (const float*)d_in[4];
    const float* Wx       = (const float*)d_in[5];
    const float* Wh       = (const float*)d_in[6];
    const float* Wattn    = (const float*)d_in[7];
    const float* b        = (const float*)d_in[8];
    const float* W_vocab  = (const float*)d_in[9];
    const float* b_vocab  = (const float*)d_in[10];
    float* out = (float*)d_out;

    cudaFuncSetAttribute(rnn_loop, cudaFuncAttributeMaxDynamicSharedMemorySize, SM_TOT);

    combo_init<<<1, 256>>>(out);
    f2b_all<<<(R4 + 255) / 256, 256>>>(W_embed, Wx, Wh, Wattn, W_vocab);
    kA<<<N_, 256>>>(features, W_proj, b_proj);
    gemm_embed<<<dim3(H4_ / 128, (N_ * T_) / 128), 256>>>(captions, b);
    gemm_P<<<dim3(H4_ / 128, (N_ * L_) / 128), 256>>>();
    rnn_loop<<<NBLK, 256, SM_TOT>>>();
    gemm_vocab<<<dim3(NBX, (N_ * T_) / 128), 256>>>(b_vocab, captions);
    loss_f<<<(N_ * T_) / 32, 256>>>(captions, out);
}

// round 14
// speedup vs baseline: 5.1383x; 1.0367x over previous
#include <cuda_runtime.h>
#include <cuda_bf16.h>
#include <cstdint>
#include <math.h>

#define N_   128
#define T_   32
#define TCAP 33
#define D_   400
#define WE_  512
#define H_   1024
#define H4_  4096
#define V_   10000
#define L_   16
#define NBLK 128
#define NBX  79
#define NLSE (NBX * 2)

// ---------------- device scratch ----------------
__device__ float g_A[N_ * H_ * L_];                       // [n][h][l]
__device__ float g_h0[N_ * H_];
__device__ float g_xproj[(size_t)N_ * T_ * H4_];
__device__ float g_w[N_ * L_];
__device__ float2 g_lsep[(size_t)N_ * T_ * NLSE];
__device__ float g_stgt[N_ * T_];
__device__ __align__(128) unsigned g_flags[NBLK * 8];     // 1 flag / 32B sector

// bf16 operands
__device__ __nv_bfloat16 gb_Wemb[(size_t)V_ * WE_];
__device__ __nv_bfloat16 gb_Wx[(size_t)WE_ * H4_];
__device__ __nv_bfloat16 gb_Wh[(size_t)H_ * H4_];
__device__ __nv_bfloat16 gb_Wattn[(size_t)H_ * H4_];
__device__ __nv_bfloat16 gb_Wv[(size_t)H_ * V_];
__device__ __nv_bfloat16 gb_At[N_ * L_ * H_];
__device__ __nv_bfloat16 gb_hbuf[2][N_ * H_];
__device__ __nv_bfloat16 gb_hn[N_ * T_ * H_];
__device__ __nv_bfloat16 gb_Pp[(size_t)N_ * L_ * H4_];    // [blk][n][c32][l] bf16

extern __shared__ char sm_raw[];

// fast transcendentals (MUFU)
__device__ __forceinline__ float tanhfast(float x) {
    float y; asm("tanh.approx.f32 %0, %1;" : "=f"(y) : "f"(x)); return y;
}
__device__ __forceinline__ float sigfast(float x) {
    return fmaf(0.5f, tanhfast(0.5f * x), 0.5f);
}

// ---------------- combined init (out + flags) ----------------
__global__ void combo_init(float* out) {
    if (threadIdx.x == 0) out[0] = 0.0f;
    for (int i = threadIdx.x; i < NBLK * 8; i += 256) g_flags[i] = 0u;
}

// ---------------- all fp32 -> bf16 conversions in ONE kernel ----------------
#define R0 640000u
#define R1 (R0 + 262144u)
#define R2 (R1 + 524288u)
#define R3 (R2 + 524288u)
#define R4 (R3 + 1280000u)
__global__ __launch_bounds__(256) void f2b_all(const float* __restrict__ Wemb,
                                               const float* __restrict__ Wx,
                                               const float* __restrict__ Wh,
                                               const float* __restrict__ Wattn,
                                               const float* __restrict__ Wv) {
    unsigned i8 = blockIdx.x * 256 + threadIdx.x;
    const float* s; __nv_bfloat16* d; unsigned base;
    if (i8 < R0)      { s = Wemb;  d = gb_Wemb;  base = 0; }
    else if (i8 < R1) { s = Wx;    d = gb_Wx;    base = R0; }
    else if (i8 < R2) { s = Wh;    d = gb_Wh;    base = R1; }
    else if (i8 < R3) { s = Wattn; d = gb_Wattn; base = R2; }
    else if (i8 < R4) { s = Wv;    d = gb_Wv;    base = R3; }
    else return;
    size_t off = (size_t)(i8 - base) * 8;
    float4 v0 = *(const float4*)(s + off);
    float4 v1 = *(const float4*)(s + off + 4);
    union { __nv_bfloat162 h2[4]; uint4 u; } o;
    o.h2[0] = __floats2bfloat162_rn(v0.x, v0.y);
    o.h2[1] = __floats2bfloat162_rn(v0.z, v0.w);
    o.h2[2] = __floats2bfloat162_rn(v1.x, v1.y);
    o.h2[3] = __floats2bfloat162_rn(v1.z, v1.w);
    *(uint4*)(d + off) = o.u;
}

// ---------------- A_flat + A^T + h0 ----------------
__global__ __launch_bounds__(256) void kA(const float* __restrict__ feat,
                                          const float* __restrict__ Wp,
                                          const float* __restrict__ bp) {
    int n = blockIdx.x;
    __shared__ float fsh[D_ * L_];
    const float* f = feat + (size_t)n * D_ * L_;
    for (int i = threadIdx.x; i < D_ * L_; i += 256) fsh[i] = f[i];
    __syncthreads();
    for (int h = threadIdx.x; h < H_; h += 256) {
        float acc[L_];
        float bb = bp[h];
#pragma unroll
        for (int l = 0; l < L_; l++) acc[l] = bb;
        for (int d = 0; d < D_; d++) {
            float wv = Wp[d * H_ + h];
            const float* fr = &fsh[d * L_];
#pragma unroll
            for (int l = 0; l < L_; l++) acc[l] = fmaf(fr[l], wv, acc[l]);
        }
        float s = 0.0f;
        float* Ar = g_A + ((size_t)n * H_ + h) * L_;
#pragma unroll
        for (int l = 0; l < L_; l++) {
            Ar[l] = acc[l];
            gb_At[((size_t)n * L_ + l) * H_ + h] = __float2bfloat16_rn(acc[l]);
            s += acc[l];
        }
        float h0 = s * (1.0f / 16.0f);
        g_h0[n * H_ + h] = h0;
        gb_hbuf[0][n * H_ + h] = __float2bfloat16_rn(h0);
    }
}

// ================= BF16 mma GEMM core (2-stage, static smem) =================
__device__ __forceinline__ void ldsm4(uint32_t a, unsigned& r0, unsigned& r1,
                                      unsigned& r2, unsigned& r3) {
    asm volatile("ldmatrix.sync.aligned.m8n8.x4.shared.b16 {%0,%1,%2,%3}, [%4];"
                 : "=r"(r0), "=r"(r1), "=r"(r2), "=r"(r3) : "r"(a));
}
__device__ __forceinline__ void ldsm4t(uint32_t a, unsigned& r0, unsigned& r1,
                                       unsigned& r2, unsigned& r3) {
    asm volatile("ldmatrix.sync.aligned.m8n8.x4.trans.shared.b16 {%0,%1,%2,%3}, [%4];"
                 : "=r"(r0), "=r"(r1), "=r"(r2), "=r"(r3) : "r"(a));
}
__device__ __forceinline__ void bmma(float* c, const unsigned* a,
                                     unsigned b0, unsigned b1) {
    asm volatile("mma.sync.aligned.m16n8k16.row.col.f32.bf16.bf16.f32 "
                 "{%0,%1,%2,%3},{%4,%5,%6,%7},{%8,%9},{%0,%1,%2,%3};"
                 : "+f"(c[0]), "+f"(c[1]), "+f"(c[2]), "+f"(c[3])
                 : "r"(a[0]), "r"(a[1]), "r"(a[2]), "r"(a[3]), "r"(b0), "r"(b1));
}
__device__ __forceinline__ void cpa16(uint32_t dst, const void* src) {
    asm volatile("cp.async.cg.shared.global [%0], [%1], 16;" ::"r"(dst), "l"(src));
}
__device__ __forceinline__ void cpa16z(uint32_t dst, const void* src, unsigned sz) {
    asm volatile("cp.async.cg.shared.global [%0], [%1], 16, %2;"
                 ::"r"(dst), "l"(src), "r"(sz));
}
__device__ __forceinline__ void cp_commit() { asm volatile("cp.async.commit_group;"); }
__device__ __forceinline__ void cp_wait2() { asm volatile("cp.async.wait_group 2;"); }
__device__ __forceinline__ void cp_wait1() { asm volatile("cp.async.wait_group 1;"); }
__device__ __forceinline__ void cp_wait0() { asm volatile("cp.async.wait_group 0;"); }

struct BfgLoader {
    const __nv_bfloat16 *a0, *a1, *b0, *b1;
    uint32_t aoff0, aoff1, boff0, boff1;
    size_t bstep;
    unsigned bsz;
    __device__ __forceinline__ void issue(int it, uint32_t dA, uint32_t dB) const {
        cpa16(dA + aoff0, a0 + it * 32);
        cpa16(dA + aoff1, a1 + it * 32);
        cpa16z(dB + boff0, b0 + (size_t)it * bstep, bsz);
        cpa16z(dB + boff1, b1 + (size_t)it * bstep, bsz);
    }
};

__device__ __forceinline__ void bfg_compute(uint32_t bA, uint32_t bB,
                                            int lane, int wm, int wn,
                                            float acc[2][8][4]) {
    const int l15 = lane & 15, l7 = lane & 7, lhi = lane >> 4;
    const int mA0 = wm * 32 + l15, mA1 = mA0 + 16;
    const uint32_t aR0 = (uint32_t)mA0 * 128, aR1 = (uint32_t)mA1 * 128;
    const int a70 = mA0 & 7, a71 = mA1 & 7;
    const uint32_t bRk = (uint32_t)l15 * 256;
#pragma unroll
    for (int ks = 0; ks < 2; ks++) {
        int c = ks * 2 + lhi;
        unsigned af0[4], af1[4];
        ldsm4(bA + aR0 + (uint32_t)(((c ^ a70) & 7) << 4),
              af0[0], af0[1], af0[2], af0[3]);
        ldsm4(bA + aR1 + (uint32_t)(((c ^ a71) & 7) << 4),
              af1[0], af1[1], af1[2], af1[3]);
#pragma unroll
        for (int p = 0; p < 4; p++) {
            unsigned bf0, bf1, bf2, bf3;
            int g = wn * 8 + p * 2 + lhi;
            ldsm4t(bB + (uint32_t)(ks * 16) * 256 + bRk + (uint32_t)((g ^ l7) << 4),
                   bf0, bf1, bf2, bf3);
            bmma(acc[0][2 * p],     af0, bf0, bf1);
            bmma(acc[0][2 * p + 1], af0, bf2, bf3);
            bmma(acc[1][2 * p],     af1, bf0, bf1);
            bmma(acc[1][2 * p + 1], af1, bf2, bf3);
        }
    }
}

__device__ __forceinline__ void bfg_run(const BfgLoader& ld, int nIter,
                                        uint32_t sA0, uint32_t sB0,
                                        int lane, int wm, int wn,
                                        float acc[2][8][4]) {
    ld.issue(0, sA0, sB0);
    cp_commit();
    for (int it = 0; it < nIter; it++) {
        uint32_t bA = sA0 + (uint32_t)(it & 1) * 16384;
        uint32_t bB = sB0 + (uint32_t)(it & 1) * 8192;
        if (it + 1 < nIter) {
            ld.issue(it + 1, sA0 + (uint32_t)((it + 1) & 1) * 16384,
                     sB0 + (uint32_t)((it + 1) & 1) * 8192);
            cp_commit();
            cp_wait1();
        } else {
            cp_wait0();
        }
        __syncthreads();
        bfg_compute(bA, bB, lane, wm, wn, acc);
        __syncthreads();
    }
}

struct BfgIdx {
    int tid, lane, wid, wm, wn, am, ag, bks, bg;
    uint32_t aoff0, aoff1, boff0, boff1;
    __device__ __forceinline__ BfgIdx() {
        tid = threadIdx.x; lane = tid & 31; wid = tid >> 5;
        wm = wid >> 1; wn = wid & 1;
        am = tid >> 2; ag = tid & 3;
        bks = tid >> 4; bg = tid & 15;
        aoff0 = (uint32_t)am * 128 + (uint32_t)(((ag ^ (am & 7)) & 7) << 4);
        aoff1 = aoff0 + 64 * 128;
        boff0 = (uint32_t)bks * 256 + (uint32_t)((bg ^ (bks & 7)) << 4);
        boff1 = boff0 + 16 * 256;
    }
};

#define BFG_SMEM                                                               \
    __shared__ __align__(16) char sAm[2][16384];                               \
    __shared__ __align__(16) char sBm[2][8192];                                \
    uint32_t sA0 = (uint32_t)__cvta_generic_to_shared(sAm);                    \
    uint32_t sB0 = (uint32_t)__cvta_generic_to_shared(sBm);

// ---- xproj = W_embed[cap] @ Wx + b ----
__global__ __launch_bounds__(256) void gemm_embed(const int* __restrict__ captions,
                                                  const float* __restrict__ bias) {
    int row0 = blockIdx.y * 128, col0 = blockIdx.x * 128;
    BFG_SMEM;
    BfgIdx ix;
    float acc[2][8][4] = {};
    int r0i = row0 + ix.am, r1i = r0i + 64;
    BfgLoader ld;
    ld.a0 = gb_Wemb + (size_t)captions[(r0i >> 5) * TCAP + (r0i & 31)] * WE_ + ix.ag * 8;
    ld.a1 = gb_Wemb + (size_t)captions[(r1i >> 5) * TCAP + (r1i & 31)] * WE_ + ix.ag * 8;
    ld.b0 = gb_Wx + (size_t)ix.bks * H4_ + col0 + ix.bg * 8;
    ld.b1 = ld.b0 + (size_t)16 * H4_;
    ld.aoff0 = ix.aoff0; ld.aoff1 = ix.aoff1; ld.boff0 = ix.boff0; ld.boff1 = ix.boff1;
    ld.bstep = (size_t)32 * H4_; ld.bsz = 16;
    bfg_run(ld, WE_ / 32, sA0, sB0, ix.lane, ix.wm, ix.wn, acc);
    int eg = ix.lane >> 2, ec = (ix.lane & 3) * 2;
#pragma unroll
    for (int mt = 0; mt < 2; mt++)
#pragma unroll
        for (int nt = 0; nt < 8; nt++) {
            int row = row0 + ix.wm * 32 + mt * 16 + eg;
            int col = col0 + ix.wn * 64 + nt * 8 + ec;
            float b0v = bias[col], b1v = bias[col + 1];
            *(float2*)&g_xproj[(size_t)row * H4_ + col] =
                make_float2(acc[mt][nt][0] + b0v, acc[mt][nt][1] + b1v);
            *(float2*)&g_xproj[(size_t)(row + 8) * H4_ + col] =
                make_float2(acc[mt][nt][2] + b0v, acc[mt][nt][3] + b1v);
        }
}

// ---- P = A^T @ Wattn, written bf16 block-major [blk][n][c32][l] ----
__global__ __launch_bounds__(256) void gemm_P() {
    int row0 = blockIdx.y * 128, col0 = blockIdx.x * 128;
    BFG_SMEM;
    BfgIdx ix;
    float acc[2][8][4] = {};
    BfgLoader ld;
    ld.a0 = gb_At + (size_t)(row0 + ix.am) * H_ + ix.ag * 8;
    ld.a1 = ld.a0 + (size_t)64 * H_;
    ld.b0 = gb_Wattn + (size_t)ix.bks * H4_ + col0 + ix.bg * 8;
    ld.b1 = ld.b0 + (size_t)16 * H4_;
    ld.aoff0 = ix.aoff0; ld.aoff1 = ix.aoff1; ld.boff0 = ix.boff0; ld.boff1 = ix.boff1;
    ld.bstep = (size_t)32 * H4_; ld.bsz = 16;
    bfg_run(ld, H_ / 32, sA0, sB0, ix.lane, ix.wm, ix.wn, acc);
    int eg = ix.lane >> 2, ec = (ix.lane & 3) * 2;
#pragma unroll
    for (int mt = 0; mt < 2; mt++)
#pragma unroll
        for (int nt = 0; nt < 8; nt++) {
            int row = row0 + ix.wm * 32 + mt * 16 + eg;        // = n*16 + l, l in 0..7
            int col = col0 + ix.wn * 64 + nt * 8 + ec;
            int n = row >> 4, l = row & 15;
            int gate = col >> 10, rem = col & 1023;
            int bblk = rem >> 3, c32 = gate * 8 + (rem & 7);
            size_t base = (((size_t)bblk * 128 + n) * 32 + c32) * 16 + l;
            gb_Pp[base]          = __float2bfloat16_rn(acc[mt][nt][0]);
            gb_Pp[base + 16]     = __float2bfloat16_rn(acc[mt][nt][1]);  // c32+1
            gb_Pp[base + 8]      = __float2bfloat16_rn(acc[mt][nt][2]);  // l+8
            gb_Pp[base + 16 + 8] = __float2bfloat16_rn(acc[mt][nt][3]);
        }
}

// ---- LSE merge helper ----
__device__ __forceinline__ void lsemerge(float& m, float& s, float om, float os) {
    float M = fmaxf(m, om);
    if (M == -INFINITY) { s = 0.0f; return; }
    float t1 = (m == -INFINITY) ? 0.0f : s * __expf(m - M);
    float t2 = (om == -INFINITY) ? 0.0f : os * __expf(om - M);
    m = M; s = t1 + t2;
}

// ---- scores = hn @ W_vocab + b : fused LSE partials + target harvest ----
__global__ __launch_bounds__(256) void gemm_vocab(const float* __restrict__ bv,
                                                  const int* __restrict__ captions) {
    int row0 = blockIdx.y * 128, col0 = blockIdx.x * 128;
    BFG_SMEM;
    BfgIdx ix;
    float acc[2][8][4] = {};
    BfgLoader ld;
    ld.a0 = gb_hn + (size_t)(row0 + ix.am) * H_ + ix.ag * 8;
    ld.a1 = ld.a0 + (size_t)64 * H_;
    int bcol = col0 + ix.bg * 8;
    ld.bsz = (bcol + 8 <= V_) ? 16u : 0u;
    ld.b0 = gb_Wv + (size_t)ix.bks * V_ + ((bcol + 8 <= V_) ? bcol : 0);
    ld.b1 = ld.b0 + (size_t)16 * V_;
    ld.aoff0 = ix.aoff0; ld.aoff1 = ix.aoff1; ld.boff0 = ix.boff0; ld.boff1 = ix.boff1;
    ld.bstep = (size_t)32 * V_;
    bfg_run(ld, H_ / 32, sA0, sB0, ix.lane, ix.wm, ix.wn, acc);
    int eg = ix.lane >> 2, ec = (ix.lane & 3) * 2;
    float bvr[8][2];
#pragma unroll
    for (int nt = 0; nt < 8; nt++) {
        int col = col0 + ix.wn * 64 + nt * 8 + ec;
        bvr[nt][0] = (col < V_) ? bv[col] : 0.0f;
        bvr[nt][1] = (col + 1 < V_) ? bv[col + 1] : 0.0f;
    }
#pragma unroll
    for (int mt = 0; mt < 2; mt++)
#pragma unroll
        for (int qn = 0; qn < 2; qn++) {
            int row = row0 + ix.wm * 32 + mt * 16 + eg + 8 * qn;
            int tgt = captions[(row >> 5) * TCAP + (row & 31) + 1];
            float vals[16];
            float m = -INFINITY;
#pragma unroll
            for (int nt = 0; nt < 8; nt++)
#pragma unroll
                for (int j = 0; j < 2; j++) {
                    int col = col0 + ix.wn * 64 + nt * 8 + ec + j;
                    float v = acc[mt][nt][2 * qn + j] + bvr[nt][j];
                    vals[nt * 2 + j] = v;
                    if (col < V_) {
                        m = fmaxf(m, v);
                        if (col == tgt) g_stgt[row] = v;
                    }
                }
            float s = 0.0f;
#pragma unroll
            for (int nt = 0; nt < 8; nt++)
#pragma unroll
                for (int j = 0; j < 2; j++) {
                    int col = col0 + ix.wn * 64 + nt * 8 + ec + j;
                    if (col < V_)
                        s += __expf(vals[nt * 2 + j] - m);
                }
#pragma unroll
            for (int off = 1; off <= 2; off <<= 1) {
                float om = __shfl_xor_sync(0xffffffffu, m, off);
                float os = __shfl_xor_sync(0xffffffffu, s, off);
                lsemerge(m, s, om, os);
            }
            if ((ix.lane & 3) == 0)
                g_lsep[(size_t)row * NLSE + blockIdx.x * 2 + ix.wn] = make_float2(m, s);
        }
}

// ---- loss: merge LSE partials, nll on targets ----
__global__ __launch_bounds__(256) void loss_f(const int* __restrict__ captions,
                                              float* __restrict__ out) {
    int r = blockIdx.x * 32 + (threadIdx.x >> 3);
    int j8 = threadIdx.x & 7;
    float m = -INFINITY, s = 0.0f;
    for (int j = j8; j < NLSE; j += 8) {
        float2 p = g_lsep[(size_t)r * NLSE + j];
        lsemerge(m, s, p.x, p.y);
    }
#pragma unroll
    for (int off = 1; off <= 4; off <<= 1) {
        float om = __shfl_xor_sync(0xffffffffu, m, off);
        float os = __shfl_xor_sync(0xffffffffu, s, off);
        lsemerge(m, s, om, os);
    }
    if (j8 == 0) {
        int n = r >> 5, t = r & 31;
        int tgt = captions[n * TCAP + t + 1];
        if (tgt != 0) {
            float nll = logf(s) + m - g_stgt[r];
            atomicAdd(out, nll * (1.0f / (float)N_));
        }
    }
}

// ================= persistent RNN loop =================
// smem: Wh 81920 | h 3x32768 | zx 16384 | ws 8192 | red 1536
#define SM_WH   0
#define SM_H    81920
#define SM_ZX   180224
#define SM_WS   196608
#define SM_RED  204800
#define SM_TOT  206336

// contention-free flag barrier: 1 flag / 32B sector
__device__ __forceinline__ void gbar(unsigned& gen) {
    gen++;
    __syncthreads();
    __threadfence();
    if (threadIdx.x == 0) __stcg(&g_flags[blockIdx.x * 8], gen);
    if (threadIdx.x < 32) {
        for (;;) {
            unsigned v0 = __ldcg(&g_flags[threadIdx.x * 8]);
            unsigned v1 = __ldcg(&g_flags[(threadIdx.x + 32) * 8]);
            unsigned v2 = __ldcg(&g_flags[(threadIdx.x + 64) * 8]);
            unsigned v3 = __ldcg(&g_flags[(threadIdx.x + 96) * 8]);
            if (v0 >= gen && v1 >= gen && v2 >= gen && v3 >= gen) break;
        }
    }
    __threadfence();
    __syncthreads();
}

__global__ __launch_bounds__(256, 1) void rnn_loop() {
    const int tid = threadIdx.x, bid = blockIdx.x;
    const int lane = tid & 31, w = tid >> 5;
    const int l15 = lane & 15, lhi = lane >> 4;
    uint32_t smb = (uint32_t)__cvta_generic_to_shared(sm_raw);
    uint32_t whb = smb + SM_WH, hb = smb + SM_H;
    float* sZX = (float*)(sm_raw + SM_ZX);
    float* sWs = (float*)(sm_raw + SM_WS);
    float* sRed = (float*)(sm_raw + SM_RED);

    for (int i = tid; i < 4096; i += 256) {
        int k = i >> 2, g = i & 3;
        cpa16(whb + (uint32_t)k * 80 + g * 16,
              gb_Wh + (size_t)k * H4_ + g * 1024 + bid * 8);
    }
    cp_commit(); cp_wait0();
    __syncthreads();

    float creg[2][2];
#pragma unroll
    for (int qn = 0; qn < 2; qn++) {
        int n = 16 * w + (lane >> 2) + 8 * qn;
#pragma unroll
        for (int qh = 0; qh < 2; qh++)
            creg[qn][qh] = g_h0[n * H_ + bid * 8 + (lane & 3) * 2 + qh];
    }

    unsigned gen = 0;

    // score indexing for sample n == bid
    const int sc_part = tid >> 4;         // 0..15 : which 8-dim slice of the chunk
    const int sc_l = tid & 15;            // which attention location l
    const uint32_t sc_soff = (uint32_t)bid * 256 + (uint32_t)((sc_part & 8) << 4) +
                             (uint32_t)(((sc_part & 7) ^ (bid & 7)) << 4);

    auto issue_h = [&](const __nv_bfloat16* hsrc, int kc, uint32_t dst) {
#pragma unroll
        for (int i = 0; i < 8; i++) {
            int id = tid + 256 * i;
            int n = id >> 4, g = id & 15;
            uint32_t off = (uint32_t)n * 256 + ((g & 8) << 4) + ((((g & 7) ^ (n & 7))) << 4);
            cpa16(dst + off, hsrc + (size_t)n * H_ + kc * 128 + g * 8);
        }
        cp_commit();
    };

    for (int t = 0; t < T_; t++) {
        const int cur = t & 1, nxt = cur ^ 1;
        const __nv_bfloat16* hsrc = gb_hbuf[cur];

        // ---- GEMM z = h @ Wh-slice + in-stream attention score for n=bid ----
        issue_h(hsrc, 0, hb);
        issue_h(hsrc, 1, hb + 32768);
        float acc[4][4] = {};
        float scacc = 0.0f;
        for (int kc = 0; kc < 8; kc++) {
            int b = kc % 3;
            if (kc + 2 < 8) {
                issue_h(hsrc, kc + 2, hb + (uint32_t)((kc + 2) % 3) * 32768);
                cp_wait2();
            } else if (kc + 1 < 8) {
                cp_wait1();
            } else {
                cp_wait0();
            }
            __syncthreads();
            uint32_t hbase = hb + (uint32_t)b * 32768;
            int n_ld = 16 * w + l15;
#pragma unroll
            for (int k16 = 0; k16 < 8; k16++) {
                int cf = 2 * k16 + lhi;
                unsigned af[4];
                ldsm4(hbase + (uint32_t)n_ld * 256 + ((cf & 8) << 4) +
                          (uint32_t)(((cf & 7) ^ (n_ld & 7)) << 4),
                      af[0], af[1], af[2], af[3]);
                int kg = kc * 8 + k16;
                uint32_t brow = whb + (uint32_t)(kg * 16 + l15) * 80;
                unsigned b0, b1, b2, b3, b4, b5, b6, b7;
                ldsm4t(brow + (uint32_t)(lhi << 4), b0, b1, b2, b3);
                ldsm4t(brow + (uint32_t)((2 + lhi) << 4), b4, b5, b6, b7);
                bmma(acc[0], af, b0, b1);
                bmma(acc[1], af, b2, b3);
                bmma(acc[2], af, b4, b5);
                bmma(acc[3], af, b6, b7);
            }
            // score accumulation: h[bid][kc*128 + sc_part*8 .. +8] x A[bid][..][sc_l]
            {
                uint4 hv4 = *(const uint4*)(sm_raw + SM_H + (size_t)b * 32768 + sc_soff);
                const __nv_bfloat162* hh = (const __nv_bfloat162*)&hv4;
                int hk0 = kc * 128 + sc_part * 8;
                const float* Ab = &g_A[((size_t)bid * H_ + hk0) * L_ + sc_l];
#pragma unroll
                for (int j = 0; j < 4; j++) {
                    float2 f = __bfloat1622float2(hh[j]);
                    scacc = fmaf(f.x, Ab[(2 * j) * L_], scacc);
                    scacc = fmaf(f.y, Ab[(2 * j + 1) * L_], scacc);
                }
            }
            __syncthreads();
        }

        // ---- local score reduce + softmax -> g_w[bid] ----
        sWs[sc_part * 16 + sc_l] = scacc;
        __syncthreads();
        if (tid < 16) {
            float s = 0.0f;
#pragma unroll
            for (int p = 0; p < 16; p++) s += sWs[p * 16 + tid];
            sRed[tid] = s * 0.03125f;
        }
        __syncthreads();
        if (tid == 0) {
            float mx = -INFINITY;
#pragma unroll
            for (int l = 0; l < 16; l++) mx = fmaxf(mx, sRed[l]);
            float se = 0.0f;
            float ev[16];
#pragma unroll
            for (int l = 0; l < 16; l++) { ev[l] = __expf(sRed[l] - mx); se += ev[l]; }
            float inv = 1.0f / se;
#pragma unroll
            for (int l = 0; l < 16; l++) g_w[bid * 16 + l] = ev[l] * inv;
        }

        // ---- preload xproj into sZX (before the barrier) ----
        for (int v = tid; v < 4096; v += 256) {
            int n = v >> 5, c32 = v & 31;
            int gcol = (c32 >> 3) * 1024 + bid * 8 + (c32 & 7);
            sZX[v] = g_xproj[((size_t)(n * T_ + t)) * H4_ + gcol];
        }

        // ---- barrier publishes g_w (all samples) ----
        gbar(gen);

        // ---- zx += w . Pp (bf16, [n][c32][l] layout) ----
        for (int i = tid; i < 2048; i += 256) sWs[i] = __ldcg(&g_w[i]);
        __syncthreads();
        for (int v = tid; v < 4096; v += 256) {
            int n = v >> 5, c32 = v & 31;
            float a = sZX[v];
            const __nv_bfloat16* pp = &gb_Pp[(((size_t)bid * 128 + n) * 32 + c32) * 16];
            uint4 p0 = *(const uint4*)pp;
            uint4 p1 = *(const uint4*)(pp + 8);
            const float* wn_ = &sWs[n * 16];
            const __nv_bfloat162* h2a = (const __nv_bfloat162*)&p0;
            const __nv_bfloat162* h2b = (const __nv_bfloat162*)&p1;
#pragma unroll
            for (int j = 0; j < 4; j++) {
                float2 fa = __bfloat1622float2(h2a[j]);
                float2 fb = __bfloat1622float2(h2b[j]);
                a = fmaf(wn_[2 * j], fa.x, a);
                a = fmaf(wn_[2 * j + 1], fa.y, a);
                a = fmaf(wn_[8 + 2 * j], fb.x, a);
                a = fmaf(wn_[8 + 2 * j + 1], fb.y, a);
            }
            sZX[v] = a;
        }
        __syncthreads();

        // ---- gates ----
#pragma unroll
        for (int qn = 0; qn < 2; qn++) {
            int n = 16 * w + (lane >> 2) + 8 * qn;
#pragma unroll
            for (int qh = 0; qh < 2; qh++) {
                int hh = (lane & 3) * 2 + qh;
                int q = 2 * qn + qh;
                float zi = acc[0][q] + sZX[n * 32 + hh];
                float zf = acc[1][q] + sZX[n * 32 + 8 + hh];
                float zo = acc[2][q] + sZX[n * 32 + 16 + hh];
                float zg = acc[3][q] + sZX[n * 32 + 24 + hh];
                float c = sigfast(zf) * creg[qn][qh] + sigfast(zi) * tanhfast(zg);
                float hv = sigfast(zo) * tanhfast(c);
                creg[qn][qh] = c;
                __nv_bfloat16 hb16 = __float2bfloat16_rn(hv);
                gb_hbuf[nxt][n * H_ + bid * 8 + hh] = hb16;
                gb_hn[((size_t)n * T_ + t) * H_ + bid * 8 + hh] = hb16;
            }
        }

        // ---- barrier publishes h(t) ----
        if (t < T_ - 1) gbar(gen);
    }
}

// ---------------- launch ----------------
extern "C" void kernel_launch(void* const* d_in, const int* in_sizes, int n_in,
                              void* d_out, int out_size) {
    const float* features = (const float*)d_in[0];
    const int*   captions = (const int*)d_in[1];
    const float* W_embed  = (const float*)d_in[2];
    const float* W_proj   = (const float*)d_in[3];
    const float* b_proj   = (const float*)d_in[4];
    const float* Wx       = (const float*)d_in[5];
    const float* Wh       = (const float*)d_in[6];
    const float* Wattn    = (const float*)d_in[7];
    const float* b        = (const float*)d_in[8];
    const float* W_vocab  = (const float*)d_in[9];
    const float* b_vocab  = (const float*)d_in[10];
    float* out = (float*)d_out;

    cudaFuncSetAttribute(rnn_loop, cudaFuncAttributeMaxDynamicSharedMemorySize, SM_TOT);

    combo_init<<<1, 256>>>(out);
    f2b_all<<<(R4 + 255) / 256, 256>>>(W_embed, Wx, Wh, Wattn, W_vocab);
    kA<<<N_, 256>>>(features, W_proj, b_proj);
    gemm_embed<<<dim3(H4_ / 128, (N_ * T_) / 128), 256>>>(captions, b);
    gemm_P<<<dim3(H4_ / 128, (N_ * L_) / 128), 256>>>();
    rnn_loop<<<NBLK, 256, SM_TOT>>>();
    gemm_vocab<<<dim3(NBX, (N_ * T_) / 128), 256>>>(b_vocab, captions);
    loss_f<<<(N_ * T_) / 32, 256>>>(captions, out);
}

// round 16
// speedup vs baseline: 5.1592x; 1.0041x over previous
#include <cuda_runtime.h>
#include <cuda_bf16.h>
#include <cstdint>
#include <math.h>

#define N_   128
#define T_   32
#define TCAP 33
#define D_   400
#define WE_  512
#define H_   1024
#define H4_  4096
#define V_   10000
#define L_   16
#define NBLK 128
#define NBX  79
#define NLSE (NBX * 2)

// ---------------- device scratch ----------------
__device__ float g_A[N_ * H_ * L_];                       // [n][h][l]
__device__ float g_h0[N_ * H_];
__device__ float g_xproj[(size_t)N_ * T_ * H4_];
__device__ float g_w[N_ * L_];
__device__ float2 g_lsep[(size_t)N_ * T_ * NLSE];
__device__ float g_stgt[N_ * T_];
__device__ __align__(128) unsigned g_flags[NBLK * 8];     // 1 flag / 32B sector

// bf16 operands
__device__ __nv_bfloat16 gb_Wemb[(size_t)V_ * WE_];
__device__ __nv_bfloat16 gb_Wx[(size_t)WE_ * H4_];
__device__ __nv_bfloat16 gb_Wh[(size_t)H_ * H4_];
__device__ __nv_bfloat16 gb_Wattn[(size_t)H_ * H4_];
__device__ __nv_bfloat16 gb_Wv[(size_t)H_ * V_];
__device__ __nv_bfloat16 gb_At[N_ * L_ * H_];
__device__ __nv_bfloat16 gb_hbuf[2][N_ * H_];
__device__ __nv_bfloat16 gb_hn[N_ * T_ * H_];
__device__ __nv_bfloat16 gb_Pp[(size_t)N_ * L_ * H4_];    // [blk][n][c32][l] bf16

extern __shared__ char sm_raw[];

// fast transcendentals (MUFU)
__device__ __forceinline__ float tanhfast(float x) {
    float y; asm("tanh.approx.f32 %0, %1;" : "=f"(y) : "f"(x)); return y;
}
__device__ __forceinline__ float sigfast(float x) {
    return fmaf(0.5f, tanhfast(0.5f * x), 0.5f);
}

// ---------------- merged prep: init + f2b + kA in ONE kernel ----------------
#define R0 640000u
#define R1 (R0 + 262144u)
#define R2 (R1 + 524288u)
#define R3 (R2 + 524288u)
#define R4 (R3 + 1280000u)
#define F2B_BLKS ((R4 + 255u) / 256u)
#define PREP_BLKS (F2B_BLKS + NBLK)

__global__ __launch_bounds__(256) void prep_all(const float* __restrict__ Wemb,
                                                const float* __restrict__ Wx,
                                                const float* __restrict__ Wh,
                                                const float* __restrict__ Wattn,
                                                const float* __restrict__ Wv,
                                                const float* __restrict__ feat,
                                                const float* __restrict__ Wp,
                                                const float* __restrict__ bp,
                                                float* out) {
    __shared__ float fsh[D_ * L_];
    if (blockIdx.x < F2B_BLKS) {
        if (blockIdx.x == 0) {
            if (threadIdx.x == 0) out[0] = 0.0f;
            for (int i = threadIdx.x; i < NBLK * 8; i += 256) g_flags[i] = 0u;
        }
        unsigned i8 = blockIdx.x * 256 + threadIdx.x;
        const float* s; __nv_bfloat16* d; unsigned base;
        if (i8 < R0)      { s = Wemb;  d = gb_Wemb;  base = 0; }
        else if (i8 < R1) { s = Wx;    d = gb_Wx;    base = R0; }
        else if (i8 < R2) { s = Wh;    d = gb_Wh;    base = R1; }
        else if (i8 < R3) { s = Wattn; d = gb_Wattn; base = R2; }
        else if (i8 < R4) { s = Wv;    d = gb_Wv;    base = R3; }
        else return;
        size_t off = (size_t)(i8 - base) * 8;
        float4 v0 = *(const float4*)(s + off);
        float4 v1 = *(const float4*)(s + off + 4);
        union { __nv_bfloat162 h2[4]; uint4 u; } o;
        o.h2[0] = __floats2bfloat162_rn(v0.x, v0.y);
        o.h2[1] = __floats2bfloat162_rn(v0.z, v0.w);
        o.h2[2] = __floats2bfloat162_rn(v1.x, v1.y);
        o.h2[3] = __floats2bfloat162_rn(v1.z, v1.w);
        *(uint4*)(d + off) = o.u;
        return;
    }
    // ---- kA part ----
    int n = blockIdx.x - F2B_BLKS;
    const float* f = feat + (size_t)n * D_ * L_;
    for (int i = threadIdx.x; i < D_ * L_; i += 256) fsh[i] = f[i];
    __syncthreads();
    for (int h = threadIdx.x; h < H_; h += 256) {
        float acc[L_];
        float bb = bp[h];
#pragma unroll
        for (int l = 0; l < L_; l++) acc[l] = bb;
        for (int d = 0; d < D_; d++) {
            float wv = Wp[d * H_ + h];
            const float* fr = &fsh[d * L_];
#pragma unroll
            for (int l = 0; l < L_; l++) acc[l] = fmaf(fr[l], wv, acc[l]);
        }
        float s = 0.0f;
        float* Ar = g_A + ((size_t)n * H_ + h) * L_;
#pragma unroll
        for (int l = 0; l < L_; l++) {
            Ar[l] = acc[l];
            gb_At[((size_t)n * L_ + l) * H_ + h] = __float2bfloat16_rn(acc[l]);
            s += acc[l];
        }
        float h0 = s * (1.0f / 16.0f);
        g_h0[n * H_ + h] = h0;
        gb_hbuf[0][n * H_ + h] = __float2bfloat16_rn(h0);
    }
}

// ================= BF16 mma GEMM core (2-stage, static smem) =================
__device__ __forceinline__ void ldsm4(uint32_t a, unsigned& r0, unsigned& r1,
                                      unsigned& r2, unsigned& r3) {
    asm volatile("ldmatrix.sync.aligned.m8n8.x4.shared.b16 {%0,%1,%2,%3}, [%4];"
                 : "=r"(r0), "=r"(r1), "=r"(r2), "=r"(r3) : "r"(a));
}
__device__ __forceinline__ void ldsm4t(uint32_t a, unsigned& r0, unsigned& r1,
                                       unsigned& r2, unsigned& r3) {
    asm volatile("ldmatrix.sync.aligned.m8n8.x4.trans.shared.b16 {%0,%1,%2,%3}, [%4];"
                 : "=r"(r0), "=r"(r1), "=r"(r2), "=r"(r3) : "r"(a));
}
__device__ __forceinline__ void bmma(float* c, const unsigned* a,
                                     unsigned b0, unsigned b1) {
    asm volatile("mma.sync.aligned.m16n8k16.row.col.f32.bf16.bf16.f32 "
                 "{%0,%1,%2,%3},{%4,%5,%6,%7},{%8,%9},{%0,%1,%2,%3};"
                 : "+f"(c[0]), "+f"(c[1]), "+f"(c[2]), "+f"(c[3])
                 : "r"(a[0]), "r"(a[1]), "r"(a[2]), "r"(a[3]), "r"(b0), "r"(b1));
}
__device__ __forceinline__ void cpa16(uint32_t dst, const void* src) {
    asm volatile("cp.async.cg.shared.global [%0], [%1], 16;" ::"r"(dst), "l"(src));
}
__device__ __forceinline__ void cpa16z(uint32_t dst, const void* src, unsigned sz) {
    asm volatile("cp.async.cg.shared.global [%0], [%1], 16, %2;"
                 ::"r"(dst), "l"(src), "r"(sz));
}
__device__ __forceinline__ void cp_commit() { asm volatile("cp.async.commit_group;"); }
__device__ __forceinline__ void cp_wait1() { asm volatile("cp.async.wait_group 1;"); }
__device__ __forceinline__ void cp_wait0() { asm volatile("cp.async.wait_group 0;"); }

struct BfgLoader {
    const __nv_bfloat16 *a0, *a1, *b0, *b1;
    uint32_t aoff0, aoff1, boff0, boff1;
    size_t bstep;
    unsigned bsz;
    __device__ __forceinline__ void issue(int it, uint32_t dA, uint32_t dB) const {
        cpa16(dA + aoff0, a0 + it * 32);
        cpa16(dA + aoff1, a1 + it * 32);
        cpa16z(dB + boff0, b0 + (size_t)it * bstep, bsz);
        cpa16z(dB + boff1, b1 + (size_t)it * bstep, bsz);
    }
};

__device__ __forceinline__ void bfg_compute(uint32_t bA, uint32_t bB,
                                            int lane, int wm, int wn,
                                            float acc[2][8][4]) {
    const int l15 = lane & 15, l7 = lane & 7, lhi = lane >> 4;
    const int mA0 = wm * 32 + l15, mA1 = mA0 + 16;
    const uint32_t aR0 = (uint32_t)mA0 * 128, aR1 = (uint32_t)mA1 * 128;
    const int a70 = mA0 & 7, a71 = mA1 & 7;
    const uint32_t bRk = (uint32_t)l15 * 256;
#pragma unroll
    for (int ks = 0; ks < 2; ks++) {
        int c = ks * 2 + lhi;
        unsigned af0[4], af1[4];
        ldsm4(bA + aR0 + (uint32_t)(((c ^ a70) & 7) << 4),
              af0[0], af0[1], af0[2], af0[3]);
        ldsm4(bA + aR1 + (uint32_t)(((c ^ a71) & 7) << 4),
              af1[0], af1[1], af1[2], af1[3]);
#pragma unroll
        for (int p = 0; p < 4; p++) {
            unsigned bf0, bf1, bf2, bf3;
            int g = wn * 8 + p * 2 + lhi;
            ldsm4t(bB + (uint32_t)(ks * 16) * 256 + bRk + (uint32_t)((g ^ l7) << 4),
                   bf0, bf1, bf2, bf3);
            bmma(acc[0][2 * p],     af0, bf0, bf1);
            bmma(acc[0][2 * p + 1], af0, bf2, bf3);
            bmma(acc[1][2 * p],     af1, bf0, bf1);
            bmma(acc[1][2 * p + 1], af1, bf2, bf3);
        }
    }
}

__device__ __forceinline__ void bfg_run(const BfgLoader& ld, int nIter,
                                        uint32_t sA0, uint32_t sB0,
                                        int lane, int wm, int wn,
                                        float acc[2][8][4]) {
    ld.issue(0, sA0, sB0);
    cp_commit();
    for (int it = 0; it < nIter; it++) {
        uint32_t bA = sA0 + (uint32_t)(it & 1) * 16384;
        uint32_t bB = sB0 + (uint32_t)(it & 1) * 8192;
        if (it + 1 < nIter) {
            ld.issue(it + 1, sA0 + (uint32_t)((it + 1) & 1) * 16384,
                     sB0 + (uint32_t)((it + 1) & 1) * 8192);
            cp_commit();
            cp_wait1();
        } else {
            cp_wait0();
        }
        __syncthreads();
        bfg_compute(bA, bB, lane, wm, wn, acc);
        __syncthreads();
    }
}

struct BfgIdx {
    int tid, lane, wid, wm, wn, am, ag, bks, bg;
    uint32_t aoff0, aoff1, boff0, boff1;
    __device__ __forceinline__ BfgIdx() {
        tid = threadIdx.x; lane = tid & 31; wid = tid >> 5;
        wm = wid >> 1; wn = wid & 1;
        am = tid >> 2; ag = tid & 3;
        bks = tid >> 4; bg = tid & 15;
        aoff0 = (uint32_t)am * 128 + (uint32_t)(((ag ^ (am & 7)) & 7) << 4);
        aoff1 = aoff0 + 64 * 128;
        boff0 = (uint32_t)bks * 256 + (uint32_t)((bg ^ (bks & 7)) << 4);
        boff1 = boff0 + 16 * 256;
    }
};

#define BFG_SMEM                                                               \
    __shared__ __align__(16) char sAm[2][16384];                               \
    __shared__ __align__(16) char sBm[2][8192];                                \
    uint32_t sA0 = (uint32_t)__cvta_generic_to_shared(sAm);                    \
    uint32_t sB0 = (uint32_t)__cvta_generic_to_shared(sBm);

// ---- xproj = W_embed[cap] @ Wx + b ----
__global__ __launch_bounds__(256) void gemm_embed(const int* __restrict__ captions,
                                                  const float* __restrict__ bias) {
    int row0 = blockIdx.y * 128, col0 = blockIdx.x * 128;
    BFG_SMEM;
    BfgIdx ix;
    float acc[2][8][4] = {};
    int r0i = row0 + ix.am, r1i = r0i + 64;
    BfgLoader ld;
    ld.a0 = gb_Wemb + (size_t)captions[(r0i >> 5) * TCAP + (r0i & 31)] * WE_ + ix.ag * 8;
    ld.a1 = gb_Wemb + (size_t)captions[(r1i >> 5) * TCAP + (r1i & 31)] * WE_ + ix.ag * 8;
    ld.b0 = gb_Wx + (size_t)ix.bks * H4_ + col0 + ix.bg * 8;
    ld.b1 = ld.b0 + (size_t)16 * H4_;
    ld.aoff0 = ix.aoff0; ld.aoff1 = ix.aoff1; ld.boff0 = ix.boff0; ld.boff1 = ix.boff1;
    ld.bstep = (size_t)32 * H4_; ld.bsz = 16;
    bfg_run(ld, WE_ / 32, sA0, sB0, ix.lane, ix.wm, ix.wn, acc);
    int eg = ix.lane >> 2, ec = (ix.lane & 3) * 2;
#pragma unroll
    for (int mt = 0; mt < 2; mt++)
#pragma unroll
        for (int nt = 0; nt < 8; nt++) {
            int row = row0 + ix.wm * 32 + mt * 16 + eg;
            int col = col0 + ix.wn * 64 + nt * 8 + ec;
            float b0v = bias[col], b1v = bias[col + 1];
            *(float2*)&g_xproj[(size_t)row * H4_ + col] =
                make_float2(acc[mt][nt][0] + b0v, acc[mt][nt][1] + b1v);
            *(float2*)&g_xproj[(size_t)(row + 8) * H4_ + col] =
                make_float2(acc[mt][nt][2] + b0v, acc[mt][nt][3] + b1v);
        }
}

// ---- P = A^T @ Wattn, written bf16 block-major [blk][n][c32][l] ----
__global__ __launch_bounds__(256) void gemm_P() {
    int row0 = blockIdx.y * 128, col0 = blockIdx.x * 128;
    BFG_SMEM;
    BfgIdx ix;
    float acc[2][8][4] = {};
    BfgLoader ld;
    ld.a0 = gb_At + (size_t)(row0 + ix.am) * H_ + ix.ag * 8;
    ld.a1 = ld.a0 + (size_t)64 * H_;
    ld.b0 = gb_Wattn + (size_t)ix.bks * H4_ + col0 + ix.bg * 8;
    ld.b1 = ld.b0 + (size_t)16 * H4_;
    ld.aoff0 = ix.aoff0; ld.aoff1 = ix.aoff1; ld.boff0 = ix.boff0; ld.boff1 = ix.boff1;
    ld.bstep = (size_t)32 * H4_; ld.bsz = 16;
    bfg_run(ld, H_ / 32, sA0, sB0, ix.lane, ix.wm, ix.wn, acc);
    int eg = ix.lane >> 2, ec = (ix.lane & 3) * 2;
#pragma unroll
    for (int mt = 0; mt < 2; mt++)
#pragma unroll
        for (int nt = 0; nt < 8; nt++) {
            int row = row0 + ix.wm * 32 + mt * 16 + eg;        // = n*16 + l, l in 0..7
            int col = col0 + ix.wn * 64 + nt * 8 + ec;
            int n = row >> 4, l = row & 15;
            int gate = col >> 10, rem = col & 1023;
            int bblk = rem >> 3, c32 = gate * 8 + (rem & 7);
            size_t base = (((size_t)bblk * 128 + n) * 32 + c32) * 16 + l;
            gb_Pp[base]          = __float2bfloat16_rn(acc[mt][nt][0]);
            gb_Pp[base + 16]     = __float2bfloat16_rn(acc[mt][nt][1]);  // c32+1
            gb_Pp[base + 8]      = __float2bfloat16_rn(acc[mt][nt][2]);  // l+8
            gb_Pp[base + 16 + 8] = __float2bfloat16_rn(acc[mt][nt][3]);
        }
}

// ---- LSE merge helper ----
__device__ __forceinline__ void lsemerge(float& m, float& s, float om, float os) {
    float M = fmaxf(m, om);
    if (M == -INFINITY) { s = 0.0f; return; }
    float t1 = (m == -INFINITY) ? 0.0f : s * __expf(m - M);
    float t2 = (om == -INFINITY) ? 0.0f : os * __expf(om - M);
    m = M; s = t1 + t2;
}

// ---- scores = hn @ W_vocab + b : fused LSE partials + target harvest ----
__global__ __launch_bounds__(256) void gemm_vocab(const float* __restrict__ bv,
                                                  const int* __restrict__ captions) {
    int row0 = blockIdx.y * 128, col0 = blockIdx.x * 128;
    BFG_SMEM;
    BfgIdx ix;
    float acc[2][8][4] = {};
    BfgLoader ld;
    ld.a0 = gb_hn + (size_t)(row0 + ix.am) * H_ + ix.ag * 8;
    ld.a1 = ld.a0 + (size_t)64 * H_;
    int bcol = col0 + ix.bg * 8;
    ld.bsz = (bcol + 8 <= V_) ? 16u : 0u;
    ld.b0 = gb_Wv + (size_t)ix.bks * V_ + ((bcol + 8 <= V_) ? bcol : 0);
    ld.b1 = ld.b0 + (size_t)16 * V_;
    ld.aoff0 = ix.aoff0; ld.aoff1 = ix.aoff1; ld.boff0 = ix.boff0; ld.boff1 = ix.boff1;
    ld.bstep = (size_t)32 * V_;
    bfg_run(ld, H_ / 32, sA0, sB0, ix.lane, ix.wm, ix.wn, acc);
    int eg = ix.lane >> 2, ec = (ix.lane & 3) * 2;
    float bvr[8][2];
#pragma unroll
    for (int nt = 0; nt < 8; nt++) {
        int col = col0 + ix.wn * 64 + nt * 8 + ec;
        bvr[nt][0] = (col < V_) ? bv[col] : 0.0f;
        bvr[nt][1] = (col + 1 < V_) ? bv[col + 1] : 0.0f;
    }
#pragma unroll
    for (int mt = 0; mt < 2; mt++)
#pragma unroll
        for (int qn = 0; qn < 2; qn++) {
            int row = row0 + ix.wm * 32 + mt * 16 + eg + 8 * qn;
            int tgt = captions[(row >> 5) * TCAP + (row & 31) + 1];
            float vals[16];
            float m = -INFINITY;
#pragma unroll
            for (int nt = 0; nt < 8; nt++)
#pragma unroll
                for (int j = 0; j < 2; j++) {
                    int col = col0 + ix.wn * 64 + nt * 8 + ec + j;
                    float v = acc[mt][nt][2 * qn + j] + bvr[nt][j];
                    vals[nt * 2 + j] = v;
                    if (col < V_) {
                        m = fmaxf(m, v);
                        if (col == tgt) g_stgt[row] = v;
                    }
                }
            float s = 0.0f;
#pragma unroll
            for (int nt = 0; nt < 8; nt++)
#pragma unroll
                for (int j = 0; j < 2; j++) {
                    int col = col0 + ix.wn * 64 + nt * 8 + ec + j;
                    if (col < V_)
                        s += __expf(vals[nt * 2 + j] - m);
                }
#pragma unroll
            for (int off = 1; off <= 2; off <<= 1) {
                float om = __shfl_xor_sync(0xffffffffu, m, off);
                float os = __shfl_xor_sync(0xffffffffu, s, off);
                lsemerge(m, s, om, os);
            }
            if ((ix.lane & 3) == 0)
                g_lsep[(size_t)row * NLSE + blockIdx.x * 2 + ix.wn] = make_float2(m, s);
        }
}

// ---- loss: merge LSE partials, nll on targets ----
__global__ __launch_bounds__(256) void loss_f(const int* __restrict__ captions,
                                              float* __restrict__ out) {
    int r = blockIdx.x * 32 + (threadIdx.x >> 3);
    int j8 = threadIdx.x & 7;
    float m = -INFINITY, s = 0.0f;
    for (int j = j8; j < NLSE; j += 8) {
        float2 p = g_lsep[(size_t)r * NLSE + j];
        lsemerge(m, s, p.x, p.y);
    }
#pragma unroll
    for (int off = 1; off <= 4; off <<= 1) {
        float om = __shfl_xor_sync(0xffffffffu, m, off);
        float os = __shfl_xor_sync(0xffffffffu, s, off);
        lsemerge(m, s, om, os);
    }
    if (j8 == 0) {
        int n = r >> 5, t = r & 31;
        int tgt = captions[n * TCAP + t + 1];
        if (tgt != 0) {
            float nll = logf(s) + m - g_stgt[r];
            atomicAdd(out, nll * (1.0f / (float)N_));
        }
    }
}

// ================= persistent RNN loop =================
// smem: Wh 81920 | h 3x32768 | zx 16384 | ws 8192 | red 1536
#define SM_WH   0
#define SM_H    81920
#define SM_ZX   180224
#define SM_WS   196608
#define SM_RED  204800
#define SM_TOT  206336

// contention-free flag barrier: 1 flag / 32B sector
__device__ __forceinline__ void gbar(unsigned& gen) {
    gen++;
    __syncthreads();
    __threadfence();
    if (threadIdx.x == 0) __stcg(&g_flags[blockIdx.x * 8], gen);
    if (threadIdx.x < 32) {
        for (;;) {
            unsigned v0 = __ldcg(&g_flags[threadIdx.x * 8]);
            unsigned v1 = __ldcg(&g_flags[(threadIdx.x + 32) * 8]);
            unsigned v2 = __ldcg(&g_flags[(threadIdx.x + 64) * 8]);
            unsigned v3 = __ldcg(&g_flags[(threadIdx.x + 96) * 8]);
            if (v0 >= gen && v1 >= gen && v2 >= gen && v3 >= gen) break;
        }
    }
    __threadfence();
    __syncthreads();
}

__global__ __launch_bounds__(256, 1) void rnn_loop() {
    const int tid = threadIdx.x, bid = blockIdx.x;
    const int lane = tid & 31, w = tid >> 5;
    const int l15 = lane & 15, lhi = lane >> 4;
    uint32_t smb = (uint32_t)__cvta_generic_to_shared(sm_raw);
    uint32_t whb = smb + SM_WH, hb = smb + SM_H;
    float* sZX = (float*)(sm_raw + SM_ZX);
    float* sWs = (float*)(sm_raw + SM_WS);
    float* sRed = (float*)(sm_raw + SM_RED);

    for (int i = tid; i < 4096; i += 256) {
        int k = i >> 2, g = i & 3;
        cpa16(whb + (uint32_t)k * 80 + g * 16,
              gb_Wh + (size_t)k * H4_ + g * 1024 + bid * 8);
    }
    cp_commit(); cp_wait0();
    __syncthreads();

    float creg[2][2];
#pragma unroll
    for (int qn = 0; qn < 2; qn++) {
        int n = 16 * w + (lane >> 2) + 8 * qn;
#pragma unroll
        for (int qh = 0; qh < 2; qh++)
            creg[qn][qh] = g_h0[n * H_ + bid * 8 + (lane & 3) * 2 + qh];
    }

    unsigned gen = 0;

    // score indexing for sample n == bid
    const int sc_part = tid >> 4;         // 0..15 : which 8-dim slice of the chunk
    const int sc_l = tid & 15;            // which attention location l
    const uint32_t sc_soff = (uint32_t)bid * 256 + (uint32_t)((sc_part & 8) << 4) +
                             (uint32_t)(((sc_part & 7) ^ (bid & 7)) << 4);

    auto issue_h = [&](const __nv_bfloat16* hsrc, int kc, uint32_t dst) {
#pragma unroll
        for (int i = 0; i < 8; i++) {
            int id = tid + 256 * i;
            int n = id >> 4, g = id & 15;
            uint32_t off = (uint32_t)n * 256 + ((g & 8) << 4) + ((((g & 7) ^ (n & 7))) << 4);
            cpa16(dst + off, hsrc + (size_t)n * H_ + kc * 128 + g * 8);
        }
        cp_commit();
    };

    for (int t = 0; t < T_; t++) {
        const int cur = t & 1, nxt = cur ^ 1;
        const __nv_bfloat16* hsrc = gb_hbuf[cur];

        // ---- GEMM z = h @ Wh-slice + in-stream attention score for n=bid ----
        // single sync per chunk: issue follows the sync (write target == buffer
        // computed last iteration, so the sync orders reuse correctly)
        issue_h(hsrc, 0, hb);
        issue_h(hsrc, 1, hb + 32768);
        float acc[4][4] = {};
        float scacc = 0.0f;
        for (int kc = 0; kc < 8; kc++) {
            int b = kc % 3;
            if (kc < 7) cp_wait1(); else cp_wait0();
            __syncthreads();
            if (kc + 2 < 8)
                issue_h(hsrc, kc + 2, hb + (uint32_t)((kc + 2) % 3) * 32768);
            uint32_t hbase = hb + (uint32_t)b * 32768;
            int n_ld = 16 * w + l15;
#pragma unroll
            for (int k16 = 0; k16 < 8; k16++) {
                int cf = 2 * k16 + lhi;
                unsigned af[4];
                ldsm4(hbase + (uint32_t)n_ld * 256 + ((cf & 8) << 4) +
                          (uint32_t)(((cf & 7) ^ (n_ld & 7)) << 4),
                      af[0], af[1], af[2], af[3]);
                int kg = kc * 8 + k16;
                uint32_t brow = whb + (uint32_t)(kg * 16 + l15) * 80;
                unsigned b0, b1, b2, b3, b4, b5, b6, b7;
                ldsm4t(brow + (uint32_t)(lhi << 4), b0, b1, b2, b3);
                ldsm4t(brow + (uint32_t)((2 + lhi) << 4), b4, b5, b6, b7);
                bmma(acc[0], af, b0, b1);
                bmma(acc[1], af, b2, b3);
                bmma(acc[2], af, b4, b5);
                bmma(acc[3], af, b6, b7);
            }
            // score accumulation: h[bid][kc*128 + sc_part*8 .. +8] x A[bid][..][sc_l]
            {
                uint4 hv4 = *(const uint4*)(sm_raw + SM_H + (size_t)b * 32768 + sc_soff);
                const __nv_bfloat162* hh = (const __nv_bfloat162*)&hv4;
                int hk0 = kc * 128 + sc_part * 8;
                const float* Ab = &g_A[((size_t)bid * H_ + hk0) * L_ + sc_l];
#pragma unroll
                for (int j = 0; j < 4; j++) {
                    float2 f = __bfloat1622float2(hh[j]);
                    scacc = fmaf(f.x, Ab[(2 * j) * L_], scacc);
                    scacc = fmaf(f.y, Ab[(2 * j + 1) * L_], scacc);
                }
            }
        }
        __syncthreads();

        // ---- local score reduce + softmax -> g_w[bid] ----
        sWs[sc_part * 16 + sc_l] = scacc;
        __syncthreads();
        if (tid < 16) {
            float s = 0.0f;
#pragma unroll
            for (int p = 0; p < 16; p++) s += sWs[p * 16 + tid];
            sRed[tid] = s * 0.03125f;
        }
        __syncthreads();
        if (tid == 0) {
            float mx = -INFINITY;
#pragma unroll
            for (int l = 0; l < 16; l++) mx = fmaxf(mx, sRed[l]);
            float se = 0.0f;
            float ev[16];
#pragma unroll
            for (int l = 0; l < 16; l++) { ev[l] = __expf(sRed[l] - mx); se += ev[l]; }
            float inv = 1.0f / se;
#pragma unroll
            for (int l = 0; l < 16; l++) g_w[bid * 16 + l] = ev[l] * inv;
        }

        // ---- preload xproj into sZX (before the barrier) ----
        for (int v = tid; v < 4096; v += 256) {
            int n = v >> 5, c32 = v & 31;
            int gcol = (c32 >> 3) * 1024 + bid * 8 + (c32 & 7);
            sZX[v] = g_xproj[((size_t)(n * T_ + t)) * H4_ + gcol];
        }

        // ---- barrier publishes g_w (all samples) ----
        gbar(gen);

        // ---- zx += w . Pp (bf16, [n][c32][l] layout) ----
        for (int i = tid; i < 2048; i += 256) sWs[i] = __ldcg(&g_w[i]);
        __syncthreads();
        for (int v = tid; v < 4096; v += 256) {
            int n = v >> 5, c32 = v & 31;
            float a = sZX[v];
            const __nv_bfloat16* pp = &gb_Pp[(((size_t)bid * 128 + n) * 32 + c32) * 16];
            uint4 p0 = *(const uint4*)pp;
            uint4 p1 = *(const uint4*)(pp + 8);
            const float* wn_ = &sWs[n * 16];
            const __nv_bfloat162* h2a = (const __nv_bfloat162*)&p0;
            const __nv_bfloat162* h2b = (const __nv_bfloat162*)&p1;
#pragma unroll
            for (int j = 0; j < 4; j++) {
                float2 fa = __bfloat1622float2(h2a[j]);
                float2 fb = __bfloat1622float2(h2b[j]);
                a = fmaf(wn_[2 * j], fa.x, a);
                a = fmaf(wn_[2 * j + 1], fa.y, a);
                a = fmaf(wn_[8 + 2 * j], fb.x, a);
                a = fmaf(wn_[8 + 2 * j + 1], fb.y, a);
            }
            sZX[v] = a;
        }
        __syncthreads();

        // ---- gates ----
#pragma unroll
        for (int qn = 0; qn < 2; qn++) {
            int n = 16 * w + (lane >> 2) + 8 * qn;
#pragma unroll
            for (int qh = 0; qh < 2; qh++) {
                int hh = (lane & 3) * 2 + qh;
                int q = 2 * qn + qh;
                float zi = acc[0][q] + sZX[n * 32 + hh];
                float zf = acc[1][q] + sZX[n * 32 + 8 + hh];
                float zo = acc[2][q] + sZX[n * 32 + 16 + hh];
                float zg = acc[3][q] + sZX[n * 32 + 24 + hh];
                float c = sigfast(zf) * creg[qn][qh] + sigfast(zi) * tanhfast(zg);
                float hv = sigfast(zo) * tanhfast(c);
                creg[qn][qh] = c;
                __nv_bfloat16 hb16 = __float2bfloat16_rn(hv);
                gb_hbuf[nxt][n * H_ + bid * 8 + hh] = hb16;
                gb_hn[((size_t)n * T_ + t) * H_ + bid * 8 + hh] = hb16;
            }
        }

        // ---- barrier publishes h(t) ----
        if (t < T_ - 1) gbar(gen);
    }
}

// ---------------- launch ----------------
extern "C" void kernel_launch(void* const* d_in, const int* in_sizes, int n_in,
                              void* d_out, int out_size) {
    const float* features = (const float*)d_in[0];
    const int*   captions = (const int*)d_in[1];
    const float* W_embed  = (const float*)d_in[2];
    const float* W_proj   = (const float*)d_in[3];
    const float* b_proj   = (const float*)d_in[4];
    const float* Wx       = (const float*)d_in[5];
    const float* Wh       = (const float*)d_in[6];
    const float* Wattn    = (const float*)d_in[7];
    const float* b        = (const float*)d_in[8];
    const float* W_vocab  = (const float*)d_in[9];
    const float* b_vocab  = (const float*)d_in[10];
    float* out = (float*)d_out;

    cudaFuncSetAttribute(rnn_loop, cudaFuncAttributeMaxDynamicSharedMemorySize, SM_TOT);

    prep_all<<<PREP_BLKS, 256>>>(W_embed, Wx, Wh, Wattn, W_vocab,
                                 features, W_proj, b_proj, out);            // 0
    gemm_embed<<<dim3(H4_ / 128, (N_ * T_) / 128), 256>>>(captions, b);     // 1
    gemm_P<<<dim3(H4_ / 128, (N_ * L_) / 128), 256>>>();                    // 2
    rnn_loop<<<NBLK, 256, SM_TOT>>>();                                      // 3 -> ncu
    gemm_vocab<<<dim3(NBX, (N_ * T_) / 128), 256>>>(b_vocab, captions);     // 4
    loss_f<<<(N_ * T_) / 32, 256>>>(captions, out);                         // 5
}